// round 1
// baseline (speedup 1.0000x reference)
#include <cuda_runtime.h>

#define BB 2
#define SS 2048
#define DIN 1024
#define DM 1024
#define HH 16
#define HD 64
#define BH (BB*HH)

// Scratch (allocation-free rule: __device__ globals)
__device__ float g_q[BH*SS*HD];
__device__ float g_k[BH*SS*HD];
__device__ float g_v[BH*SS*HD];
__device__ float g_attn[BB*SS*DM];

// ---------------------------------------------------------------------------
// SGEMM 128x128x16, 256 threads, 8x8 per thread.
// ---------------------------------------------------------------------------
__global__ void __launch_bounds__(256) qkv_gemm_kernel(const float* __restrict__ x,
                                                       const float* __restrict__ w,
                                                       const float* __restrict__ bias) {
    const int K = DIN, N = 3 * DM;
    __shared__ __align__(16) float As[16][132];
    __shared__ __align__(16) float Bs[16][128];
    int tid = threadIdx.x;
    int tx = tid & 15, ty = tid >> 4;
    int mBase = blockIdx.y * 128;
    int nBase = blockIdx.x * 128;
    float acc[8][8];
#pragma unroll
    for (int i = 0; i < 8; i++)
#pragma unroll
        for (int j = 0; j < 8; j++) acc[i][j] = 0.f;

    int aRow = tid >> 2;          // 0..63
    int aCol4 = (tid & 3) * 4;    // 0,4,8,12
    int bRow = tid >> 5;          // 0..7
    int bCol4 = (tid & 31) * 4;   // 0..124

    for (int k0 = 0; k0 < K; k0 += 16) {
#pragma unroll
        for (int r = 0; r < 2; r++) {
            int row = aRow + r * 64;
            float4 v = *(const float4*)(x + (mBase + row) * K + k0 + aCol4);
            As[aCol4 + 0][row] = v.x;
            As[aCol4 + 1][row] = v.y;
            As[aCol4 + 2][row] = v.z;
            As[aCol4 + 3][row] = v.w;
        }
#pragma unroll
        for (int r = 0; r < 2; r++) {
            int row = bRow + r * 8;
            float4 v = *(const float4*)(w + (k0 + row) * N + nBase + bCol4);
            *(float4*)&Bs[row][bCol4] = v;
        }
        __syncthreads();
#pragma unroll
        for (int kk = 0; kk < 16; kk++) {
            float a[8], b[8];
            *(float4*)(a)     = *(float4*)&As[kk][ty * 8];
            *(float4*)(a + 4) = *(float4*)&As[kk][ty * 8 + 4];
            *(float4*)(b)     = *(float4*)&Bs[kk][tx * 8];
            *(float4*)(b + 4) = *(float4*)&Bs[kk][tx * 8 + 4];
#pragma unroll
            for (int i = 0; i < 8; i++)
#pragma unroll
                for (int j = 0; j < 8; j++) acc[i][j] += a[i] * b[j];
        }
        __syncthreads();
    }
    // Epilogue: scatter into g_q/g_k/g_v [bh][s][d]
#pragma unroll
    for (int i = 0; i < 8; i++) {
        int m = mBase + ty * 8 + i;
        int b = m >> 11;           // /S
        int s = m & (SS - 1);
#pragma unroll
        for (int j = 0; j < 8; j++) {
            int n = nBase + tx * 8 + j;
            float v = acc[i][j] + bias[n];
            int h = n / 192;
            int rem = n - h * 192;
            int t = rem >> 6;
            int d = rem & 63;
            int idx = ((b * HH + h) * SS + s) * HD + d;
            if (t == 0) g_q[idx] = v;
            else if (t == 1) g_k[idx] = v;
            else g_v[idx] = v;
        }
    }
}

__global__ void __launch_bounds__(256) out_gemm_kernel(const float* __restrict__ a_in,
                                                       const float* __restrict__ w,
                                                       const float* __restrict__ bias,
                                                       float* __restrict__ out) {
    const int K = DM, N = DM;
    __shared__ __align__(16) float As[16][132];
    __shared__ __align__(16) float Bs[16][128];
    int tid = threadIdx.x;
    int tx = tid & 15, ty = tid >> 4;
    int mBase = blockIdx.y * 128;
    int nBase = blockIdx.x * 128;
    float acc[8][8];
#pragma unroll
    for (int i = 0; i < 8; i++)
#pragma unroll
        for (int j = 0; j < 8; j++) acc[i][j] = 0.f;

    int aRow = tid >> 2;
    int aCol4 = (tid & 3) * 4;
    int bRow = tid >> 5;
    int bCol4 = (tid & 31) * 4;

    for (int k0 = 0; k0 < K; k0 += 16) {
#pragma unroll
        for (int r = 0; r < 2; r++) {
            int row = aRow + r * 64;
            float4 v = *(const float4*)(a_in + (mBase + row) * K + k0 + aCol4);
            As[aCol4 + 0][row] = v.x;
            As[aCol4 + 1][row] = v.y;
            As[aCol4 + 2][row] = v.z;
            As[aCol4 + 3][row] = v.w;
        }
#pragma unroll
        for (int r = 0; r < 2; r++) {
            int row = bRow + r * 8;
            float4 v = *(const float4*)(w + (k0 + row) * N + nBase + bCol4);
            *(float4*)&Bs[row][bCol4] = v;
        }
        __syncthreads();
#pragma unroll
        for (int kk = 0; kk < 16; kk++) {
            float a[8], b[8];
            *(float4*)(a)     = *(float4*)&As[kk][ty * 8];
            *(float4*)(a + 4) = *(float4*)&As[kk][ty * 8 + 4];
            *(float4*)(b)     = *(float4*)&Bs[kk][tx * 8];
            *(float4*)(b + 4) = *(float4*)&Bs[kk][tx * 8 + 4];
#pragma unroll
            for (int i = 0; i < 8; i++)
#pragma unroll
                for (int j = 0; j < 8; j++) acc[i][j] += a[i] * b[j];
        }
        __syncthreads();
    }
#pragma unroll
    for (int i = 0; i < 8; i++) {
        int m = mBase + ty * 8 + i;
#pragma unroll
        for (int j = 0; j < 8; j += 4) {
            int n = nBase + tx * 8 + j;
            float4 v;
            v.x = acc[i][j + 0] + bias[n + 0];
            v.y = acc[i][j + 1] + bias[n + 1];
            v.z = acc[i][j + 2] + bias[n + 2];
            v.w = acc[i][j + 3] + bias[n + 3];
            *(float4*)(out + m * N + n) = v;
        }
    }
}

// ---------------------------------------------------------------------------
// Flash attention, fp32, causal. 64x64 tiles, 256 threads.
// smem: sQ (d-major, 64x68), sK (d-major, 64x68, aliased by P), sV (row-major 64x68)
// Thread (tx,ty) 16x16 grid: rows ty*4+ri, cols tx*4+ci.
// ---------------------------------------------------------------------------
#define APAD 68
#define ATILE (64 * APAD)

__global__ void __launch_bounds__(256) attn_kernel() {
    extern __shared__ float sm[];
    float* sQ = sm;              // [d][row]
    float* sK = sm + ATILE;      // [d][col]; later aliased as sP [row][kk]
    float* sV = sm + 2 * ATILE;  // [kvrow][d]

    int tid = threadIdx.x;
    int tx = tid & 15, ty = tid >> 4;
    int qt = blockIdx.x;         // 0..31
    int bh = blockIdx.y;         // 0..31
    int b = bh >> 4, h = bh & 15;
    int qBase = qt * 64;

    const float scale = 0.125f;  // 1/sqrt(64)
    const float* Qg = g_q + (bh * SS + qBase) * HD;
    const float* Kg = g_k + bh * SS * HD;
    const float* Vg = g_v + bh * SS * HD;

    // Load Q tile transposed (d-major), pre-scaled
    {
        int lrow = tid >> 4;          // 0..15
        int d4 = (tid & 15) * 4;
#pragma unroll
        for (int p = 0; p < 4; p++) {
            int row = lrow + p * 16;
            float4 v = *(const float4*)(Qg + row * HD + d4);
            sQ[(d4 + 0) * APAD + row] = v.x * scale;
            sQ[(d4 + 1) * APAD + row] = v.y * scale;
            sQ[(d4 + 2) * APAD + row] = v.z * scale;
            sQ[(d4 + 3) * APAD + row] = v.w * scale;
        }
    }

    float acc[4][4];
    float mrow[4], lrow_[4];
#pragma unroll
    for (int i = 0; i < 4; i++) {
        mrow[i] = -1e30f;
        lrow_[i] = 0.f;
#pragma unroll
        for (int j = 0; j < 4; j++) acc[i][j] = 0.f;
    }

    int ldrow = tid >> 4;
    int ldd4 = (tid & 15) * 4;

    for (int j = 0; j <= qt; j++) {
        __syncthreads();  // previous iteration's P/V reads complete
        // Load K (transposed) and V tiles
        const float* Kt = Kg + j * 64 * HD;
        const float* Vt = Vg + j * 64 * HD;
#pragma unroll
        for (int p = 0; p < 4; p++) {
            int row = ldrow + p * 16;
            float4 kv = *(const float4*)(Kt + row * HD + ldd4);
            sK[(ldd4 + 0) * APAD + row] = kv.x;
            sK[(ldd4 + 1) * APAD + row] = kv.y;
            sK[(ldd4 + 2) * APAD + row] = kv.z;
            sK[(ldd4 + 3) * APAD + row] = kv.w;
            float4 vv = *(const float4*)(Vt + row * HD + ldd4);
            *(float4*)&sV[row * APAD + ldd4] = vv;
        }
        __syncthreads();

        // Scores: s[ri][ci] = sum_d Q[qrow][d] * K[kcol][d]
        float s[4][4];
#pragma unroll
        for (int i = 0; i < 4; i++)
#pragma unroll
            for (int c = 0; c < 4; c++) s[i][c] = 0.f;
#pragma unroll 8
        for (int d = 0; d < 64; d++) {
            float4 qv = *(float4*)&sQ[d * APAD + ty * 4];
            float4 kv = *(float4*)&sK[d * APAD + tx * 4];
            float qa[4] = {qv.x, qv.y, qv.z, qv.w};
            float ka[4] = {kv.x, kv.y, kv.z, kv.w};
#pragma unroll
            for (int i = 0; i < 4; i++)
#pragma unroll
                for (int c = 0; c < 4; c++) s[i][c] += qa[i] * ka[c];
        }

        // Causal mask (only the diagonal tile)
        if (j == qt) {
#pragma unroll
            for (int i = 0; i < 4; i++) {
                int qr = ty * 4 + i;
#pragma unroll
                for (int c = 0; c < 4; c++) {
                    int kc = tx * 4 + c;
                    if (kc > qr) s[i][c] = -1e30f;
                }
            }
        }

        // Online softmax per row
#pragma unroll
        for (int i = 0; i < 4; i++) {
            float mloc = fmaxf(fmaxf(s[i][0], s[i][1]), fmaxf(s[i][2], s[i][3]));
#pragma unroll
            for (int o = 8; o >= 1; o >>= 1)
                mloc = fmaxf(mloc, __shfl_xor_sync(0xffffffffu, mloc, o));
            float mnew = fmaxf(mrow[i], mloc);
            float alpha = __expf(mrow[i] - mnew);
            float lsum = 0.f;
#pragma unroll
            for (int c = 0; c < 4; c++) {
                float p = __expf(s[i][c] - mnew);
                s[i][c] = p;
                lsum += p;
            }
#pragma unroll
            for (int o = 8; o >= 1; o >>= 1)
                lsum += __shfl_xor_sync(0xffffffffu, lsum, o);
            lrow_[i] = lrow_[i] * alpha + lsum;
            mrow[i] = mnew;
#pragma unroll
            for (int c = 0; c < 4; c++) acc[i][c] *= alpha;
        }

        __syncthreads();  // all score reads of sK done; safe to alias as sP
        float* sP = sK;   // [row][kk]
#pragma unroll
        for (int i = 0; i < 4; i++)
#pragma unroll
            for (int c = 0; c < 4; c++)
                sP[(ty * 4 + i) * APAD + tx * 4 + c] = s[i][c];
        __syncthreads();

        // O += P @ V
#pragma unroll 8
        for (int kk = 0; kk < 64; kk++) {
            float4 vv = *(float4*)&sV[kk * APAD + tx * 4];
            float va[4] = {vv.x, vv.y, vv.z, vv.w};
            float p0 = sP[(ty * 4 + 0) * APAD + kk];
            float p1 = sP[(ty * 4 + 1) * APAD + kk];
            float p2 = sP[(ty * 4 + 2) * APAD + kk];
            float p3 = sP[(ty * 4 + 3) * APAD + kk];
#pragma unroll
            for (int c = 0; c < 4; c++) {
                acc[0][c] += p0 * va[c];
                acc[1][c] += p1 * va[c];
                acc[2][c] += p2 * va[c];
                acc[3][c] += p3 * va[c];
            }
        }
    }

    // Write O to concat layout [b][s][h*HD+d]
#pragma unroll
    for (int i = 0; i < 4; i++) {
        int srow = qBase + ty * 4 + i;
        float inv = 1.0f / lrow_[i];
        float4 o;
        o.x = acc[i][0] * inv;
        o.y = acc[i][1] * inv;
        o.z = acc[i][2] * inv;
        o.w = acc[i][3] * inv;
        *(float4*)&g_attn[(b * SS + srow) * DM + h * HD + tx * 4] = o;
    }
}

// ---------------------------------------------------------------------------

extern "C" void kernel_launch(void* const* d_in, const int* in_sizes, int n_in,
                              void* d_out, int out_size) {
    (void)in_sizes; (void)n_in; (void)out_size;
    const float* x     = (const float*)d_in[0];
    const float* w_qkv = (const float*)d_in[1];
    const float* b_qkv = (const float*)d_in[2];
    const float* w_out = (const float*)d_in[3];
    const float* b_out = (const float*)d_in[4];
    float* out = (float*)d_out;

    float* attn_ptr = nullptr;
    cudaGetSymbolAddress((void**)&attn_ptr, g_attn);

    // QKV GEMM: M=4096, N=3072
    {
        dim3 grid(3 * DM / 128, BB * SS / 128);
        qkv_gemm_kernel<<<grid, 256>>>(x, w_qkv, b_qkv);
    }
    // Flash attention
    {
        static const int smem_bytes = 3 * ATILE * sizeof(float);
        cudaFuncSetAttribute(attn_kernel, cudaFuncAttributeMaxDynamicSharedMemorySize, smem_bytes);
        dim3 grid(SS / 64, BH);
        attn_kernel<<<grid, 256, smem_bytes>>>();
    }
    // Output GEMM: M=4096, N=1024
    {
        dim3 grid(DM / 128, BB * SS / 128);
        out_gemm_kernel<<<grid, 256>>>(attn_ptr, w_out, b_out, out);
    }
}

// round 2
// speedup vs baseline: 1.1159x; 1.1159x over previous
#include <cuda_runtime.h>
#include <cstdint>

#define BB 2
#define SS 2048
#define DIN 1024
#define DM 1024
#define HH 16
#define HD 64
#define BH (BB*HH)

// Scratch (allocation-free rule: __device__ globals)
__device__ float g_q[BH*SS*HD];
__device__ float g_k[BH*SS*HD];
__device__ float g_v[BH*SS*HD];
__device__ float g_attn[BB*SS*DM];

// ---------------------------------------------------------------------------
// TF32 helpers
// ---------------------------------------------------------------------------
__device__ __forceinline__ uint32_t f2tf(float f) {
    uint32_t u;
    asm("cvt.rna.tf32.f32 %0, %1;" : "=r"(u) : "f"(f));
    return u;
}
__device__ __forceinline__ void dec_tf32(float f, uint32_t& hi, uint32_t& lo) {
    hi = f2tf(f);
    float r = f - __uint_as_float(hi);
    lo = f2tf(r);
}
__device__ __forceinline__ void mma_tf32(float c[4],
                                         uint32_t a0, uint32_t a1, uint32_t a2, uint32_t a3,
                                         uint32_t b0, uint32_t b1) {
    asm volatile(
        "mma.sync.aligned.m16n8k8.row.col.f32.tf32.tf32.f32 "
        "{%0,%1,%2,%3}, {%4,%5,%6,%7}, {%8,%9}, {%0,%1,%2,%3};"
        : "+f"(c[0]), "+f"(c[1]), "+f"(c[2]), "+f"(c[3])
        : "r"(a0), "r"(a1), "r"(a2), "r"(a3), "r"(b0), "r"(b1));
}

// ---------------------------------------------------------------------------
// 3xTF32 GEMM: C[M,N] = A[M,K] @ W[K,N] + bias, M tiles of 128, N tiles of 128,
// K-tile 32. 256 threads = 8 warps as 2(m) x 4(n), warp tile 64x32.
// smem layouts: A hi/lo [128][36] (pad 36 -> bank = (4m+k)%32, conflict-free),
//               B hi/lo [32][132] (pad 132 -> bank = (4k+n)%32, conflict-free).
// ---------------------------------------------------------------------------
#define SA_PAD 36
#define SB_PAD 132
#define SA_SZ (128 * SA_PAD)
#define SB_SZ (32 * SB_PAD)
#define GEMM_SMEM_FLOATS (2 * SA_SZ + 2 * SB_SZ)
#define GEMM_SMEM_BYTES (GEMM_SMEM_FLOATS * 4)

template <int N, int K, bool SCATTER>
__global__ void __launch_bounds__(256, 1) tf32_gemm_kernel(const float* __restrict__ A,
                                                           const float* __restrict__ W,
                                                           const float* __restrict__ bias,
                                                           float* __restrict__ out) {
    extern __shared__ uint32_t sm_u[];
    uint32_t* sAH = sm_u;
    uint32_t* sAL = sm_u + SA_SZ;
    uint32_t* sBH = sm_u + 2 * SA_SZ;
    uint32_t* sBL = sm_u + 2 * SA_SZ + SB_SZ;

    const int tid = threadIdx.x;
    const int lane = tid & 31;
    const int warp = tid >> 5;
    const int wm = warp & 1;   // 0..1 -> m offset 0/64
    const int wn = warp >> 1;  // 0..3 -> n offset 0/32/64/96
    const int g = lane >> 2;   // group 0..7
    const int t = lane & 3;    // thread-in-group

    const int mBase = blockIdx.y * 128;
    const int nBase = blockIdx.x * 128;

    // global load indices
    const int aRow = tid >> 3;        // 0..31
    const int ak4 = (tid & 7) * 4;    // 0..28
    const int bRow = tid >> 5;        // 0..7
    const int bn4 = (tid & 31) * 4;   // 0..124

    float c[2 == 2 ? 4 : 4][4][4];  // [mi][ni][4]
#pragma unroll
    for (int mi = 0; mi < 4; mi++)
#pragma unroll
        for (int ni = 0; ni < 4; ni++)
#pragma unroll
            for (int r = 0; r < 4; r++) c[mi][ni][r] = 0.f;

    for (int k0 = 0; k0 < K; k0 += 32) {
        __syncthreads();
#pragma unroll
        for (int p = 0; p < 4; p++) {
            // A: 128 rows x 32 k
            int r = aRow + p * 32;
            float4 v = *(const float4*)(A + (size_t)(mBase + r) * K + k0 + ak4);
            uint32_t h0, l0, h1, l1, h2, l2, h3, l3;
            dec_tf32(v.x, h0, l0);
            dec_tf32(v.y, h1, l1);
            dec_tf32(v.z, h2, l2);
            dec_tf32(v.w, h3, l3);
            uint32_t base = r * SA_PAD + ak4;
            uint4 hh = {h0, h1, h2, h3};
            uint4 ll = {l0, l1, l2, l3};
            *(uint4*)&sAH[base] = hh;
            *(uint4*)&sAL[base] = ll;
            // B: 32 k-rows x 128 n
            int rb = bRow + p * 8;
            float4 wv = *(const float4*)(W + (size_t)(k0 + rb) * N + nBase + bn4);
            dec_tf32(wv.x, h0, l0);
            dec_tf32(wv.y, h1, l1);
            dec_tf32(wv.z, h2, l2);
            dec_tf32(wv.w, h3, l3);
            uint32_t bbase = rb * SB_PAD + bn4;
            uint4 bh = {h0, h1, h2, h3};
            uint4 bl = {l0, l1, l2, l3};
            *(uint4*)&sBH[bbase] = bh;
            *(uint4*)&sBL[bbase] = bl;
        }
        __syncthreads();

#pragma unroll
        for (int ks = 0; ks < 4; ks++) {
            const int kk = ks * 8;
            uint32_t ah[4][4], al[4][4];
#pragma unroll
            for (int mi = 0; mi < 4; mi++) {
                int m0 = wm * 64 + mi * 16;
                int i00 = (m0 + g) * SA_PAD + kk + t;
                int i10 = (m0 + g + 8) * SA_PAD + kk + t;
                ah[mi][0] = sAH[i00];
                ah[mi][1] = sAH[i10];
                ah[mi][2] = sAH[i00 + 4];
                ah[mi][3] = sAH[i10 + 4];
                al[mi][0] = sAL[i00];
                al[mi][1] = sAL[i10];
                al[mi][2] = sAL[i00 + 4];
                al[mi][3] = sAL[i10 + 4];
            }
            uint32_t bh[4][2], bl[4][2];
#pragma unroll
            for (int ni = 0; ni < 4; ni++) {
                int n0 = wn * 32 + ni * 8;
                int j0 = (kk + t) * SB_PAD + n0 + g;
                int j1 = (kk + t + 4) * SB_PAD + n0 + g;
                bh[ni][0] = sBH[j0];
                bh[ni][1] = sBH[j1];
                bl[ni][0] = sBL[j0];
                bl[ni][1] = sBL[j1];
            }
#pragma unroll
            for (int mi = 0; mi < 4; mi++)
#pragma unroll
                for (int ni = 0; ni < 4; ni++) {
                    mma_tf32(c[mi][ni], al[mi][0], al[mi][1], al[mi][2], al[mi][3],
                             bh[ni][0], bh[ni][1]);
                    mma_tf32(c[mi][ni], ah[mi][0], ah[mi][1], ah[mi][2], ah[mi][3],
                             bl[ni][0], bl[ni][1]);
                    mma_tf32(c[mi][ni], ah[mi][0], ah[mi][1], ah[mi][2], ah[mi][3],
                             bh[ni][0], bh[ni][1]);
                }
        }
    }

    // Epilogue
#pragma unroll
    for (int mi = 0; mi < 4; mi++) {
#pragma unroll
        for (int ni = 0; ni < 4; ni++) {
#pragma unroll
            for (int half = 0; half < 2; half++) {
                int m = mBase + wm * 64 + mi * 16 + g + half * 8;
                int n = nBase + wn * 32 + ni * 8 + t * 2;
                float v0 = c[mi][ni][half * 2 + 0] + bias[n];
                float v1 = c[mi][ni][half * 2 + 1] + bias[n + 1];
                if (SCATTER) {
                    // n in [0,3072): h = n/192, type = (n%192)/64, d = n%64
                    int b = m >> 11;
                    int s = m & (SS - 1);
                    int h = n / 192;
                    int rem = n - h * 192;
                    int ty2 = rem >> 6;
                    int d = rem & 63;
                    int idx = ((b * HH + h) * SS + s) * HD + d;
                    float* dst = (ty2 == 0) ? g_q : (ty2 == 1) ? g_k : g_v;
                    dst[idx] = v0;
                    dst[idx + 1] = v1;  // d and d+1 stay in same 64-block (n even)
                } else {
                    *(float2*)(out + (size_t)m * N + n) = make_float2(v0, v1);
                }
            }
        }
    }
}

// ---------------------------------------------------------------------------
// Flash attention, fp32, causal. 64x64 tiles, 256 threads. (unchanged)
// ---------------------------------------------------------------------------
#define APAD 68
#define ATILE (64 * APAD)

__global__ void __launch_bounds__(256) attn_kernel() {
    extern __shared__ float sm[];
    float* sQ = sm;              // [d][row]
    float* sK = sm + ATILE;      // [d][col]; later aliased as sP [row][kk]
    float* sV = sm + 2 * ATILE;  // [kvrow][d]

    int tid = threadIdx.x;
    int tx = tid & 15, ty = tid >> 4;
    int qt = blockIdx.x;
    int bh = blockIdx.y;
    int b = bh >> 4, h = bh & 15;
    int qBase = qt * 64;

    const float scale = 0.125f;
    const float* Qg = g_q + (bh * SS + qBase) * HD;
    const float* Kg = g_k + bh * SS * HD;
    const float* Vg = g_v + bh * SS * HD;

    {
        int lrow = tid >> 4;
        int d4 = (tid & 15) * 4;
#pragma unroll
        for (int p = 0; p < 4; p++) {
            int row = lrow + p * 16;
            float4 v = *(const float4*)(Qg + row * HD + d4);
            sQ[(d4 + 0) * APAD + row] = v.x * scale;
            sQ[(d4 + 1) * APAD + row] = v.y * scale;
            sQ[(d4 + 2) * APAD + row] = v.z * scale;
            sQ[(d4 + 3) * APAD + row] = v.w * scale;
        }
    }

    float acc[4][4];
    float mrow[4], lrow_[4];
#pragma unroll
    for (int i = 0; i < 4; i++) {
        mrow[i] = -1e30f;
        lrow_[i] = 0.f;
#pragma unroll
        for (int j = 0; j < 4; j++) acc[i][j] = 0.f;
    }

    int ldrow = tid >> 4;
    int ldd4 = (tid & 15) * 4;

    for (int j = 0; j <= qt; j++) {
        __syncthreads();
        const float* Kt = Kg + j * 64 * HD;
        const float* Vt = Vg + j * 64 * HD;
#pragma unroll
        for (int p = 0; p < 4; p++) {
            int row = ldrow + p * 16;
            float4 kv = *(const float4*)(Kt + row * HD + ldd4);
            sK[(ldd4 + 0) * APAD + row] = kv.x;
            sK[(ldd4 + 1) * APAD + row] = kv.y;
            sK[(ldd4 + 2) * APAD + row] = kv.z;
            sK[(ldd4 + 3) * APAD + row] = kv.w;
            float4 vv = *(const float4*)(Vt + row * HD + ldd4);
            *(float4*)&sV[row * APAD + ldd4] = vv;
        }
        __syncthreads();

        float s[4][4];
#pragma unroll
        for (int i = 0; i < 4; i++)
#pragma unroll
            for (int cc = 0; cc < 4; cc++) s[i][cc] = 0.f;
#pragma unroll 8
        for (int d = 0; d < 64; d++) {
            float4 qv = *(float4*)&sQ[d * APAD + ty * 4];
            float4 kv = *(float4*)&sK[d * APAD + tx * 4];
            float qa[4] = {qv.x, qv.y, qv.z, qv.w};
            float ka[4] = {kv.x, kv.y, kv.z, kv.w};
#pragma unroll
            for (int i = 0; i < 4; i++)
#pragma unroll
                for (int cc = 0; cc < 4; cc++) s[i][cc] += qa[i] * ka[cc];
        }

        if (j == qt) {
#pragma unroll
            for (int i = 0; i < 4; i++) {
                int qr = ty * 4 + i;
#pragma unroll
                for (int cc = 0; cc < 4; cc++) {
                    int kc = tx * 4 + cc;
                    if (kc > qr) s[i][cc] = -1e30f;
                }
            }
        }

#pragma unroll
        for (int i = 0; i < 4; i++) {
            float mloc = fmaxf(fmaxf(s[i][0], s[i][1]), fmaxf(s[i][2], s[i][3]));
#pragma unroll
            for (int o = 8; o >= 1; o >>= 1)
                mloc = fmaxf(mloc, __shfl_xor_sync(0xffffffffu, mloc, o));
            float mnew = fmaxf(mrow[i], mloc);
            float alpha = __expf(mrow[i] - mnew);
            float lsum = 0.f;
#pragma unroll
            for (int cc = 0; cc < 4; cc++) {
                float p = __expf(s[i][cc] - mnew);
                s[i][cc] = p;
                lsum += p;
            }
#pragma unroll
            for (int o = 8; o >= 1; o >>= 1)
                lsum += __shfl_xor_sync(0xffffffffu, lsum, o);
            lrow_[i] = lrow_[i] * alpha + lsum;
            mrow[i] = mnew;
#pragma unroll
            for (int cc = 0; cc < 4; cc++) acc[i][cc] *= alpha;
        }

        __syncthreads();
        float* sP = sK;
#pragma unroll
        for (int i = 0; i < 4; i++)
#pragma unroll
            for (int cc = 0; cc < 4; cc++)
                sP[(ty * 4 + i) * APAD + tx * 4 + cc] = s[i][cc];
        __syncthreads();

#pragma unroll 8
        for (int kk = 0; kk < 64; kk++) {
            float4 vv = *(float4*)&sV[kk * APAD + tx * 4];
            float va[4] = {vv.x, vv.y, vv.z, vv.w};
            float p0 = sP[(ty * 4 + 0) * APAD + kk];
            float p1 = sP[(ty * 4 + 1) * APAD + kk];
            float p2 = sP[(ty * 4 + 2) * APAD + kk];
            float p3 = sP[(ty * 4 + 3) * APAD + kk];
#pragma unroll
            for (int cc = 0; cc < 4; cc++) {
                acc[0][cc] += p0 * va[cc];
                acc[1][cc] += p1 * va[cc];
                acc[2][cc] += p2 * va[cc];
                acc[3][cc] += p3 * va[cc];
            }
        }
    }

#pragma unroll
    for (int i = 0; i < 4; i++) {
        int srow = qBase + ty * 4 + i;
        float inv = 1.0f / lrow_[i];
        float4 o;
        o.x = acc[i][0] * inv;
        o.y = acc[i][1] * inv;
        o.z = acc[i][2] * inv;
        o.w = acc[i][3] * inv;
        *(float4*)&g_attn[(b * SS + srow) * DM + h * HD + tx * 4] = o;
    }
}

// ---------------------------------------------------------------------------

extern "C" void kernel_launch(void* const* d_in, const int* in_sizes, int n_in,
                              void* d_out, int out_size) {
    (void)in_sizes; (void)n_in; (void)out_size;
    const float* x     = (const float*)d_in[0];
    const float* w_qkv = (const float*)d_in[1];
    const float* b_qkv = (const float*)d_in[2];
    const float* w_out = (const float*)d_in[3];
    const float* b_out = (const float*)d_in[4];
    float* out = (float*)d_out;

    float* attn_ptr = nullptr;
    cudaGetSymbolAddress((void**)&attn_ptr, g_attn);

    // QKV GEMM: M=4096, N=3072, K=1024 (3xTF32 tensor core)
    {
        cudaFuncSetAttribute(tf32_gemm_kernel<3 * DM, DIN, true>,
                             cudaFuncAttributeMaxDynamicSharedMemorySize, GEMM_SMEM_BYTES);
        dim3 grid(3 * DM / 128, BB * SS / 128);
        tf32_gemm_kernel<3 * DM, DIN, true><<<grid, 256, GEMM_SMEM_BYTES>>>(x, w_qkv, b_qkv, nullptr);
    }
    // Flash attention (fp32)
    {
        const int smem_bytes = 3 * ATILE * sizeof(float);
        cudaFuncSetAttribute(attn_kernel, cudaFuncAttributeMaxDynamicSharedMemorySize, smem_bytes);
        dim3 grid(SS / 64, BH);
        attn_kernel<<<grid, 256, smem_bytes>>>();
    }
    // Output GEMM: M=4096, N=1024, K=1024 (3xTF32 tensor core)
    {
        cudaFuncSetAttribute(tf32_gemm_kernel<DM, DM, false>,
                             cudaFuncAttributeMaxDynamicSharedMemorySize, GEMM_SMEM_BYTES);
        dim3 grid(DM / 128, BB * SS / 128);
        tf32_gemm_kernel<DM, DM, false><<<grid, 256, GEMM_SMEM_BYTES>>>(attn_ptr, w_out, b_out, out);
    }
}

// round 3
// speedup vs baseline: 1.3449x; 1.2051x over previous
#include <cuda_runtime.h>
#include <cstdint>

#define BB 2
#define SS 2048
#define DIN 1024
#define DM 1024
#define HH 16
#define HD 64
#define BH (BB*HH)

// ---------------------------------------------------------------------------
// Scratch (__device__ globals; no allocation allowed)
// ---------------------------------------------------------------------------
__device__ float g_q[BH*SS*HD];
__device__ float g_k[BH*SS*HD];
__device__ float g_v[BH*SS*HD];
__device__ float g_xh[BB*SS*DIN];
__device__ float g_xl[BB*SS*DIN];
__device__ float g_wqh[DIN*3*DM];
__device__ float g_wql[DIN*3*DM];
__device__ float g_woh[DM*DM];
__device__ float g_wol[DM*DM];
__device__ float g_attn_h[BB*SS*DM];
__device__ float g_attn_l[BB*SS*DM];

// ---------------------------------------------------------------------------
// TF32 helpers
// ---------------------------------------------------------------------------
__device__ __forceinline__ uint32_t f2tf(float f) {
    uint32_t u;
    asm("cvt.rna.tf32.f32 %0, %1;" : "=r"(u) : "f"(f));
    return u;
}
__device__ __forceinline__ float tf_hi(float f) { return __uint_as_float(f2tf(f)); }
__device__ __forceinline__ float tf_lo(float f, float hi) { return __uint_as_float(f2tf(f - hi)); }

__device__ __forceinline__ void mma_tf32(float c[4],
                                         uint32_t a0, uint32_t a1, uint32_t a2, uint32_t a3,
                                         uint32_t b0, uint32_t b1) {
    asm volatile(
        "mma.sync.aligned.m16n8k8.row.col.f32.tf32.tf32.f32 "
        "{%0,%1,%2,%3}, {%4,%5,%6,%7}, {%8,%9}, {%0,%1,%2,%3};"
        : "+f"(c[0]), "+f"(c[1]), "+f"(c[2]), "+f"(c[3])
        : "r"(a0), "r"(a1), "r"(a2), "r"(a3), "r"(b0), "r"(b1));
}

__device__ __forceinline__ void cp16(uint32_t dst, const void* src) {
    asm volatile("cp.async.ca.shared.global [%0], [%1], 16;" :: "r"(dst), "l"(src));
}
__device__ __forceinline__ void cp_commit() { asm volatile("cp.async.commit_group;"); }
template <int n>
__device__ __forceinline__ void cp_wait() { asm volatile("cp.async.wait_group %0;" :: "n"(n)); }

// ---------------------------------------------------------------------------
// Decompose kernel: src -> (hi, lo) tf32 pairs
// ---------------------------------------------------------------------------
__global__ void dec_kernel(const float* __restrict__ src, float* __restrict__ h,
                           float* __restrict__ l, int n4) {
    int i = blockIdx.x * blockDim.x + threadIdx.x;
    if (i >= n4) return;
    float4 v = ((const float4*)src)[i];
    float4 hv, lv;
    hv.x = tf_hi(v.x); lv.x = tf_lo(v.x, hv.x);
    hv.y = tf_hi(v.y); lv.y = tf_lo(v.y, hv.y);
    hv.z = tf_hi(v.z); lv.z = tf_lo(v.z, hv.z);
    hv.w = tf_hi(v.w); lv.w = tf_lo(v.w, hv.w);
    ((float4*)h)[i] = hv;
    ((float4*)l)[i] = lv;
}

// ---------------------------------------------------------------------------
// 3xTF32 GEMM with pre-decomposed inputs + cp.async double buffering.
// Tile 128x128x32, 256 threads = 8 warps (2m x 4n), warp tile 64x32.
// smem A [128][36] (hi,lo), B [32][132] (hi,lo), two stages.
// ---------------------------------------------------------------------------
#define SA_PAD 36
#define SB_PAD 132
#define SA_SZ (128 * SA_PAD)     // 4608 floats
#define SB_SZ (32 * SB_PAD)      // 4224 floats
#define STG_FL (2 * SA_SZ + 2 * SB_SZ)   // 17664 floats per stage
#define GEMM2_SMEM_BYTES (2 * STG_FL * 4)  // 141312 bytes

template <int N, int K, bool SCATTER>
__global__ void __launch_bounds__(256, 1) tf32_gemm2(const float* __restrict__ Ah,
                                                     const float* __restrict__ Al,
                                                     const float* __restrict__ Wh,
                                                     const float* __restrict__ Wl,
                                                     const float* __restrict__ bias,
                                                     float* __restrict__ out) {
    extern __shared__ float smf[];
    const int tid = threadIdx.x;
    const int lane = tid & 31;
    const int warp = tid >> 5;
    const int wm = warp & 1;
    const int wn = warp >> 1;
    const int g = lane >> 2;
    const int t = lane & 3;
    const int mBase = blockIdx.y * 128;
    const int nBase = blockIdx.x * 128;

    const int aRow = tid >> 3;       // 0..31
    const int ak4 = (tid & 7) * 4;   // 0..28
    const int bRow = tid >> 5;       // 0..7
    const int bn4 = (tid & 31) * 4;  // 0..124

    auto loadStage = [&](int buf, int k0) {
        float* s = smf + buf * STG_FL;
        uint32_t sAh = (uint32_t)__cvta_generic_to_shared(s);
        uint32_t sAl = (uint32_t)__cvta_generic_to_shared(s + SA_SZ);
        uint32_t sBh = (uint32_t)__cvta_generic_to_shared(s + 2 * SA_SZ);
        uint32_t sBl = (uint32_t)__cvta_generic_to_shared(s + 2 * SA_SZ + SB_SZ);
#pragma unroll
        for (int p = 0; p < 4; p++) {
            int r = aRow + p * 32;
            size_t goff = (size_t)(mBase + r) * K + k0 + ak4;
            uint32_t soff = (r * SA_PAD + ak4) * 4;
            cp16(sAh + soff, Ah + goff);
            cp16(sAl + soff, Al + goff);
            int rb = bRow + p * 8;
            size_t gboff = (size_t)(k0 + rb) * N + nBase + bn4;
            uint32_t sboff = (rb * SB_PAD + bn4) * 4;
            cp16(sBh + sboff, Wh + gboff);
            cp16(sBl + sboff, Wl + gboff);
        }
    };

    float c[4][4][4];
#pragma unroll
    for (int mi = 0; mi < 4; mi++)
#pragma unroll
        for (int ni = 0; ni < 4; ni++)
#pragma unroll
            for (int r = 0; r < 4; r++) c[mi][ni][r] = 0.f;

    const int KT = K / 32;
    loadStage(0, 0);
    cp_commit();

    for (int kt = 0; kt < KT; kt++) {
        if (kt + 1 < KT) {
            loadStage((kt + 1) & 1, (kt + 1) * 32);
            cp_commit();
            cp_wait<1>();
        } else {
            cp_wait<0>();
        }
        __syncthreads();

        const float* s = smf + (kt & 1) * STG_FL;
        const float* sAH = s;
        const float* sAL = s + SA_SZ;
        const float* sBH = s + 2 * SA_SZ;
        const float* sBL = s + 2 * SA_SZ + SB_SZ;

#pragma unroll
        for (int ks = 0; ks < 4; ks++) {
            const int kk = ks * 8;
            uint32_t ah[4][4], al[4][4];
#pragma unroll
            for (int mi = 0; mi < 4; mi++) {
                int m0 = wm * 64 + mi * 16;
                int i00 = (m0 + g) * SA_PAD + kk + t;
                int i10 = (m0 + g + 8) * SA_PAD + kk + t;
                ah[mi][0] = __float_as_uint(sAH[i00]);
                ah[mi][1] = __float_as_uint(sAH[i10]);
                ah[mi][2] = __float_as_uint(sAH[i00 + 4]);
                ah[mi][3] = __float_as_uint(sAH[i10 + 4]);
                al[mi][0] = __float_as_uint(sAL[i00]);
                al[mi][1] = __float_as_uint(sAL[i10]);
                al[mi][2] = __float_as_uint(sAL[i00 + 4]);
                al[mi][3] = __float_as_uint(sAL[i10 + 4]);
            }
            uint32_t bh[4][2], bl[4][2];
#pragma unroll
            for (int ni = 0; ni < 4; ni++) {
                int n0 = wn * 32 + ni * 8;
                int j0 = (kk + t) * SB_PAD + n0 + g;
                int j1 = (kk + t + 4) * SB_PAD + n0 + g;
                bh[ni][0] = __float_as_uint(sBH[j0]);
                bh[ni][1] = __float_as_uint(sBH[j1]);
                bl[ni][0] = __float_as_uint(sBL[j0]);
                bl[ni][1] = __float_as_uint(sBL[j1]);
            }
#pragma unroll
            for (int mi = 0; mi < 4; mi++)
#pragma unroll
                for (int ni = 0; ni < 4; ni++) {
                    mma_tf32(c[mi][ni], al[mi][0], al[mi][1], al[mi][2], al[mi][3],
                             bh[ni][0], bh[ni][1]);
                    mma_tf32(c[mi][ni], ah[mi][0], ah[mi][1], ah[mi][2], ah[mi][3],
                             bl[ni][0], bl[ni][1]);
                    mma_tf32(c[mi][ni], ah[mi][0], ah[mi][1], ah[mi][2], ah[mi][3],
                             bh[ni][0], bh[ni][1]);
                }
        }
        __syncthreads();
    }

    // Epilogue
#pragma unroll
    for (int mi = 0; mi < 4; mi++) {
#pragma unroll
        for (int ni = 0; ni < 4; ni++) {
#pragma unroll
            for (int half = 0; half < 2; half++) {
                int m = mBase + wm * 64 + mi * 16 + g + half * 8;
                int n = nBase + wn * 32 + ni * 8 + t * 2;
                float v0 = c[mi][ni][half * 2 + 0] + bias[n];
                float v1 = c[mi][ni][half * 2 + 1] + bias[n + 1];
                if (SCATTER) {
                    int b = m >> 11;
                    int s2 = m & (SS - 1);
                    int h = n / 192;
                    int rem = n - h * 192;
                    int ty2 = rem >> 6;
                    int d = rem & 63;
                    int idx = ((b * HH + h) * SS + s2) * HD + d;
                    float* dst = (ty2 == 0) ? g_q : (ty2 == 1) ? g_k : g_v;
                    dst[idx] = v0;
                    dst[idx + 1] = v1;
                } else {
                    *(float2*)(out + (size_t)m * N + n) = make_float2(v0, v1);
                }
            }
        }
    }
}

// ---------------------------------------------------------------------------
// TF32 flash attention. Q tile 128 rows, KV tile 64, 8 warps, each warp owns
// 16 exclusive Q rows -> warp-local softmax. 3-term tf32 mma for both GEMMs.
// smem (floats): Qh[128][68] Ql | Kh[64][68] Kl | VTh[64][68] VTl | Ph[128][68] Pl
// ---------------------------------------------------------------------------
#define AP 68
#define ATTN_SMEM_FLOATS (2*128*AP + 2*64*AP + 2*64*AP + 2*128*AP)
#define ATTN_SMEM_BYTES (ATTN_SMEM_FLOATS * 4)   // 208896

__global__ void __launch_bounds__(256, 1) attn_kernel2() {
    extern __shared__ float smf[];
    float* sQh = smf;                    // [128][68]
    float* sQl = smf + 128 * AP;
    float* sKh = smf + 2 * 128 * AP;     // [64][68]
    float* sKl = sKh + 64 * AP;
    float* sVh = sKl + 64 * AP;          // [d][kv] transposed
    float* sVl = sVh + 64 * AP;
    float* sPh = sVl + 64 * AP;          // [128][68]
    float* sPl = sPh + 128 * AP;

    const int tid = threadIdx.x;
    const int lane = tid & 31;
    const int warp = tid >> 5;
    const int g = lane >> 2;
    const int t = lane & 3;
    const int qt = (gridDim.x - 1) - blockIdx.x;  // heavy tiles first
    const int bh = blockIdx.y;
    const int b = bh >> 4, h = bh & 15;
    const int qBase = qt * 128;
    const int m0 = warp * 16;

    const float* Qg = g_q + (size_t)(bh * SS + qBase) * HD;
    const float* Kg = g_k + (size_t)bh * SS * HD;
    const float* Vg = g_v + (size_t)bh * SS * HD;

    // Load Q: scale, decompose, store [m][k]
    {
        int lr = tid >> 4;
        int d4 = (tid & 15) * 4;
#pragma unroll
        for (int p = 0; p < 8; p++) {
            int row = lr + p * 16;
            float4 v = *(const float4*)(Qg + row * HD + d4);
            v.x *= 0.125f; v.y *= 0.125f; v.z *= 0.125f; v.w *= 0.125f;
            float4 hv, lv;
            hv.x = tf_hi(v.x); lv.x = tf_lo(v.x, hv.x);
            hv.y = tf_hi(v.y); lv.y = tf_lo(v.y, hv.y);
            hv.z = tf_hi(v.z); lv.z = tf_lo(v.z, hv.z);
            hv.w = tf_hi(v.w); lv.w = tf_lo(v.w, hv.w);
            *(float4*)&sQh[row * AP + d4] = hv;
            *(float4*)&sQl[row * AP + d4] = lv;
        }
    }

    float m_[2] = {-1e30f, -1e30f};
    float l_[2] = {0.f, 0.f};
    float co[8][4];
#pragma unroll
    for (int ni = 0; ni < 8; ni++)
#pragma unroll
        for (int r = 0; r < 4; r++) co[ni][r] = 0.f;

    const int jmax = 2 * qt + 1;
    for (int j = 0; j <= jmax; j++) {
        const int kvBase = j * 64;
        __syncthreads();  // previous iter's K/V reads complete (also orders Q stores on j=0)
        // Load + decompose K (row-major) and V (transposed)
        {
            int lr = tid >> 4;
            int d4 = (tid & 15) * 4;
            const float* Kt = Kg + (size_t)kvBase * HD;
            const float* Vt = Vg + (size_t)kvBase * HD;
#pragma unroll
            for (int p = 0; p < 4; p++) {
                int row = lr + p * 16;
                float4 kv = *(const float4*)(Kt + row * HD + d4);
                float4 hv, lv;
                hv.x = tf_hi(kv.x); lv.x = tf_lo(kv.x, hv.x);
                hv.y = tf_hi(kv.y); lv.y = tf_lo(kv.y, hv.y);
                hv.z = tf_hi(kv.z); lv.z = tf_lo(kv.z, hv.z);
                hv.w = tf_hi(kv.w); lv.w = tf_lo(kv.w, hv.w);
                *(float4*)&sKh[row * AP + d4] = hv;
                *(float4*)&sKl[row * AP + d4] = lv;
                float4 vv = *(const float4*)(Vt + row * HD + d4);
                float vh0 = tf_hi(vv.x), vh1 = tf_hi(vv.y), vh2 = tf_hi(vv.z), vh3 = tf_hi(vv.w);
                sVh[(d4 + 0) * AP + row] = vh0;
                sVh[(d4 + 1) * AP + row] = vh1;
                sVh[(d4 + 2) * AP + row] = vh2;
                sVh[(d4 + 3) * AP + row] = vh3;
                sVl[(d4 + 0) * AP + row] = tf_lo(vv.x, vh0);
                sVl[(d4 + 1) * AP + row] = tf_lo(vv.y, vh1);
                sVl[(d4 + 2) * AP + row] = tf_lo(vv.z, vh2);
                sVl[(d4 + 3) * AP + row] = tf_lo(vv.w, vh3);
            }
        }
        __syncthreads();

        if (kvBase > qBase + m0 + 15) continue;  // warp tile fully masked

        // Scores S = Q K^T (3-term tf32)
        float sc[8][4];
#pragma unroll
        for (int ni = 0; ni < 8; ni++)
#pragma unroll
            for (int r = 0; r < 4; r++) sc[ni][r] = 0.f;
#pragma unroll
        for (int ks = 0; ks < 8; ks++) {
            const int kk = ks * 8;
            int i0 = (m0 + g) * AP + kk + t;
            int i1 = (m0 + g + 8) * AP + kk + t;
            uint32_t qh[4] = {__float_as_uint(sQh[i0]), __float_as_uint(sQh[i1]),
                              __float_as_uint(sQh[i0 + 4]), __float_as_uint(sQh[i1 + 4])};
            uint32_t ql[4] = {__float_as_uint(sQl[i0]), __float_as_uint(sQl[i1]),
                              __float_as_uint(sQl[i0 + 4]), __float_as_uint(sQl[i1 + 4])};
#pragma unroll
            for (int ni = 0; ni < 8; ni++) {
                int bi = (ni * 8 + g) * AP + kk + t;
                uint32_t kh0 = __float_as_uint(sKh[bi]);
                uint32_t kh1 = __float_as_uint(sKh[bi + 4]);
                uint32_t kl0 = __float_as_uint(sKl[bi]);
                uint32_t kl1 = __float_as_uint(sKl[bi + 4]);
                mma_tf32(sc[ni], ql[0], ql[1], ql[2], ql[3], kh0, kh1);
                mma_tf32(sc[ni], qh[0], qh[1], qh[2], qh[3], kl0, kl1);
                mma_tf32(sc[ni], qh[0], qh[1], qh[2], qh[3], kh0, kh1);
            }
        }

        // Causal mask (tiles overlapping the diagonal)
        if (kvBase + 63 > qBase + m0) {
#pragma unroll
            for (int ni = 0; ni < 8; ni++) {
#pragma unroll
                for (int r = 0; r < 4; r++) {
                    int row = qBase + m0 + g + ((r >= 2) ? 8 : 0);
                    int col = kvBase + ni * 8 + 2 * t + (r & 1);
                    if (col > row) sc[ni][r] = -1e30f;
                }
            }
        }

        // Warp-local online softmax (rows g and g+8)
        float mx0 = -1e30f, mx1 = -1e30f;
#pragma unroll
        for (int ni = 0; ni < 8; ni++) {
            mx0 = fmaxf(mx0, fmaxf(sc[ni][0], sc[ni][1]));
            mx1 = fmaxf(mx1, fmaxf(sc[ni][2], sc[ni][3]));
        }
#pragma unroll
        for (int o = 1; o <= 2; o <<= 1) {
            mx0 = fmaxf(mx0, __shfl_xor_sync(0xffffffffu, mx0, o));
            mx1 = fmaxf(mx1, __shfl_xor_sync(0xffffffffu, mx1, o));
        }
        float mn0 = fmaxf(m_[0], mx0), mn1 = fmaxf(m_[1], mx1);
        float a0 = __expf(m_[0] - mn0), a1 = __expf(m_[1] - mn1);
        float s0 = 0.f, s1 = 0.f;
#pragma unroll
        for (int ni = 0; ni < 8; ni++) {
            sc[ni][0] = __expf(sc[ni][0] - mn0);
            sc[ni][1] = __expf(sc[ni][1] - mn0);
            sc[ni][2] = __expf(sc[ni][2] - mn1);
            sc[ni][3] = __expf(sc[ni][3] - mn1);
            s0 += sc[ni][0] + sc[ni][1];
            s1 += sc[ni][2] + sc[ni][3];
        }
#pragma unroll
        for (int o = 1; o <= 2; o <<= 1) {
            s0 += __shfl_xor_sync(0xffffffffu, s0, o);
            s1 += __shfl_xor_sync(0xffffffffu, s1, o);
        }
        l_[0] = l_[0] * a0 + s0; m_[0] = mn0;
        l_[1] = l_[1] * a1 + s1; m_[1] = mn1;
#pragma unroll
        for (int ni = 0; ni < 8; ni++) {
            co[ni][0] *= a0; co[ni][1] *= a0;
            co[ni][2] *= a1; co[ni][3] *= a1;
        }

        // Store P (hi/lo) — warp-exclusive rows, only __syncwarp needed
#pragma unroll
        for (int ni = 0; ni < 8; ni++) {
            int b0 = (m0 + g) * AP + ni * 8 + 2 * t;
            int b1 = (m0 + g + 8) * AP + ni * 8 + 2 * t;
            float h0 = tf_hi(sc[ni][0]), h1 = tf_hi(sc[ni][1]);
            float h2 = tf_hi(sc[ni][2]), h3 = tf_hi(sc[ni][3]);
            *(float2*)&sPh[b0] = make_float2(h0, h1);
            *(float2*)&sPh[b1] = make_float2(h2, h3);
            *(float2*)&sPl[b0] = make_float2(tf_lo(sc[ni][0], h0), tf_lo(sc[ni][1], h1));
            *(float2*)&sPl[b1] = make_float2(tf_lo(sc[ni][2], h2), tf_lo(sc[ni][3], h3));
        }
        __syncwarp();

        // O += P @ V (3-term tf32)
#pragma unroll
        for (int ks = 0; ks < 8; ks++) {
            const int kk = ks * 8;
            int i0 = (m0 + g) * AP + kk + t;
            int i1 = (m0 + g + 8) * AP + kk + t;
            uint32_t ph[4] = {__float_as_uint(sPh[i0]), __float_as_uint(sPh[i1]),
                              __float_as_uint(sPh[i0 + 4]), __float_as_uint(sPh[i1 + 4])};
            uint32_t pl[4] = {__float_as_uint(sPl[i0]), __float_as_uint(sPl[i1]),
                              __float_as_uint(sPl[i0 + 4]), __float_as_uint(sPl[i1 + 4])};
#pragma unroll
            for (int ni = 0; ni < 8; ni++) {
                int bi = (ni * 8 + g) * AP + kk + t;
                uint32_t vh0 = __float_as_uint(sVh[bi]);
                uint32_t vh1 = __float_as_uint(sVh[bi + 4]);
                uint32_t vl0 = __float_as_uint(sVl[bi]);
                uint32_t vl1 = __float_as_uint(sVl[bi + 4]);
                mma_tf32(co[ni], pl[0], pl[1], pl[2], pl[3], vh0, vh1);
                mma_tf32(co[ni], ph[0], ph[1], ph[2], ph[3], vl0, vl1);
                mma_tf32(co[ni], ph[0], ph[1], ph[2], ph[3], vh0, vh1);
            }
        }
    }

    // Epilogue: normalize, decompose, write to g_attn_h/l
    float inv0 = 1.0f / l_[0];
    float inv1 = 1.0f / l_[1];
    int r0 = qBase + m0 + g;
    int r1 = r0 + 8;
#pragma unroll
    for (int ni = 0; ni < 8; ni++) {
        int d0 = ni * 8 + 2 * t;
        size_t i0 = (size_t)(b * SS + r0) * DM + h * HD + d0;
        size_t i1 = (size_t)(b * SS + r1) * DM + h * HD + d0;
        float v0 = co[ni][0] * inv0, v1 = co[ni][1] * inv0;
        float v2 = co[ni][2] * inv1, v3 = co[ni][3] * inv1;
        float h0 = tf_hi(v0), h1 = tf_hi(v1), h2 = tf_hi(v2), h3 = tf_hi(v3);
        *(float2*)&g_attn_h[i0] = make_float2(h0, h1);
        *(float2*)&g_attn_h[i1] = make_float2(h2, h3);
        *(float2*)&g_attn_l[i0] = make_float2(tf_lo(v0, h0), tf_lo(v1, h1));
        *(float2*)&g_attn_l[i1] = make_float2(tf_lo(v2, h2), tf_lo(v3, h3));
    }
}

// ---------------------------------------------------------------------------

extern "C" void kernel_launch(void* const* d_in, const int* in_sizes, int n_in,
                              void* d_out, int out_size) {
    (void)in_sizes; (void)n_in; (void)out_size;
    const float* x     = (const float*)d_in[0];
    const float* w_qkv = (const float*)d_in[1];
    const float* b_qkv = (const float*)d_in[2];
    const float* w_out = (const float*)d_in[3];
    const float* b_out = (const float*)d_in[4];
    float* out = (float*)d_out;

    float *xh, *xl, *wqh, *wql, *woh, *wol, *ath, *atl;
    cudaGetSymbolAddress((void**)&xh, g_xh);
    cudaGetSymbolAddress((void**)&xl, g_xl);
    cudaGetSymbolAddress((void**)&wqh, g_wqh);
    cudaGetSymbolAddress((void**)&wql, g_wql);
    cudaGetSymbolAddress((void**)&woh, g_woh);
    cudaGetSymbolAddress((void**)&wol, g_wol);
    cudaGetSymbolAddress((void**)&ath, g_attn_h);
    cudaGetSymbolAddress((void**)&atl, g_attn_l);

    // Decompose inputs to tf32 hi/lo
    dec_kernel<<<(BB*SS*DIN/4 + 255) / 256, 256>>>(x, xh, xl, BB*SS*DIN/4);
    dec_kernel<<<(DIN*3*DM/4 + 255) / 256, 256>>>(w_qkv, wqh, wql, DIN*3*DM/4);
    dec_kernel<<<(DM*DM/4 + 255) / 256, 256>>>(w_out, woh, wol, DM*DM/4);

    // QKV GEMM (scatter to per-head q/k/v)
    {
        cudaFuncSetAttribute(tf32_gemm2<3 * DM, DIN, true>,
                             cudaFuncAttributeMaxDynamicSharedMemorySize, GEMM2_SMEM_BYTES);
        dim3 grid(3 * DM / 128, BB * SS / 128);
        tf32_gemm2<3 * DM, DIN, true><<<grid, 256, GEMM2_SMEM_BYTES>>>(xh, xl, wqh, wql, b_qkv, nullptr);
    }
    // Flash attention (tf32 mma), writes decomposed output
    {
        cudaFuncSetAttribute(attn_kernel2, cudaFuncAttributeMaxDynamicSharedMemorySize, ATTN_SMEM_BYTES);
        dim3 grid(SS / 128, BH);
        attn_kernel2<<<grid, 256, ATTN_SMEM_BYTES>>>();
    }
    // Output GEMM
    {
        cudaFuncSetAttribute(tf32_gemm2<DM, DM, false>,
                             cudaFuncAttributeMaxDynamicSharedMemorySize, GEMM2_SMEM_BYTES);
        dim3 grid(DM / 128, BB * SS / 128);
        tf32_gemm2<DM, DM, false><<<grid, 256, GEMM2_SMEM_BYTES>>>(ath, atl, woh, wol, b_out, out);
    }
}

// round 5
// speedup vs baseline: 1.7689x; 1.3153x over previous
#include <cuda_runtime.h>
#include <cstdint>

#define BB 2
#define SS 2048
#define DIN 1024
#define DM 1024
#define HH 16
#define HD 64
#define BH (BB*HH)

// ---------------------------------------------------------------------------
// Scratch (__device__ globals; no allocation allowed)
// ---------------------------------------------------------------------------
__device__ float g_q[BH*SS*HD];
__device__ float g_k[BH*SS*HD];
__device__ float g_v[BH*SS*HD];
__device__ float g_xh[BB*SS*DIN];
__device__ float g_xl[BB*SS*DIN];
__device__ float g_wqh[DIN*3*DM];
__device__ float g_woh[DM*DM];
__device__ float g_attn_h[BB*SS*DM];
__device__ float g_attn_l[BB*SS*DM];

// ---------------------------------------------------------------------------
// TF32 helpers
// ---------------------------------------------------------------------------
__device__ __forceinline__ uint32_t f2tf(float f) {
    uint32_t u;
    asm("cvt.rna.tf32.f32 %0, %1;" : "=r"(u) : "f"(f));
    return u;
}
__device__ __forceinline__ float tf_hi(float f) { return __uint_as_float(f2tf(f)); }
__device__ __forceinline__ float tf_lo(float f, float hi) { return __uint_as_float(f2tf(f - hi)); }

__device__ __forceinline__ void mma_tf32(float c[4],
                                         uint32_t a0, uint32_t a1, uint32_t a2, uint32_t a3,
                                         uint32_t b0, uint32_t b1) {
    asm volatile(
        "mma.sync.aligned.m16n8k8.row.col.f32.tf32.tf32.f32 "
        "{%0,%1,%2,%3}, {%4,%5,%6,%7}, {%8,%9}, {%0,%1,%2,%3};"
        : "+f"(c[0]), "+f"(c[1]), "+f"(c[2]), "+f"(c[3])
        : "r"(a0), "r"(a1), "r"(a2), "r"(a3), "r"(b0), "r"(b1));
}

__device__ __forceinline__ void cp16(uint32_t dst, const void* src) {
    asm volatile("cp.async.ca.shared.global [%0], [%1], 16;" :: "r"(dst), "l"(src));
}
__device__ __forceinline__ void cp_commit() { asm volatile("cp.async.commit_group;"); }
template <int n>
__device__ __forceinline__ void cp_wait() { asm volatile("cp.async.wait_group %0;" :: "n"(n)); }

// ---------------------------------------------------------------------------
// Decompose kernels
// ---------------------------------------------------------------------------
__global__ void dec_kernel(const float* __restrict__ src, float* __restrict__ h,
                           float* __restrict__ l, int n4) {
    int i = blockIdx.x * blockDim.x + threadIdx.x;
    if (i >= n4) return;
    float4 v = ((const float4*)src)[i];
    float4 hv, lv;
    hv.x = tf_hi(v.x); lv.x = tf_lo(v.x, hv.x);
    hv.y = tf_hi(v.y); lv.y = tf_lo(v.y, hv.y);
    hv.z = tf_hi(v.z); lv.z = tf_lo(v.z, hv.z);
    hv.w = tf_hi(v.w); lv.w = tf_lo(v.w, hv.w);
    ((float4*)h)[i] = hv;
    ((float4*)l)[i] = lv;
}
__global__ void dec_hi_kernel(const float* __restrict__ src, float* __restrict__ h, int n4) {
    int i = blockIdx.x * blockDim.x + threadIdx.x;
    if (i >= n4) return;
    float4 v = ((const float4*)src)[i];
    float4 hv;
    hv.x = tf_hi(v.x);
    hv.y = tf_hi(v.y);
    hv.z = tf_hi(v.z);
    hv.w = tf_hi(v.w);
    ((float4*)h)[i] = hv;
}

// ---------------------------------------------------------------------------
// 2xTF32 GEMM (a_hi*b_hi + a_lo*b_hi), pre-decomposed, cp.async double buffer.
// Tile 128x128x32, 256 threads = 8 warps (2m x 4n), warp tile 64x32.
// smem/stage: Ah[128][36], Al[128][36], Bh[32][132]  -> 2 stages = 105 KB
// 2 CTAs/SM via launch_bounds.
// ---------------------------------------------------------------------------
#define SA_PAD 36
#define SB_PAD 132
#define SA_SZ (128 * SA_PAD)     // 4608 floats
#define SB_SZ (32 * SB_PAD)      // 4224 floats
#define STG_FL (2 * SA_SZ + SB_SZ)       // 13440 floats per stage
#define GEMM3_SMEM_BYTES (2 * STG_FL * 4)  // 107520 bytes

template <int N, int K, bool SCATTER>
__global__ void __launch_bounds__(256, 2) tf32_gemm3(const float* __restrict__ Ah,
                                                     const float* __restrict__ Al,
                                                     const float* __restrict__ Wh,
                                                     const float* __restrict__ bias,
                                                     float* __restrict__ out) {
    extern __shared__ float smf[];
    const int tid = threadIdx.x;
    const int lane = tid & 31;
    const int warp = tid >> 5;
    const int wm = warp & 1;
    const int wn = warp >> 1;
    const int g = lane >> 2;
    const int t = lane & 3;
    const int mBase = blockIdx.y * 128;
    const int nBase = blockIdx.x * 128;

    const int aRow = tid >> 3;       // 0..31
    const int ak4 = (tid & 7) * 4;   // 0..28
    const int bRow = tid >> 5;       // 0..7
    const int bn4 = (tid & 31) * 4;  // 0..124

    auto loadStage = [&](int buf, int k0) {
        float* s = smf + buf * STG_FL;
        uint32_t sAh = (uint32_t)__cvta_generic_to_shared(s);
        uint32_t sAl = (uint32_t)__cvta_generic_to_shared(s + SA_SZ);
        uint32_t sBh = (uint32_t)__cvta_generic_to_shared(s + 2 * SA_SZ);
#pragma unroll
        for (int p = 0; p < 4; p++) {
            int r = aRow + p * 32;
            size_t goff = (size_t)(mBase + r) * K + k0 + ak4;
            uint32_t soff = (r * SA_PAD + ak4) * 4;
            cp16(sAh + soff, Ah + goff);
            cp16(sAl + soff, Al + goff);
            int rb = bRow + p * 8;
            size_t gboff = (size_t)(k0 + rb) * N + nBase + bn4;
            uint32_t sboff = (rb * SB_PAD + bn4) * 4;
            cp16(sBh + sboff, Wh + gboff);
        }
    };

    float c[4][4][4];
#pragma unroll
    for (int mi = 0; mi < 4; mi++)
#pragma unroll
        for (int ni = 0; ni < 4; ni++)
#pragma unroll
            for (int r = 0; r < 4; r++) c[mi][ni][r] = 0.f;

    const int KT = K / 32;
    loadStage(0, 0);
    cp_commit();

    for (int kt = 0; kt < KT; kt++) {
        if (kt + 1 < KT) {
            loadStage((kt + 1) & 1, (kt + 1) * 32);
            cp_commit();
            cp_wait<1>();
        } else {
            cp_wait<0>();
        }
        __syncthreads();

        const float* s = smf + (kt & 1) * STG_FL;
        const float* sAH = s;
        const float* sAL = s + SA_SZ;
        const float* sBH = s + 2 * SA_SZ;

#pragma unroll
        for (int ks = 0; ks < 4; ks++) {
            const int kk = ks * 8;
            uint32_t ah[4][4], al[4][4];
#pragma unroll
            for (int mi = 0; mi < 4; mi++) {
                int m0 = wm * 64 + mi * 16;
                int i00 = (m0 + g) * SA_PAD + kk + t;
                int i10 = (m0 + g + 8) * SA_PAD + kk + t;
                ah[mi][0] = __float_as_uint(sAH[i00]);
                ah[mi][1] = __float_as_uint(sAH[i10]);
                ah[mi][2] = __float_as_uint(sAH[i00 + 4]);
                ah[mi][3] = __float_as_uint(sAH[i10 + 4]);
                al[mi][0] = __float_as_uint(sAL[i00]);
                al[mi][1] = __float_as_uint(sAL[i10]);
                al[mi][2] = __float_as_uint(sAL[i00 + 4]);
                al[mi][3] = __float_as_uint(sAL[i10 + 4]);
            }
            uint32_t bh[4][2];
#pragma unroll
            for (int ni = 0; ni < 4; ni++) {
                int n0 = wn * 32 + ni * 8;
                int j0 = (kk + t) * SB_PAD + n0 + g;
                int j1 = (kk + t + 4) * SB_PAD + n0 + g;
                bh[ni][0] = __float_as_uint(sBH[j0]);
                bh[ni][1] = __float_as_uint(sBH[j1]);
            }
#pragma unroll
            for (int mi = 0; mi < 4; mi++)
#pragma unroll
                for (int ni = 0; ni < 4; ni++) {
                    mma_tf32(c[mi][ni], al[mi][0], al[mi][1], al[mi][2], al[mi][3],
                             bh[ni][0], bh[ni][1]);
                    mma_tf32(c[mi][ni], ah[mi][0], ah[mi][1], ah[mi][2], ah[mi][3],
                             bh[ni][0], bh[ni][1]);
                }
        }
        __syncthreads();
    }

    // Epilogue
#pragma unroll
    for (int mi = 0; mi < 4; mi++) {
#pragma unroll
        for (int ni = 0; ni < 4; ni++) {
#pragma unroll
            for (int half = 0; half < 2; half++) {
                int m = mBase + wm * 64 + mi * 16 + g + half * 8;
                int n = nBase + wn * 32 + ni * 8 + t * 2;
                float v0 = c[mi][ni][half * 2 + 0] + bias[n];
                float v1 = c[mi][ni][half * 2 + 1] + bias[n + 1];
                if (SCATTER) {
                    int b = m >> 11;
                    int s2 = m & (SS - 1);
                    int h = n / 192;
                    int rem = n - h * 192;
                    int ty2 = rem >> 6;
                    int d = rem & 63;
                    int idx = ((b * HH + h) * SS + s2) * HD + d;
                    float* dst = (ty2 == 0) ? g_q : (ty2 == 1) ? g_k : g_v;
                    dst[idx] = v0;
                    dst[idx + 1] = v1;
                } else {
                    *(float2*)(out + (size_t)m * N + n) = make_float2(v0, v1);
                }
            }
        }
    }
}

// ---------------------------------------------------------------------------
// 2xTF32 flash attention. Q tile 128, KV tile 64, 8 warps x 16 exclusive rows.
// cp.async staging prefetch for next K/V tile. b-side (K, V) hi-only.
// smem: Qh,Ql,Ph,Pl [128][68] | Kh,VhT [64][68] | staging Ks,Vs [64][68]
// ---------------------------------------------------------------------------
#define AP 68
#define QSZ (128 * AP)
#define KSZ (64 * AP)
#define ATTN_SMEM_FLOATS (4 * QSZ + 4 * KSZ)
#define ATTN_SMEM_BYTES (ATTN_SMEM_FLOATS * 4)   // 208896

__global__ void __launch_bounds__(256, 1) attn_kernel3() {
    extern __shared__ float smf[];
    float* sQh = smf;
    float* sQl = sQh + QSZ;
    float* sPh = sQl + QSZ;
    float* sPl = sPh + QSZ;
    float* sKh = sPl + QSZ;          // [kv][d]
    float* sVh = sKh + KSZ;          // [d][kv] transposed
    float* sKs = sVh + KSZ;          // staging raw fp32
    float* sVs = sKs + KSZ;

    const int tid = threadIdx.x;
    const int lane = tid & 31;
    const int warp = tid >> 5;
    const int g = lane >> 2;
    const int t = lane & 3;
    const int qt = (gridDim.x - 1) - blockIdx.x;  // heavy tiles first
    const int bh = blockIdx.y;
    const int b = bh >> 4, h = bh & 15;
    const int qBase = qt * 128;
    const int m0 = warp * 16;

    const float* Qg = g_q + (size_t)(bh * SS + qBase) * HD;
    const float* Kg = g_k + (size_t)bh * SS * HD;
    const float* Vg = g_v + (size_t)bh * SS * HD;

    const int lr = tid >> 4;          // 0..15
    const int d4 = (tid & 15) * 4;

    // Load Q: scale, decompose, store [m][k]
#pragma unroll
    for (int p = 0; p < 8; p++) {
        int row = lr + p * 16;
        float4 v = *(const float4*)(Qg + row * HD + d4);
        v.x *= 0.125f; v.y *= 0.125f; v.z *= 0.125f; v.w *= 0.125f;
        float4 hv, lv;
        hv.x = tf_hi(v.x); lv.x = tf_lo(v.x, hv.x);
        hv.y = tf_hi(v.y); lv.y = tf_lo(v.y, hv.y);
        hv.z = tf_hi(v.z); lv.z = tf_lo(v.z, hv.z);
        hv.w = tf_hi(v.w); lv.w = tf_lo(v.w, hv.w);
        *(float4*)&sQh[row * AP + d4] = hv;
        *(float4*)&sQl[row * AP + d4] = lv;
    }

    uint32_t sKs_u = (uint32_t)__cvta_generic_to_shared(sKs);
    uint32_t sVs_u = (uint32_t)__cvta_generic_to_shared(sVs);
    auto prefetch = [&](int kvB) {
        const float* Kt = Kg + (size_t)kvB * HD;
        const float* Vt = Vg + (size_t)kvB * HD;
#pragma unroll
        for (int p = 0; p < 4; p++) {
            int row = lr + p * 16;
            uint32_t soff = (row * AP + d4) * 4;
            cp16(sKs_u + soff, Kt + row * HD + d4);
            cp16(sVs_u + soff, Vt + row * HD + d4);
        }
    };

    float m_[2] = {-1e30f, -1e30f};
    float l_[2] = {0.f, 0.f};
    float co[8][4];
#pragma unroll
    for (int ni = 0; ni < 8; ni++)
#pragma unroll
        for (int r = 0; r < 4; r++) co[ni][r] = 0.f;

    const int jmax = 2 * qt + 1;
    prefetch(0);
    cp_commit();

    for (int j = 0; j <= jmax; j++) {
        const int kvBase = j * 64;
        cp_wait<0>();
        __syncthreads();  // staging ready; prior compute done

        // Decompose staging -> Kh [kv][d] (hi), Vh [d][kv] (hi, transposed)
#pragma unroll
        for (int p = 0; p < 4; p++) {
            int row = lr + p * 16;
            float4 kv = *(float4*)&sKs[row * AP + d4];
            float4 hv;
            hv.x = tf_hi(kv.x);
            hv.y = tf_hi(kv.y);
            hv.z = tf_hi(kv.z);
            hv.w = tf_hi(kv.w);
            *(float4*)&sKh[row * AP + d4] = hv;
            float4 vv = *(float4*)&sVs[row * AP + d4];
            sVh[(d4 + 0) * AP + row] = tf_hi(vv.x);
            sVh[(d4 + 1) * AP + row] = tf_hi(vv.y);
            sVh[(d4 + 2) * AP + row] = tf_hi(vv.z);
            sVh[(d4 + 3) * AP + row] = tf_hi(vv.w);
        }
        __syncthreads();  // decompose done; staging free; Kh/Vh visible

        if (j < jmax) prefetch(kvBase + 64);
        cp_commit();

        if (kvBase > qBase + m0 + 15) continue;  // warp tile fully masked

        // Scores S = Q K^T (2-term tf32)
        float sc[8][4];
#pragma unroll
        for (int ni = 0; ni < 8; ni++)
#pragma unroll
            for (int r = 0; r < 4; r++) sc[ni][r] = 0.f;
#pragma unroll
        for (int ks = 0; ks < 8; ks++) {
            const int kk = ks * 8;
            int i0 = (m0 + g) * AP + kk + t;
            int i1 = (m0 + g + 8) * AP + kk + t;
            uint32_t qh[4] = {__float_as_uint(sQh[i0]), __float_as_uint(sQh[i1]),
                              __float_as_uint(sQh[i0 + 4]), __float_as_uint(sQh[i1 + 4])};
            uint32_t ql[4] = {__float_as_uint(sQl[i0]), __float_as_uint(sQl[i1]),
                              __float_as_uint(sQl[i0 + 4]), __float_as_uint(sQl[i1 + 4])};
#pragma unroll
            for (int ni = 0; ni < 8; ni++) {
                int bi = (ni * 8 + g) * AP + kk + t;
                uint32_t kh0 = __float_as_uint(sKh[bi]);
                uint32_t kh1 = __float_as_uint(sKh[bi + 4]);
                mma_tf32(sc[ni], ql[0], ql[1], ql[2], ql[3], kh0, kh1);
                mma_tf32(sc[ni], qh[0], qh[1], qh[2], qh[3], kh0, kh1);
            }
        }

        // Causal mask (tiles overlapping the diagonal)
        if (kvBase + 63 > qBase + m0) {
#pragma unroll
            for (int ni = 0; ni < 8; ni++) {
#pragma unroll
                for (int r = 0; r < 4; r++) {
                    int row = qBase + m0 + g + ((r >= 2) ? 8 : 0);
                    int col = kvBase + ni * 8 + 2 * t + (r & 1);
                    if (col > row) sc[ni][r] = -1e30f;
                }
            }
        }

        // Warp-local online softmax (rows g and g+8)
        float mx0 = -1e30f, mx1 = -1e30f;
#pragma unroll
        for (int ni = 0; ni < 8; ni++) {
            mx0 = fmaxf(mx0, fmaxf(sc[ni][0], sc[ni][1]));
            mx1 = fmaxf(mx1, fmaxf(sc[ni][2], sc[ni][3]));
        }
#pragma unroll
        for (int o = 1; o <= 2; o <<= 1) {
            mx0 = fmaxf(mx0, __shfl_xor_sync(0xffffffffu, mx0, o));
            mx1 = fmaxf(mx1, __shfl_xor_sync(0xffffffffu, mx1, o));
        }
        float mn0 = fmaxf(m_[0], mx0), mn1 = fmaxf(m_[1], mx1);
        float a0 = __expf(m_[0] - mn0), a1 = __expf(m_[1] - mn1);
        float s0 = 0.f, s1 = 0.f;
#pragma unroll
        for (int ni = 0; ni < 8; ni++) {
            sc[ni][0] = __expf(sc[ni][0] - mn0);
            sc[ni][1] = __expf(sc[ni][1] - mn0);
            sc[ni][2] = __expf(sc[ni][2] - mn1);
            sc[ni][3] = __expf(sc[ni][3] - mn1);
            s0 += sc[ni][0] + sc[ni][1];
            s1 += sc[ni][2] + sc[ni][3];
        }
#pragma unroll
        for (int o = 1; o <= 2; o <<= 1) {
            s0 += __shfl_xor_sync(0xffffffffu, s0, o);
            s1 += __shfl_xor_sync(0xffffffffu, s1, o);
        }
        l_[0] = l_[0] * a0 + s0; m_[0] = mn0;
        l_[1] = l_[1] * a1 + s1; m_[1] = mn1;
#pragma unroll
        for (int ni = 0; ni < 8; ni++) {
            co[ni][0] *= a0; co[ni][1] *= a0;
            co[ni][2] *= a1; co[ni][3] *= a1;
        }

        // Store P (hi/lo) — warp-exclusive rows
#pragma unroll
        for (int ni = 0; ni < 8; ni++) {
            int b0 = (m0 + g) * AP + ni * 8 + 2 * t;
            int b1 = (m0 + g + 8) * AP + ni * 8 + 2 * t;
            float h0 = tf_hi(sc[ni][0]), h1 = tf_hi(sc[ni][1]);
            float h2 = tf_hi(sc[ni][2]), h3 = tf_hi(sc[ni][3]);
            *(float2*)&sPh[b0] = make_float2(h0, h1);
            *(float2*)&sPh[b1] = make_float2(h2, h3);
            *(float2*)&sPl[b0] = make_float2(tf_lo(sc[ni][0], h0), tf_lo(sc[ni][1], h1));
            *(float2*)&sPl[b1] = make_float2(tf_lo(sc[ni][2], h2), tf_lo(sc[ni][3], h3));
        }
        __syncwarp();

        // O += P @ V (2-term tf32)
#pragma unroll
        for (int ks = 0; ks < 8; ks++) {
            const int kk = ks * 8;
            int i0 = (m0 + g) * AP + kk + t;
            int i1 = (m0 + g + 8) * AP + kk + t;
            uint32_t ph[4] = {__float_as_uint(sPh[i0]), __float_as_uint(sPh[i1]),
                              __float_as_uint(sPh[i0 + 4]), __float_as_uint(sPh[i1 + 4])};
            uint32_t pl[4] = {__float_as_uint(sPl[i0]), __float_as_uint(sPl[i1]),
                              __float_as_uint(sPl[i0 + 4]), __float_as_uint(sPl[i1 + 4])};
#pragma unroll
            for (int ni = 0; ni < 8; ni++) {
                int bi = (ni * 8 + g) * AP + kk + t;
                uint32_t vh0 = __float_as_uint(sVh[bi]);
                uint32_t vh1 = __float_as_uint(sVh[bi + 4]);
                mma_tf32(co[ni], pl[0], pl[1], pl[2], pl[3], vh0, vh1);
                mma_tf32(co[ni], ph[0], ph[1], ph[2], ph[3], vh0, vh1);
            }
        }
    }

    // Epilogue: normalize, decompose, write to g_attn_h/l
    float inv0 = 1.0f / l_[0];
    float inv1 = 1.0f / l_[1];
    int r0 = qBase + m0 + g;
    int r1 = r0 + 8;
#pragma unroll
    for (int ni = 0; ni < 8; ni++) {
        int d0 = ni * 8 + 2 * t;
        size_t i0 = (size_t)(b * SS + r0) * DM + h * HD + d0;
        size_t i1 = (size_t)(b * SS + r1) * DM + h * HD + d0;
        float v0 = co[ni][0] * inv0, v1 = co[ni][1] * inv0;
        float v2 = co[ni][2] * inv1, v3 = co[ni][3] * inv1;
        float h0 = tf_hi(v0), h1 = tf_hi(v1), h2 = tf_hi(v2), h3 = tf_hi(v3);
        *(float2*)&g_attn_h[i0] = make_float2(h0, h1);
        *(float2*)&g_attn_h[i1] = make_float2(h2, h3);
        *(float2*)&g_attn_l[i0] = make_float2(tf_lo(v0, h0), tf_lo(v1, h1));
        *(float2*)&g_attn_l[i1] = make_float2(tf_lo(v2, h2), tf_lo(v3, h3));
    }
}

// ---------------------------------------------------------------------------

extern "C" void kernel_launch(void* const* d_in, const int* in_sizes, int n_in,
                              void* d_out, int out_size) {
    (void)in_sizes; (void)n_in; (void)out_size;
    const float* x     = (const float*)d_in[0];
    const float* w_qkv = (const float*)d_in[1];
    const float* b_qkv = (const float*)d_in[2];
    const float* w_out = (const float*)d_in[3];
    const float* b_out = (const float*)d_in[4];
    float* out = (float*)d_out;

    float *xh, *xl, *wqh, *woh, *ath, *atl;
    cudaGetSymbolAddress((void**)&xh, g_xh);
    cudaGetSymbolAddress((void**)&xl, g_xl);
    cudaGetSymbolAddress((void**)&wqh, g_wqh);
    cudaGetSymbolAddress((void**)&woh, g_woh);
    cudaGetSymbolAddress((void**)&ath, g_attn_h);
    cudaGetSymbolAddress((void**)&atl, g_attn_l);

    // Decompose inputs (A-side hi/lo; B-side hi only)
    dec_kernel<<<(BB*SS*DIN/4 + 255) / 256, 256>>>(x, xh, xl, BB*SS*DIN/4);
    dec_hi_kernel<<<(DIN*3*DM/4 + 255) / 256, 256>>>(w_qkv, wqh, DIN*3*DM/4);
    dec_hi_kernel<<<(DM*DM/4 + 255) / 256, 256>>>(w_out, woh, DM*DM/4);

    // QKV GEMM (scatter to per-head q/k/v)
    {
        cudaFuncSetAttribute(tf32_gemm3<3 * DM, DIN, true>,
                             cudaFuncAttributeMaxDynamicSharedMemorySize, GEMM3_SMEM_BYTES);
        dim3 grid(3 * DM / 128, BB * SS / 128);
        tf32_gemm3<3 * DM, DIN, true><<<grid, 256, GEMM3_SMEM_BYTES>>>(xh, xl, wqh, b_qkv, nullptr);
    }
    // Flash attention (2xTF32 mma), writes decomposed output
    {
        cudaFuncSetAttribute(attn_kernel3, cudaFuncAttributeMaxDynamicSharedMemorySize, ATTN_SMEM_BYTES);
        dim3 grid(SS / 128, BH);
        attn_kernel3<<<grid, 256, ATTN_SMEM_BYTES>>>();
    }
    // Output GEMM
    {
        cudaFuncSetAttribute(tf32_gemm3<DM, DM, false>,
                             cudaFuncAttributeMaxDynamicSharedMemorySize, GEMM3_SMEM_BYTES);
        dim3 grid(DM / 128, BB * SS / 128);
        tf32_gemm3<DM, DM, false><<<grid, 256, GEMM3_SMEM_BYTES>>>(ath, atl, woh, b_out, out);
    }
}

// round 7
// speedup vs baseline: 1.9794x; 1.1190x over previous
#include <cuda_runtime.h>
#include <cuda_bf16.h>
#include <cstdint>

#define BB 2
#define SS 2048
#define DIN 1024
#define DM 1024
#define HH 16
#define HD 64
#define BH (BB*HH)

// ---------------------------------------------------------------------------
// Scratch (__device__ globals; no allocation allowed)
// ---------------------------------------------------------------------------
__device__ float g_q[BH*SS*HD];
__device__ float g_k[BH*SS*HD];
__device__ float g_v[BH*SS*HD];
__device__ uint32_t g_xhp[BB*SS*DIN/2];
__device__ uint32_t g_xlp[BB*SS*DIN/2];
__device__ uint32_t g_wqhp[(DIN/2)*3*DM];
__device__ uint32_t g_wqlp[(DIN/2)*3*DM];
__device__ uint32_t g_wohp[(DM/2)*DM];
__device__ uint32_t g_wolp[(DM/2)*DM];
__device__ uint32_t g_athp[BB*SS*DM/2];
__device__ uint32_t g_atlp[BB*SS*DM/2];

// ---------------------------------------------------------------------------
// bf16 helpers
// ---------------------------------------------------------------------------
__device__ __forceinline__ uint32_t pk2(float a, float b) {
    __nv_bfloat162 v = __floats2bfloat162_rn(a, b);
    return *reinterpret_cast<uint32_t*>(&v);
}
__device__ __forceinline__ float bhi(float a) {
    return __bfloat162float(__float2bfloat16(a));
}

__device__ __forceinline__ void mma_bf16(float c[4],
                                         uint32_t a0, uint32_t a1, uint32_t a2, uint32_t a3,
                                         uint32_t b0, uint32_t b1) {
    asm volatile(
        "mma.sync.aligned.m16n8k16.row.col.f32.bf16.bf16.f32 "
        "{%0,%1,%2,%3}, {%4,%5,%6,%7}, {%8,%9}, {%0,%1,%2,%3};"
        : "+f"(c[0]), "+f"(c[1]), "+f"(c[2]), "+f"(c[3])
        : "r"(a0), "r"(a1), "r"(a2), "r"(a3), "r"(b0), "r"(b1));
}

__device__ __forceinline__ void cp16(uint32_t dst, const void* src) {
    asm volatile("cp.async.ca.shared.global [%0], [%1], 16;" :: "r"(dst), "l"(src));
}
__device__ __forceinline__ void cp_commit() { asm volatile("cp.async.commit_group;"); }
template <int n>
__device__ __forceinline__ void cp_wait() { asm volatile("cp.async.wait_group %0;" :: "n"(n)); }

// ---------------------------------------------------------------------------
// Decompose/pack kernels
// ---------------------------------------------------------------------------
// A-side (k-contiguous): pack pairs of consecutive elems into bf16x2 hi/lo words
__global__ void dec_a_kernel(const float* __restrict__ src, uint32_t* __restrict__ hp,
                             uint32_t* __restrict__ lp, int n8) {
    int i = blockIdx.x * blockDim.x + threadIdx.x;
    if (i >= n8) return;
    const float4* s4 = (const float4*)src;
    float4 v0 = s4[2 * i], v1 = s4[2 * i + 1];
    uint4 h, l;
    float h0, h1;
    h0 = bhi(v0.x); h1 = bhi(v0.y); h.x = pk2(h0, h1); l.x = pk2(v0.x - h0, v0.y - h1);
    h0 = bhi(v0.z); h1 = bhi(v0.w); h.y = pk2(h0, h1); l.y = pk2(v0.z - h0, v0.w - h1);
    h0 = bhi(v1.x); h1 = bhi(v1.y); h.z = pk2(h0, h1); l.z = pk2(v1.x - h0, v1.y - h1);
    h0 = bhi(v1.z); h1 = bhi(v1.w); h.w = pk2(h0, h1); l.w = pk2(v1.z - h0, v1.w - h1);
    ((uint4*)hp)[i] = h;
    ((uint4*)lp)[i] = l;
}
// B-side (W[K][N], n-contiguous): word packs (W[2r][n], W[2r+1][n]) -> [K/2][N]
template <int N>
__global__ void dec_w_kernel(const float* __restrict__ src, uint32_t* __restrict__ hp,
                             uint32_t* __restrict__ lp, int total) {
    int i = blockIdx.x * blockDim.x + threadIdx.x;
    if (i >= total) return;
    int r = i / (N / 4);
    int c = (i % (N / 4)) * 4;
    float4 a = *(const float4*)(src + (size_t)(2 * r) * N + c);
    float4 b = *(const float4*)(src + (size_t)(2 * r + 1) * N + c);
    uint4 h, l;
    float ha, hb;
    ha = bhi(a.x); hb = bhi(b.x); h.x = pk2(ha, hb); l.x = pk2(a.x - ha, b.x - hb);
    ha = bhi(a.y); hb = bhi(b.y); h.y = pk2(ha, hb); l.y = pk2(a.y - ha, b.y - hb);
    ha = bhi(a.z); hb = bhi(b.z); h.z = pk2(ha, hb); l.z = pk2(a.z - ha, b.z - hb);
    ha = bhi(a.w); hb = bhi(b.w); h.w = pk2(ha, hb); l.w = pk2(a.w - ha, b.w - hb);
    *(uint4*)(hp + (size_t)r * N + c) = h;
    *(uint4*)(lp + (size_t)r * N + c) = l;
}

// ---------------------------------------------------------------------------
// 3-term bf16 GEMM. Block 128x128, k-tile 32 elems (16 words). 8 warps 2mx4n,
// warp tile 64x32. 3-stage cp.async pipeline, one barrier per k-tile.
// smem/stage (words): Ah[128][20] Al[128][20] Bh[16][132] Bl[16][132]
// ---------------------------------------------------------------------------
#define KTW 16
#define GA_PAD 20
#define GB_PAD 132
#define GA_SZ (128 * GA_PAD)   // 2560 words
#define GB_SZ (16 * GB_PAD)    // 2112 words
#define GSTG (2 * GA_SZ + 2 * GB_SZ)  // 9344 words
#define NSTAGE 3
#define GEMM_SMEM_BYTES (NSTAGE * GSTG * 4)  // 112128

template <int N, int K, bool SCATTER>
__global__ void __launch_bounds__(256, 2) bf16_gemm(const uint32_t* __restrict__ Ahp,
                                                    const uint32_t* __restrict__ Alp,
                                                    const uint32_t* __restrict__ Whp,
                                                    const uint32_t* __restrict__ Wlp,
                                                    const float* __restrict__ bias,
                                                    float* __restrict__ out) {
    extern __shared__ uint32_t smw[];
    const int KW = K / 2;
    const int tid = threadIdx.x;
    const int lane = tid & 31;
    const int warp = tid >> 5;
    const int wm = warp & 1;
    const int wn = warp >> 1;
    const int g = lane >> 2;
    const int t = lane & 3;
    const int mBase = blockIdx.y * 128;
    const int nBase = blockIdx.x * 128;

    const int aRow = tid >> 1;        // 0..127
    const int aw = (tid & 1) * 8;     // 0 or 8
    const int bRow = tid >> 4;        // 0..15
    const int bn = (tid & 15) * 8;    // 0..120

    auto loadStage = [&](int buf, int ktw) {
        uint32_t* s = smw + buf * GSTG;
        uint32_t sAh = (uint32_t)__cvta_generic_to_shared(s);
        uint32_t sAl = (uint32_t)__cvta_generic_to_shared(s + GA_SZ);
        uint32_t sBh = (uint32_t)__cvta_generic_to_shared(s + 2 * GA_SZ);
        uint32_t sBl = (uint32_t)__cvta_generic_to_shared(s + 2 * GA_SZ + GB_SZ);
        const uint32_t* gah = Ahp + (size_t)(mBase + aRow) * KW + ktw + aw;
        const uint32_t* gal = Alp + (size_t)(mBase + aRow) * KW + ktw + aw;
        uint32_t sa = (aRow * GA_PAD + aw) * 4;
        cp16(sAh + sa, gah);
        cp16(sAh + sa + 16, gah + 4);
        cp16(sAl + sa, gal);
        cp16(sAl + sa + 16, gal + 4);
        const uint32_t* gbh = Whp + (size_t)(ktw + bRow) * N + nBase + bn;
        const uint32_t* gbl = Wlp + (size_t)(ktw + bRow) * N + nBase + bn;
        uint32_t sb = (bRow * GB_PAD + bn) * 4;
        cp16(sBh + sb, gbh);
        cp16(sBh + sb + 16, gbh + 4);
        cp16(sBl + sb, gbl);
        cp16(sBl + sb + 16, gbl + 4);
    };

    float c[4][4][4];
#pragma unroll
    for (int mi = 0; mi < 4; mi++)
#pragma unroll
        for (int ni = 0; ni < 4; ni++)
#pragma unroll
            for (int r = 0; r < 4; r++) c[mi][ni][r] = 0.f;

    const int KT = K / 32;
    loadStage(0, 0);
    cp_commit();
    loadStage(1, KTW);
    cp_commit();

    for (int kt = 0; kt < KT; kt++) {
        if (kt < KT - 1) cp_wait<1>();
        else cp_wait<0>();
        __syncthreads();
        if (kt + 2 < KT) {
            loadStage((kt + 2) % NSTAGE, (kt + 2) * KTW);
            cp_commit();
        }

        const uint32_t* s = smw + (kt % NSTAGE) * GSTG;
        const uint32_t* sAH = s;
        const uint32_t* sAL = s + GA_SZ;
        const uint32_t* sBH = s + 2 * GA_SZ;
        const uint32_t* sBL = s + 2 * GA_SZ + GB_SZ;

#pragma unroll
        for (int ks = 0; ks < 2; ks++) {
            const int kw0 = ks * 8;
            uint32_t ah[4][4], al[4][4];
#pragma unroll
            for (int mi = 0; mi < 4; mi++) {
                int m0 = wm * 64 + mi * 16;
                int i0 = (m0 + g) * GA_PAD + kw0 + t;
                int i1 = (m0 + g + 8) * GA_PAD + kw0 + t;
                ah[mi][0] = sAH[i0];
                ah[mi][1] = sAH[i1];
                ah[mi][2] = sAH[i0 + 4];
                ah[mi][3] = sAH[i1 + 4];
                al[mi][0] = sAL[i0];
                al[mi][1] = sAL[i1];
                al[mi][2] = sAL[i0 + 4];
                al[mi][3] = sAL[i1 + 4];
            }
            uint32_t bh[4][2], bl[4][2];
#pragma unroll
            for (int ni = 0; ni < 4; ni++) {
                int n0 = wn * 32 + ni * 8;
                int j0 = (kw0 + t) * GB_PAD + n0 + g;
                int j1 = (kw0 + t + 4) * GB_PAD + n0 + g;
                bh[ni][0] = sBH[j0];
                bh[ni][1] = sBH[j1];
                bl[ni][0] = sBL[j0];
                bl[ni][1] = sBL[j1];
            }
#pragma unroll
            for (int mi = 0; mi < 4; mi++)
#pragma unroll
                for (int ni = 0; ni < 4; ni++) {
                    mma_bf16(c[mi][ni], ah[mi][0], ah[mi][1], ah[mi][2], ah[mi][3],
                             bl[ni][0], bl[ni][1]);
                    mma_bf16(c[mi][ni], al[mi][0], al[mi][1], al[mi][2], al[mi][3],
                             bh[ni][0], bh[ni][1]);
                    mma_bf16(c[mi][ni], ah[mi][0], ah[mi][1], ah[mi][2], ah[mi][3],
                             bh[ni][0], bh[ni][1]);
                }
        }
        __syncthreads();
    }

    // Epilogue
#pragma unroll
    for (int mi = 0; mi < 4; mi++) {
#pragma unroll
        for (int ni = 0; ni < 4; ni++) {
#pragma unroll
            for (int half = 0; half < 2; half++) {
                int m = mBase + wm * 64 + mi * 16 + g + half * 8;
                int n = nBase + wn * 32 + ni * 8 + t * 2;
                float v0 = c[mi][ni][half * 2 + 0] + bias[n];
                float v1 = c[mi][ni][half * 2 + 1] + bias[n + 1];
                if (SCATTER) {
                    int b = m >> 11;
                    int s2 = m & (SS - 1);
                    int h = n / 192;
                    int rem = n - h * 192;
                    int ty2 = rem >> 6;
                    int d = rem & 63;
                    int idx = ((b * HH + h) * SS + s2) * HD + d;
                    float* dst = (ty2 == 0) ? g_q : (ty2 == 1) ? g_k : g_v;
                    dst[idx] = v0;
                    dst[idx + 1] = v1;
                } else {
                    *(float2*)(out + (size_t)m * N + n) = make_float2(v0, v1);
                }
            }
        }
    }
}

// ---------------------------------------------------------------------------
// 3-term bf16 flash attention. Q tile 128, KV tile 64, 8 warps x 16 rows.
// cp.async staging for next K/V tile; packed bf16x2 words throughout.
// smem (words): Qh/Ql [128][36] | Ph/Pl [128][36] | Kh/Kl [32][68] (d-word major)
//               Vh/Vl [32][68] (kv-word major) | staging Ks,Vs fp32 [64][68]
// ---------------------------------------------------------------------------
#define AQP 36
#define AKP 68
#define AQSZ (128 * AQP)   // 4608 words
#define AKSZ (32 * AKP)    // 2176 words
#define ASTGF (64 * AKP)   // 4352 floats
#define ATTN_SMEM_WORDS (4 * AQSZ + 4 * AKSZ + 2 * ASTGF)
#define ATTN_SMEM_BYTES (ATTN_SMEM_WORDS * 4)   // 143360

__global__ void __launch_bounds__(256, 1) attn_kernel4() {
    extern __shared__ uint32_t smw[];
    uint32_t* sQh = smw;
    uint32_t* sQl = sQh + AQSZ;
    uint32_t* sPh = sQl + AQSZ;
    uint32_t* sPl = sPh + AQSZ;
    uint32_t* sKh = sPl + AQSZ;              // [d_word][kv]
    uint32_t* sKl = sKh + AKSZ;
    uint32_t* sVh = sKl + AKSZ;              // [kv_word][d]
    uint32_t* sVl = sVh + AKSZ;
    float* sKs = (float*)(sVl + AKSZ);       // staging raw fp32 [kv][d]
    float* sVs = sKs + ASTGF;

    const int tid = threadIdx.x;
    const int lane = tid & 31;
    const int warp = tid >> 5;
    const int g = lane >> 2;
    const int t = lane & 3;
    const int qt = (gridDim.x - 1) - blockIdx.x;  // heavy tiles first
    const int bh = blockIdx.y;
    const int b = bh >> 4, h = bh & 15;
    const int qBase = qt * 128;
    const int m0 = warp * 16;

    const float* Qg = g_q + (size_t)(bh * SS + qBase) * HD;
    const float* Kg = g_k + (size_t)bh * SS * HD;
    const float* Vg = g_v + (size_t)bh * SS * HD;

    const int lr = tid >> 4;          // 0..15
    const int d4 = (tid & 15) * 4;

    // Load Q: scale, decompose, pack [row][d_word]
#pragma unroll
    for (int p = 0; p < 8; p++) {
        int row = lr + p * 16;
        float4 v = *(const float4*)(Qg + row * HD + d4);
        v.x *= 0.125f; v.y *= 0.125f; v.z *= 0.125f; v.w *= 0.125f;
        float h0 = bhi(v.x), h1 = bhi(v.y), h2 = bhi(v.z), h3 = bhi(v.w);
        sQh[row * AQP + (d4 >> 1)] = pk2(h0, h1);
        sQh[row * AQP + (d4 >> 1) + 1] = pk2(h2, h3);
        sQl[row * AQP + (d4 >> 1)] = pk2(v.x - h0, v.y - h1);
        sQl[row * AQP + (d4 >> 1) + 1] = pk2(v.z - h2, v.w - h3);
    }

    uint32_t sKs_u = (uint32_t)__cvta_generic_to_shared(sKs);
    uint32_t sVs_u = (uint32_t)__cvta_generic_to_shared(sVs);
    auto prefetch = [&](int kvB) {
        const float* Kt = Kg + (size_t)kvB * HD;
        const float* Vt = Vg + (size_t)kvB * HD;
#pragma unroll
        for (int p = 0; p < 4; p++) {
            int row = lr + p * 16;
            uint32_t soff = (row * AKP + d4) * 4;
            cp16(sKs_u + soff, Kt + row * HD + d4);
            cp16(sVs_u + soff, Vt + row * HD + d4);
        }
    };

    float m_[2] = {-1e30f, -1e30f};
    float l_[2] = {0.f, 0.f};
    float co[8][4];
#pragma unroll
    for (int ni = 0; ni < 8; ni++)
#pragma unroll
        for (int r = 0; r < 4; r++) co[ni][r] = 0.f;

    const int jmax = 2 * qt + 1;
    prefetch(0);
    cp_commit();

    // V decompose thread mapping
    const int vrr = tid >> 3;          // 0..31 (kv word)
    const int vd8 = (tid & 7) * 8;     // 0..56

    for (int j = 0; j <= jmax; j++) {
        const int kvBase = j * 64;
        cp_wait<0>();
        __syncthreads();  // staging ready; prior compute done

        // K: [kv][d] -> packed [d_word][kv] (hi/lo)
#pragma unroll
        for (int p = 0; p < 4; p++) {
            int row = lr + p * 16;
            float4 kv = *(float4*)&sKs[row * AKP + d4];
            float h0 = bhi(kv.x), h1 = bhi(kv.y), h2 = bhi(kv.z), h3 = bhi(kv.w);
            sKh[(d4 >> 1) * AKP + row] = pk2(h0, h1);
            sKh[((d4 >> 1) + 1) * AKP + row] = pk2(h2, h3);
            sKl[(d4 >> 1) * AKP + row] = pk2(kv.x - h0, kv.y - h1);
            sKl[((d4 >> 1) + 1) * AKP + row] = pk2(kv.z - h2, kv.w - h3);
        }
        // V: [kv][d] -> packed [kv_word][d] (hi/lo)
        {
            float4 r0a = *(float4*)&sVs[(2 * vrr) * AKP + vd8];
            float4 r0b = *(float4*)&sVs[(2 * vrr) * AKP + vd8 + 4];
            float4 r1a = *(float4*)&sVs[(2 * vrr + 1) * AKP + vd8];
            float4 r1b = *(float4*)&sVs[(2 * vrr + 1) * AKP + vd8 + 4];
            float av[8] = {r0a.x, r0a.y, r0a.z, r0a.w, r0b.x, r0b.y, r0b.z, r0b.w};
            float bv[8] = {r1a.x, r1a.y, r1a.z, r1a.w, r1b.x, r1b.y, r1b.z, r1b.w};
#pragma unroll
            for (int i = 0; i < 8; i++) {
                float ha = bhi(av[i]), hb2 = bhi(bv[i]);
                sVh[vrr * AKP + vd8 + i] = pk2(ha, hb2);
                sVl[vrr * AKP + vd8 + i] = pk2(av[i] - ha, bv[i] - hb2);
            }
        }
        __syncthreads();  // packs visible; staging free

        if (j < jmax) prefetch(kvBase + 64);
        cp_commit();

        if (kvBase > qBase + m0 + 15) continue;  // warp tile fully masked

        // Scores S = Q K^T (3-term bf16)
        float sc[8][4];
#pragma unroll
        for (int ni = 0; ni < 8; ni++)
#pragma unroll
            for (int r = 0; r < 4; r++) sc[ni][r] = 0.f;
#pragma unroll
        for (int ks = 0; ks < 4; ks++) {
            const int kw0 = ks * 8;
            int i0 = (m0 + g) * AQP + kw0 + t;
            int i1 = (m0 + g + 8) * AQP + kw0 + t;
            uint32_t qh[4] = {sQh[i0], sQh[i1], sQh[i0 + 4], sQh[i1 + 4]};
            uint32_t ql[4] = {sQl[i0], sQl[i1], sQl[i0 + 4], sQl[i1 + 4]};
#pragma unroll
            for (int ni = 0; ni < 8; ni++) {
                int j0 = (kw0 + t) * AKP + ni * 8 + g;
                int j1 = (kw0 + t + 4) * AKP + ni * 8 + g;
                uint32_t kh0 = sKh[j0], kh1 = sKh[j1];
                uint32_t kl0 = sKl[j0], kl1 = sKl[j1];
                mma_bf16(sc[ni], qh[0], qh[1], qh[2], qh[3], kl0, kl1);
                mma_bf16(sc[ni], ql[0], ql[1], ql[2], ql[3], kh0, kh1);
                mma_bf16(sc[ni], qh[0], qh[1], qh[2], qh[3], kh0, kh1);
            }
        }

        // Causal mask (tiles overlapping the diagonal)
        if (kvBase + 63 > qBase + m0) {
#pragma unroll
            for (int ni = 0; ni < 8; ni++) {
#pragma unroll
                for (int r = 0; r < 4; r++) {
                    int row = qBase + m0 + g + ((r >= 2) ? 8 : 0);
                    int col = kvBase + ni * 8 + 2 * t + (r & 1);
                    if (col > row) sc[ni][r] = -1e30f;
                }
            }
        }

        // Warp-local online softmax (rows g and g+8)
        float mx0 = -1e30f, mx1 = -1e30f;
#pragma unroll
        for (int ni = 0; ni < 8; ni++) {
            mx0 = fmaxf(mx0, fmaxf(sc[ni][0], sc[ni][1]));
            mx1 = fmaxf(mx1, fmaxf(sc[ni][2], sc[ni][3]));
        }
#pragma unroll
        for (int o = 1; o <= 2; o <<= 1) {
            mx0 = fmaxf(mx0, __shfl_xor_sync(0xffffffffu, mx0, o));
            mx1 = fmaxf(mx1, __shfl_xor_sync(0xffffffffu, mx1, o));
        }
        float mn0 = fmaxf(m_[0], mx0), mn1 = fmaxf(m_[1], mx1);
        float a0 = __expf(m_[0] - mn0), a1 = __expf(m_[1] - mn1);
        float s0 = 0.f, s1 = 0.f;
#pragma unroll
        for (int ni = 0; ni < 8; ni++) {
            sc[ni][0] = __expf(sc[ni][0] - mn0);
            sc[ni][1] = __expf(sc[ni][1] - mn0);
            sc[ni][2] = __expf(sc[ni][2] - mn1);
            sc[ni][3] = __expf(sc[ni][3] - mn1);
            s0 += sc[ni][0] + sc[ni][1];
            s1 += sc[ni][2] + sc[ni][3];
        }
#pragma unroll
        for (int o = 1; o <= 2; o <<= 1) {
            s0 += __shfl_xor_sync(0xffffffffu, s0, o);
            s1 += __shfl_xor_sync(0xffffffffu, s1, o);
        }
        l_[0] = l_[0] * a0 + s0; m_[0] = mn0;
        l_[1] = l_[1] * a1 + s1; m_[1] = mn1;
#pragma unroll
        for (int ni = 0; ni < 8; ni++) {
            co[ni][0] *= a0; co[ni][1] *= a0;
            co[ni][2] *= a1; co[ni][3] *= a1;
        }

        // Pack P (hi/lo) — warp-exclusive rows; c-frag pair (2t,2t+1) = word ni*4+t
#pragma unroll
        for (int ni = 0; ni < 8; ni++) {
            int w0 = (m0 + g) * AQP + ni * 4 + t;
            int w1 = (m0 + g + 8) * AQP + ni * 4 + t;
            float h0 = bhi(sc[ni][0]), h1 = bhi(sc[ni][1]);
            float h2 = bhi(sc[ni][2]), h3 = bhi(sc[ni][3]);
            sPh[w0] = pk2(h0, h1);
            sPh[w1] = pk2(h2, h3);
            sPl[w0] = pk2(sc[ni][0] - h0, sc[ni][1] - h1);
            sPl[w1] = pk2(sc[ni][2] - h2, sc[ni][3] - h3);
        }
        __syncwarp();

        // O += P @ V (3-term bf16)
#pragma unroll
        for (int ks = 0; ks < 4; ks++) {
            const int kw0 = ks * 8;
            int i0 = (m0 + g) * AQP + kw0 + t;
            int i1 = (m0 + g + 8) * AQP + kw0 + t;
            uint32_t ph[4] = {sPh[i0], sPh[i1], sPh[i0 + 4], sPh[i1 + 4]};
            uint32_t pl[4] = {sPl[i0], sPl[i1], sPl[i0 + 4], sPl[i1 + 4]};
#pragma unroll
            for (int ni = 0; ni < 8; ni++) {
                int j0 = (kw0 + t) * AKP + ni * 8 + g;
                int j1 = (kw0 + t + 4) * AKP + ni * 8 + g;
                uint32_t vh0 = sVh[j0], vh1 = sVh[j1];
                uint32_t vl0 = sVl[j0], vl1 = sVl[j1];
                mma_bf16(co[ni], ph[0], ph[1], ph[2], ph[3], vl0, vl1);
                mma_bf16(co[ni], pl[0], pl[1], pl[2], pl[3], vh0, vh1);
                mma_bf16(co[ni], ph[0], ph[1], ph[2], ph[3], vh0, vh1);
            }
        }
    }

    // Epilogue: normalize, pack hi/lo words for out-proj A input
    float inv0 = 1.0f / l_[0];
    float inv1 = 1.0f / l_[1];
    int r0 = qBase + m0 + g;
    int r1 = r0 + 8;
#pragma unroll
    for (int ni = 0; ni < 8; ni++) {
        int w = h * (HD / 2) + ni * 4 + t;
        size_t i0 = (size_t)(b * SS + r0) * (DM / 2) + w;
        size_t i1 = (size_t)(b * SS + r1) * (DM / 2) + w;
        float v0 = co[ni][0] * inv0, v1 = co[ni][1] * inv0;
        float v2 = co[ni][2] * inv1, v3 = co[ni][3] * inv1;
        float h0 = bhi(v0), h1 = bhi(v1), h2 = bhi(v2), h3 = bhi(v3);
        g_athp[i0] = pk2(h0, h1);
        g_athp[i1] = pk2(h2, h3);
        g_atlp[i0] = pk2(v0 - h0, v1 - h1);
        g_atlp[i1] = pk2(v2 - h2, v3 - h3);
    }
}

// ---------------------------------------------------------------------------

extern "C" void kernel_launch(void* const* d_in, const int* in_sizes, int n_in,
                              void* d_out, int out_size) {
    (void)in_sizes; (void)n_in; (void)out_size;
    const float* x     = (const float*)d_in[0];
    const float* w_qkv = (const float*)d_in[1];
    const float* b_qkv = (const float*)d_in[2];
    const float* w_out = (const float*)d_in[3];
    const float* b_out = (const float*)d_in[4];
    float* out = (float*)d_out;

    uint32_t *xhp, *xlp, *wqhp, *wqlp, *wohp, *wolp, *athp, *atlp;
    cudaGetSymbolAddress((void**)&xhp, g_xhp);
    cudaGetSymbolAddress((void**)&xlp, g_xlp);
    cudaGetSymbolAddress((void**)&wqhp, g_wqhp);
    cudaGetSymbolAddress((void**)&wqlp, g_wqlp);
    cudaGetSymbolAddress((void**)&wohp, g_wohp);
    cudaGetSymbolAddress((void**)&wolp, g_wolp);
    cudaGetSymbolAddress((void**)&athp, g_athp);
    cudaGetSymbolAddress((void**)&atlp, g_atlp);

    // Decompose/pack inputs
    dec_a_kernel<<<(BB*SS*DIN/8 + 255) / 256, 256>>>(x, xhp, xlp, BB*SS*DIN/8);
    dec_w_kernel<3*DM><<<((DIN/2)*(3*DM/4) + 255) / 256, 256>>>(w_qkv, wqhp, wqlp, (DIN/2)*(3*DM/4));
    dec_w_kernel<DM><<<((DM/2)*(DM/4) + 255) / 256, 256>>>(w_out, wohp, wolp, (DM/2)*(DM/4));

    // QKV GEMM (scatter to per-head q/k/v)
    {
        cudaFuncSetAttribute(bf16_gemm<3 * DM, DIN, true>,
                             cudaFuncAttributeMaxDynamicSharedMemorySize, GEMM_SMEM_BYTES);
        dim3 grid(3 * DM / 128, BB * SS / 128);
        bf16_gemm<3 * DM, DIN, true><<<grid, 256, GEMM_SMEM_BYTES>>>(xhp, xlp, wqhp, wqlp, b_qkv, nullptr);
    }
    // Flash attention (3-term bf16 mma), writes packed output
    {
        cudaFuncSetAttribute(attn_kernel4, cudaFuncAttributeMaxDynamicSharedMemorySize, ATTN_SMEM_BYTES);
        dim3 grid(SS / 128, BH);
        attn_kernel4<<<grid, 256, ATTN_SMEM_BYTES>>>();
    }
    // Output GEMM
    {
        cudaFuncSetAttribute(bf16_gemm<DM, DM, false>,
                             cudaFuncAttributeMaxDynamicSharedMemorySize, GEMM_SMEM_BYTES);
        dim3 grid(DM / 128, BB * SS / 128);
        bf16_gemm<DM, DM, false><<<grid, 256, GEMM_SMEM_BYTES>>>(athp, atlp, wohp, wolp, b_out, out);
    }
}

// round 10
// speedup vs baseline: 2.2283x; 1.1258x over previous
#include <cuda_runtime.h>
#include <cuda_bf16.h>
#include <cstdint>

#define BB 2
#define SS 2048
#define DIN 1024
#define DM 1024
#define HH 16
#define HD 64
#define BH (BB*HH)

// ---------------------------------------------------------------------------
// Scratch (__device__ globals; no allocation allowed)
// ---------------------------------------------------------------------------
__device__ float g_q[BH*SS*HD];
__device__ float g_k[BH*SS*HD];
__device__ float g_v[BH*SS*HD];
__device__ uint32_t g_xhp[BB*SS*DIN/2];      // bf16 [M][K/2] hi words
__device__ uint32_t g_xlp[BB*SS*DIN/2];
__device__ uint32_t g_wqhp[3*DM*(DIN/2)];    // bf16 [N=3072][K/2] hi (transposed W)
__device__ uint32_t g_wqlp[3*DM*(DIN/2)];
__device__ uint32_t g_wohp[DM*(DM/2)];       // bf16 [N=1024][K/2]
__device__ uint32_t g_wolp[DM*(DM/2)];
__device__ uint32_t g_athp[BB*SS*DM/2];      // attn out bf16 [M][512] hi
__device__ uint32_t g_atlp[BB*SS*DM/2];

// ---------------------------------------------------------------------------
// bf16 helpers
// ---------------------------------------------------------------------------
__device__ __forceinline__ uint32_t pk2(float a, float b) {
    __nv_bfloat162 v = __floats2bfloat162_rn(a, b);
    return *reinterpret_cast<uint32_t*>(&v);
}
__device__ __forceinline__ float bhi(float a) {
    return __bfloat162float(__float2bfloat16(a));
}

__device__ __forceinline__ void mma_bf16(float c[4],
                                         uint32_t a0, uint32_t a1, uint32_t a2, uint32_t a3,
                                         uint32_t b0, uint32_t b1) {
    asm volatile(
        "mma.sync.aligned.m16n8k16.row.col.f32.bf16.bf16.f32 "
        "{%0,%1,%2,%3}, {%4,%5,%6,%7}, {%8,%9}, {%0,%1,%2,%3};"
        : "+f"(c[0]), "+f"(c[1]), "+f"(c[2]), "+f"(c[3])
        : "r"(a0), "r"(a1), "r"(a2), "r"(a3), "r"(b0), "r"(b1));
}

__device__ __forceinline__ void cp16(uint32_t dst, const void* src) {
    asm volatile("cp.async.ca.shared.global [%0], [%1], 16;" :: "r"(dst), "l"(src));
}
__device__ __forceinline__ void cp_commit() { asm volatile("cp.async.commit_group;"); }
template <int n>
__device__ __forceinline__ void cp_wait() { asm volatile("cp.async.wait_group %0;" :: "n"(n)); }

#define LDSM4(r, addr) \
    asm volatile("ldmatrix.sync.aligned.m8n8.x4.shared.b16 {%0,%1,%2,%3}, [%4];" \
                 : "=r"((r)[0]), "=r"((r)[1]), "=r"((r)[2]), "=r"((r)[3]) \
                 : "r"(addr))

// ---------------------------------------------------------------------------
// Decompose/pack kernels
// ---------------------------------------------------------------------------
__global__ void dec_a_kernel(const float* __restrict__ src, uint32_t* __restrict__ hp,
                             uint32_t* __restrict__ lp, int n8) {
    int i = blockIdx.x * blockDim.x + threadIdx.x;
    if (i >= n8) return;
    const float4* s4 = (const float4*)src;
    float4 v0 = s4[2 * i], v1 = s4[2 * i + 1];
    uint4 h, l;
    float h0, h1;
    h0 = bhi(v0.x); h1 = bhi(v0.y); h.x = pk2(h0, h1); l.x = pk2(v0.x - h0, v0.y - h1);
    h0 = bhi(v0.z); h1 = bhi(v0.w); h.y = pk2(h0, h1); l.y = pk2(v0.z - h0, v0.w - h1);
    h0 = bhi(v1.x); h1 = bhi(v1.y); h.z = pk2(h0, h1); l.z = pk2(v1.x - h0, v1.y - h1);
    h0 = bhi(v1.z); h1 = bhi(v1.w); h.w = pk2(h0, h1); l.w = pk2(v1.z - h0, v1.w - h1);
    ((uint4*)hp)[i] = h;
    ((uint4*)lp)[i] = l;
}
// Transpose-decompose: W[K][N] fp32 -> bf16 [N][K/2] hi/lo words
template <int N, int K>
__global__ void dec_wt_kernel(const float* __restrict__ src, uint32_t* __restrict__ hp,
                              uint32_t* __restrict__ lp) {
    int i = blockIdx.x * blockDim.x + threadIdx.x;
    if (i >= N * (K / 8)) return;
    int kc = i / N;       // 0..K/8-1
    int n = i % N;        // consecutive -> coalesced reads
    float v[8];
#pragma unroll
    for (int j = 0; j < 8; j++) v[j] = src[(size_t)(kc * 8 + j) * N + n];
    uint4 h, l;
    float h0, h1;
    h0 = bhi(v[0]); h1 = bhi(v[1]); h.x = pk2(h0, h1); l.x = pk2(v[0] - h0, v[1] - h1);
    h0 = bhi(v[2]); h1 = bhi(v[3]); h.y = pk2(h0, h1); l.y = pk2(v[2] - h0, v[3] - h1);
    h0 = bhi(v[4]); h1 = bhi(v[5]); h.z = pk2(h0, h1); l.z = pk2(v[4] - h0, v[5] - h1);
    h0 = bhi(v[6]); h1 = bhi(v[7]); h.w = pk2(h0, h1); l.w = pk2(v[6] - h0, v[7] - h1);
    size_t o = (size_t)n * (K / 2) + kc * 4;
    *(uint4*)(hp + o) = h;
    *(uint4*)(lp + o) = l;
}

// ---------------------------------------------------------------------------
// 3-term bf16 GEMM with ldmatrix fragment loads.
// CTA tile 128x128, k-tile 32 elems (16 words). 8 warps 2m x 4n, warp 64x32.
// A and B BOTH stored [row][k_word] pad-20 in smem (weights pre-transposed).
// 2-stage cp.async double buffer, 2 CTAs/SM.
// ---------------------------------------------------------------------------
#define GPAD 20
#define GTILE (128 * GPAD)       // 2560 words per operand array
#define GSTG2 (4 * GTILE)        // 10240 words per stage
#define GEMM_SMEM_BYTES (2 * GSTG2 * 4)   // 81920

template <int N, bool SCATTER>
__global__ void __launch_bounds__(256, 2) bf16_gemm_lm(const uint32_t* __restrict__ Ahp,
                                                       const uint32_t* __restrict__ Alp,
                                                       const uint32_t* __restrict__ Bhp,
                                                       const uint32_t* __restrict__ Blp,
                                                       const float* __restrict__ bias,
                                                       float* __restrict__ out) {
    constexpr int KW = 512;   // K=1024 -> 512 words
    constexpr int KT = 32;    // 32 k-tiles of 16 words
    extern __shared__ uint32_t smw[];
    const int tid = threadIdx.x;
    const int lane = tid & 31;
    const int warp = tid >> 5;
    const int wm = warp & 1;
    const int wn = warp >> 1;
    const int g = lane >> 2;
    const int t = lane & 3;
    const int mBase = blockIdx.y * 128;
    const int nBase = blockIdx.x * 128;

    const int fRow = tid >> 1;
    const int fh = (tid & 1) * 8;
    const uint32_t* gAh = Ahp + (size_t)(mBase + fRow) * KW + fh;
    const uint32_t* gAl = Alp + (size_t)(mBase + fRow) * KW + fh;
    const uint32_t* gBh = Bhp + (size_t)(nBase + fRow) * KW + fh;
    const uint32_t* gBl = Blp + (size_t)(nBase + fRow) * KW + fh;

    const uint32_t sBase = (uint32_t)__cvta_generic_to_shared(smw);
    const uint32_t fOff = (fRow * GPAD + fh) * 4;

    auto loadStage = [&](int s, int kt) {
        uint32_t b0 = sBase + s * (GSTG2 * 4);
        int kw = kt * 16;
        cp16(b0 + fOff, gAh + kw);
        cp16(b0 + fOff + 16, gAh + kw + 4);
        cp16(b0 + GTILE * 4 + fOff, gAl + kw);
        cp16(b0 + GTILE * 4 + fOff + 16, gAl + kw + 4);
        cp16(b0 + 2 * GTILE * 4 + fOff, gBh + kw);
        cp16(b0 + 2 * GTILE * 4 + fOff + 16, gBh + kw + 4);
        cp16(b0 + 3 * GTILE * 4 + fOff, gBl + kw);
        cp16(b0 + 3 * GTILE * 4 + fOff + 16, gBl + kw + 4);
    };

    // ldmatrix per-lane offsets (words)
    const int aOff = ((lane & 7) + ((lane >> 3) & 1) * 8) * GPAD + ((lane >> 4) & 1) * 4;
    const int bOff = ((lane & 7) + ((lane >> 4) & 1) * 8) * GPAD + ((lane >> 3) & 1) * 4;

    float c[4][4][4];
#pragma unroll
    for (int mi = 0; mi < 4; mi++)
#pragma unroll
        for (int ni = 0; ni < 4; ni++)
#pragma unroll
            for (int r = 0; r < 4; r++) c[mi][ni][r] = 0.f;

    loadStage(0, 0);
    cp_commit();

    for (int kt = 0; kt < KT; kt++) {
        if (kt + 1 < KT) {
            loadStage((kt + 1) & 1, kt + 1);   // target stage freed by last iter's end-sync
            cp_commit();
            cp_wait<1>();
        } else {
            cp_wait<0>();
        }
        __syncthreads();

        const uint32_t sb = sBase + (kt & 1) * (GSTG2 * 4);
        const uint32_t sAh_u = sb;
        const uint32_t sAl_u = sb + GTILE * 4;
        const uint32_t sBh_u = sb + 2 * GTILE * 4;
        const uint32_t sBl_u = sb + 3 * GTILE * 4;

#pragma unroll
        for (int ks = 0; ks < 2; ks++) {
            const int kw0 = ks * 8;
            uint32_t ah[4][4], al[4][4], bh[2][4], bl[2][4];
#pragma unroll
            for (int mi = 0; mi < 4; mi++) {
                uint32_t base = ((wm * 64 + mi * 16) * GPAD + aOff + kw0) * 4;
                LDSM4(ah[mi], sAh_u + base);
                LDSM4(al[mi], sAl_u + base);
            }
#pragma unroll
            for (int q = 0; q < 2; q++) {
                uint32_t base = ((wn * 32 + q * 16) * GPAD + bOff + kw0) * 4;
                LDSM4(bh[q], sBh_u + base);
                LDSM4(bl[q], sBl_u + base);
            }
#pragma unroll
            for (int mi = 0; mi < 4; mi++)
#pragma unroll
                for (int ni = 0; ni < 4; ni++) {
                    const int q = ni >> 1;
                    const int r = (ni & 1) * 2;
                    mma_bf16(c[mi][ni], ah[mi][0], ah[mi][1], ah[mi][2], ah[mi][3],
                             bl[q][r], bl[q][r + 1]);
                    mma_bf16(c[mi][ni], al[mi][0], al[mi][1], al[mi][2], al[mi][3],
                             bh[q][r], bh[q][r + 1]);
                    mma_bf16(c[mi][ni], ah[mi][0], ah[mi][1], ah[mi][2], ah[mi][3],
                             bh[q][r], bh[q][r + 1]);
                }
        }
        __syncthreads();
    }

    // Epilogue
#pragma unroll
    for (int mi = 0; mi < 4; mi++) {
#pragma unroll
        for (int ni = 0; ni < 4; ni++) {
#pragma unroll
            for (int half = 0; half < 2; half++) {
                int m = mBase + wm * 64 + mi * 16 + g + half * 8;
                int n = nBase + wn * 32 + ni * 8 + t * 2;
                float v0 = c[mi][ni][half * 2 + 0] + bias[n];
                float v1 = c[mi][ni][half * 2 + 1] + bias[n + 1];
                if (SCATTER) {
                    int b = m >> 11;
                    int s2 = m & (SS - 1);
                    int h = n / 192;
                    int rem = n - h * 192;
                    int ty2 = rem >> 6;
                    int d = rem & 63;
                    int idx = ((b * HH + h) * SS + s2) * HD + d;
                    float* dst = (ty2 == 0) ? g_q : (ty2 == 1) ? g_k : g_v;
                    dst[idx] = v0;
                    dst[idx + 1] = v1;
                } else {
                    *(float2*)(out + (size_t)m * N + n) = make_float2(v0, v1);
                }
            }
        }
    }
}

// ---------------------------------------------------------------------------
// 3-term bf16 flash attention (R7, unchanged — known-good).
// ---------------------------------------------------------------------------
#define AQP 36
#define AKP 68
#define AQSZ (128 * AQP)
#define AKSZ (32 * AKP)
#define ASTGF (64 * AKP)
#define ATTN_SMEM_WORDS (4 * AQSZ + 4 * AKSZ + 2 * ASTGF)
#define ATTN_SMEM_BYTES (ATTN_SMEM_WORDS * 4)   // 143360

__global__ void __launch_bounds__(256, 1) attn_kernel4() {
    extern __shared__ uint32_t smw[];
    uint32_t* sQh = smw;
    uint32_t* sQl = sQh + AQSZ;
    uint32_t* sPh = sQl + AQSZ;
    uint32_t* sPl = sPh + AQSZ;
    uint32_t* sKh = sPl + AQSZ;
    uint32_t* sKl = sKh + AKSZ;
    uint32_t* sVh = sKl + AKSZ;
    uint32_t* sVl = sVh + AKSZ;
    float* sKs = (float*)(sVl + AKSZ);
    float* sVs = sKs + ASTGF;

    const int tid = threadIdx.x;
    const int lane = tid & 31;
    const int warp = tid >> 5;
    const int g = lane >> 2;
    const int t = lane & 3;
    const int qt = (gridDim.x - 1) - blockIdx.x;
    const int bh = blockIdx.y;
    const int b = bh >> 4, h = bh & 15;
    const int qBase = qt * 128;
    const int m0 = warp * 16;

    const float* Qg = g_q + (size_t)(bh * SS + qBase) * HD;
    const float* Kg = g_k + (size_t)bh * SS * HD;
    const float* Vg = g_v + (size_t)bh * SS * HD;

    const int lr = tid >> 4;
    const int d4 = (tid & 15) * 4;

#pragma unroll
    for (int p = 0; p < 8; p++) {
        int row = lr + p * 16;
        float4 v = *(const float4*)(Qg + row * HD + d4);
        v.x *= 0.125f; v.y *= 0.125f; v.z *= 0.125f; v.w *= 0.125f;
        float h0 = bhi(v.x), h1 = bhi(v.y), h2 = bhi(v.z), h3 = bhi(v.w);
        sQh[row * AQP + (d4 >> 1)] = pk2(h0, h1);
        sQh[row * AQP + (d4 >> 1) + 1] = pk2(h2, h3);
        sQl[row * AQP + (d4 >> 1)] = pk2(v.x - h0, v.y - h1);
        sQl[row * AQP + (d4 >> 1) + 1] = pk2(v.z - h2, v.w - h3);
    }

    uint32_t sKs_u = (uint32_t)__cvta_generic_to_shared(sKs);
    uint32_t sVs_u = (uint32_t)__cvta_generic_to_shared(sVs);
    auto prefetch = [&](int kvB) {
        const float* Kt = Kg + (size_t)kvB * HD;
        const float* Vt = Vg + (size_t)kvB * HD;
#pragma unroll
        for (int p = 0; p < 4; p++) {
            int row = lr + p * 16;
            uint32_t soff = (row * AKP + d4) * 4;
            cp16(sKs_u + soff, Kt + row * HD + d4);
            cp16(sVs_u + soff, Vt + row * HD + d4);
        }
    };

    float m_[2] = {-1e30f, -1e30f};
    float l_[2] = {0.f, 0.f};
    float co[8][4];
#pragma unroll
    for (int ni = 0; ni < 8; ni++)
#pragma unroll
        for (int r = 0; r < 4; r++) co[ni][r] = 0.f;

    const int jmax = 2 * qt + 1;
    prefetch(0);
    cp_commit();

    const int vrr = tid >> 3;
    const int vd8 = (tid & 7) * 8;

    for (int j = 0; j <= jmax; j++) {
        const int kvBase = j * 64;
        cp_wait<0>();
        __syncthreads();

#pragma unroll
        for (int p = 0; p < 4; p++) {
            int row = lr + p * 16;
            float4 kv = *(float4*)&sKs[row * AKP + d4];
            float h0 = bhi(kv.x), h1 = bhi(kv.y), h2 = bhi(kv.z), h3 = bhi(kv.w);
            sKh[(d4 >> 1) * AKP + row] = pk2(h0, h1);
            sKh[((d4 >> 1) + 1) * AKP + row] = pk2(h2, h3);
            sKl[(d4 >> 1) * AKP + row] = pk2(kv.x - h0, kv.y - h1);
            sKl[((d4 >> 1) + 1) * AKP + row] = pk2(kv.z - h2, kv.w - h3);
        }
        {
            float4 r0a = *(float4*)&sVs[(2 * vrr) * AKP + vd8];
            float4 r0b = *(float4*)&sVs[(2 * vrr) * AKP + vd8 + 4];
            float4 r1a = *(float4*)&sVs[(2 * vrr + 1) * AKP + vd8];
            float4 r1b = *(float4*)&sVs[(2 * vrr + 1) * AKP + vd8 + 4];
            float av[8] = {r0a.x, r0a.y, r0a.z, r0a.w, r0b.x, r0b.y, r0b.z, r0b.w};
            float bv[8] = {r1a.x, r1a.y, r1a.z, r1a.w, r1b.x, r1b.y, r1b.z, r1b.w};
#pragma unroll
            for (int i = 0; i < 8; i++) {
                float ha = bhi(av[i]), hb2 = bhi(bv[i]);
                sVh[vrr * AKP + vd8 + i] = pk2(ha, hb2);
                sVl[vrr * AKP + vd8 + i] = pk2(av[i] - ha, bv[i] - hb2);
            }
        }
        __syncthreads();

        if (j < jmax) prefetch(kvBase + 64);
        cp_commit();

        if (kvBase > qBase + m0 + 15) continue;

        float sc[8][4];
#pragma unroll
        for (int ni = 0; ni < 8; ni++)
#pragma unroll
            for (int r = 0; r < 4; r++) sc[ni][r] = 0.f;
#pragma unroll
        for (int ks = 0; ks < 4; ks++) {
            const int kw0 = ks * 8;
            int i0 = (m0 + g) * AQP + kw0 + t;
            int i1 = (m0 + g + 8) * AQP + kw0 + t;
            uint32_t qh[4] = {sQh[i0], sQh[i1], sQh[i0 + 4], sQh[i1 + 4]};
            uint32_t ql[4] = {sQl[i0], sQl[i1], sQl[i0 + 4], sQl[i1 + 4]};
#pragma unroll
            for (int ni = 0; ni < 8; ni++) {
                int j0 = (kw0 + t) * AKP + ni * 8 + g;
                int j1 = (kw0 + t + 4) * AKP + ni * 8 + g;
                uint32_t kh0 = sKh[j0], kh1 = sKh[j1];
                uint32_t kl0 = sKl[j0], kl1 = sKl[j1];
                mma_bf16(sc[ni], qh[0], qh[1], qh[2], qh[3], kl0, kl1);
                mma_bf16(sc[ni], ql[0], ql[1], ql[2], ql[3], kh0, kh1);
                mma_bf16(sc[ni], qh[0], qh[1], qh[2], qh[3], kh0, kh1);
            }
        }

        if (kvBase + 63 > qBase + m0) {
#pragma unroll
            for (int ni = 0; ni < 8; ni++) {
#pragma unroll
                for (int r = 0; r < 4; r++) {
                    int row = qBase + m0 + g + ((r >= 2) ? 8 : 0);
                    int col = kvBase + ni * 8 + 2 * t + (r & 1);
                    if (col > row) sc[ni][r] = -1e30f;
                }
            }
        }

        float mx0 = -1e30f, mx1 = -1e30f;
#pragma unroll
        for (int ni = 0; ni < 8; ni++) {
            mx0 = fmaxf(mx0, fmaxf(sc[ni][0], sc[ni][1]));
            mx1 = fmaxf(mx1, fmaxf(sc[ni][2], sc[ni][3]));
        }
#pragma unroll
        for (int o = 1; o <= 2; o <<= 1) {
            mx0 = fmaxf(mx0, __shfl_xor_sync(0xffffffffu, mx0, o));
            mx1 = fmaxf(mx1, __shfl_xor_sync(0xffffffffu, mx1, o));
        }
        float mn0 = fmaxf(m_[0], mx0), mn1 = fmaxf(m_[1], mx1);
        float a0 = __expf(m_[0] - mn0), a1 = __expf(m_[1] - mn1);
        float s0 = 0.f, s1 = 0.f;
#pragma unroll
        for (int ni = 0; ni < 8; ni++) {
            sc[ni][0] = __expf(sc[ni][0] - mn0);
            sc[ni][1] = __expf(sc[ni][1] - mn0);
            sc[ni][2] = __expf(sc[ni][2] - mn1);
            sc[ni][3] = __expf(sc[ni][3] - mn1);
            s0 += sc[ni][0] + sc[ni][1];
            s1 += sc[ni][2] + sc[ni][3];
        }
#pragma unroll
        for (int o = 1; o <= 2; o <<= 1) {
            s0 += __shfl_xor_sync(0xffffffffu, s0, o);
            s1 += __shfl_xor_sync(0xffffffffu, s1, o);
        }
        l_[0] = l_[0] * a0 + s0; m_[0] = mn0;
        l_[1] = l_[1] * a1 + s1; m_[1] = mn1;
#pragma unroll
        for (int ni = 0; ni < 8; ni++) {
            co[ni][0] *= a0; co[ni][1] *= a0;
            co[ni][2] *= a1; co[ni][3] *= a1;
        }

#pragma unroll
        for (int ni = 0; ni < 8; ni++) {
            int w0 = (m0 + g) * AQP + ni * 4 + t;
            int w1 = (m0 + g + 8) * AQP + ni * 4 + t;
            float h0 = bhi(sc[ni][0]), h1 = bhi(sc[ni][1]);
            float h2 = bhi(sc[ni][2]), h3 = bhi(sc[ni][3]);
            sPh[w0] = pk2(h0, h1);
            sPh[w1] = pk2(h2, h3);
            sPl[w0] = pk2(sc[ni][0] - h0, sc[ni][1] - h1);
            sPl[w1] = pk2(sc[ni][2] - h2, sc[ni][3] - h3);
        }
        __syncwarp();

#pragma unroll
        for (int ks = 0; ks < 4; ks++) {
            const int kw0 = ks * 8;
            int i0 = (m0 + g) * AQP + kw0 + t;
            int i1 = (m0 + g + 8) * AQP + kw0 + t;
            uint32_t ph[4] = {sPh[i0], sPh[i1], sPh[i0 + 4], sPh[i1 + 4]};
            uint32_t pl[4] = {sPl[i0], sPl[i1], sPl[i0 + 4], sPl[i1 + 4]};
#pragma unroll
            for (int ni = 0; ni < 8; ni++) {
                int j0 = (kw0 + t) * AKP + ni * 8 + g;
                int j1 = (kw0 + t + 4) * AKP + ni * 8 + g;
                uint32_t vh0 = sVh[j0], vh1 = sVh[j1];
                uint32_t vl0 = sVl[j0], vl1 = sVl[j1];
                mma_bf16(co[ni], ph[0], ph[1], ph[2], ph[3], vl0, vl1);
                mma_bf16(co[ni], pl[0], pl[1], pl[2], pl[3], vh0, vh1);
                mma_bf16(co[ni], ph[0], ph[1], ph[2], ph[3], vh0, vh1);
            }
        }
    }

    float inv0 = 1.0f / l_[0];
    float inv1 = 1.0f / l_[1];
    int r0 = qBase + m0 + g;
    int r1 = r0 + 8;
#pragma unroll
    for (int ni = 0; ni < 8; ni++) {
        int w = h * (HD / 2) + ni * 4 + t;
        size_t i0 = (size_t)(b * SS + r0) * (DM / 2) + w;
        size_t i1 = (size_t)(b * SS + r1) * (DM / 2) + w;
        float v0 = co[ni][0] * inv0, v1 = co[ni][1] * inv0;
        float v2 = co[ni][2] * inv1, v3 = co[ni][3] * inv1;
        float h0 = bhi(v0), h1 = bhi(v1), h2 = bhi(v2), h3 = bhi(v3);
        g_athp[i0] = pk2(h0, h1);
        g_athp[i1] = pk2(h2, h3);
        g_atlp[i0] = pk2(v0 - h0, v1 - h1);
        g_atlp[i1] = pk2(v2 - h2, v3 - h3);
    }
}

// ---------------------------------------------------------------------------

extern "C" void kernel_launch(void* const* d_in, const int* in_sizes, int n_in,
                              void* d_out, int out_size) {
    (void)in_sizes; (void)n_in; (void)out_size;
    const float* x     = (const float*)d_in[0];
    const float* w_qkv = (const float*)d_in[1];
    const float* b_qkv = (const float*)d_in[2];
    const float* w_out = (const float*)d_in[3];
    const float* b_out = (const float*)d_in[4];
    float* out = (float*)d_out;

    uint32_t *xhp, *xlp, *wqhp, *wqlp, *wohp, *wolp, *athp, *atlp;
    cudaGetSymbolAddress((void**)&xhp, g_xhp);
    cudaGetSymbolAddress((void**)&xlp, g_xlp);
    cudaGetSymbolAddress((void**)&wqhp, g_wqhp);
    cudaGetSymbolAddress((void**)&wqlp, g_wqlp);
    cudaGetSymbolAddress((void**)&wohp, g_wohp);
    cudaGetSymbolAddress((void**)&wolp, g_wolp);
    cudaGetSymbolAddress((void**)&athp, g_athp);
    cudaGetSymbolAddress((void**)&atlp, g_atlp);

    // Decompose/pack: x -> [M][K/2]; weights transposed -> [N][K/2]
    dec_a_kernel<<<(BB*SS*DIN/8 + 255) / 256, 256>>>(x, xhp, xlp, BB*SS*DIN/8);
    dec_wt_kernel<3*DM, DIN><<<(3*DM*(DIN/8) + 255) / 256, 256>>>(w_qkv, wqhp, wqlp);
    dec_wt_kernel<DM, DM><<<(DM*(DM/8) + 255) / 256, 256>>>(w_out, wohp, wolp);

    // QKV GEMM (scatter to per-head q/k/v)
    {
        cudaFuncSetAttribute(bf16_gemm_lm<3 * DM, true>,
                             cudaFuncAttributeMaxDynamicSharedMemorySize, GEMM_SMEM_BYTES);
        dim3 grid(3 * DM / 128, BB * SS / 128);
        bf16_gemm_lm<3 * DM, true><<<grid, 256, GEMM_SMEM_BYTES>>>(xhp, xlp, wqhp, wqlp, b_qkv, nullptr);
    }
    // Flash attention (3-term bf16 mma.sync), writes packed output
    {
        cudaFuncSetAttribute(attn_kernel4, cudaFuncAttributeMaxDynamicSharedMemorySize, ATTN_SMEM_BYTES);
        dim3 grid(SS / 128, BH);
        attn_kernel4<<<grid, 256, ATTN_SMEM_BYTES>>>();
    }
    // Output GEMM
    {
        cudaFuncSetAttribute(bf16_gemm_lm<DM, false>,
                             cudaFuncAttributeMaxDynamicSharedMemorySize, GEMM_SMEM_BYTES);
        dim3 grid(DM / 128, BB * SS / 128);
        bf16_gemm_lm<DM, false><<<grid, 256, GEMM_SMEM_BYTES>>>(athp, atlp, wohp, wolp, b_out, out);
    }
}

// round 12
// speedup vs baseline: 3.2086x; 1.4399x over previous
#include <cuda_runtime.h>
#include <cuda_fp16.h>
#include <cstdint>

#define BB 2
#define SS 2048
#define DIN 1024
#define DM 1024
#define HH 16
#define HD 64
#define BH (BB*HH)

// ---------------------------------------------------------------------------
// Scratch (__device__ globals; no allocation allowed)
// ---------------------------------------------------------------------------
__device__ float g_q[BH*SS*HD];
__device__ float g_k[BH*SS*HD];
__device__ float g_v[BH*SS*HD];
__device__ uint32_t g_xhp[BB*SS*DIN/2];      // fp16 [M][K/2] hi words
__device__ uint32_t g_xlp[BB*SS*DIN/2];      // fp16 lo
__device__ uint32_t g_wqhp[3*DM*(DIN/2)];    // fp16 [N=3072][K/2] hi (transposed W)
__device__ uint32_t g_wohp[DM*(DM/2)];       // fp16 [N=1024][K/2] hi
__device__ uint32_t g_athp[BB*SS*DM/2];      // attn out fp16 hi
__device__ uint32_t g_atlp[BB*SS*DM/2];      // attn out fp16 lo

// ---------------------------------------------------------------------------
// fp16 helpers
// ---------------------------------------------------------------------------
__device__ __forceinline__ uint32_t pk2h(float a, float b) {
    __half2 v = __floats2half2_rn(a, b);
    return *reinterpret_cast<uint32_t*>(&v);
}
__device__ __forceinline__ float hhi(float a) {
    return __half2float(__float2half_rn(a));
}

__device__ __forceinline__ void mma_f16(float c[4],
                                        uint32_t a0, uint32_t a1, uint32_t a2, uint32_t a3,
                                        uint32_t b0, uint32_t b1) {
    asm volatile(
        "mma.sync.aligned.m16n8k16.row.col.f32.f16.f16.f32 "
        "{%0,%1,%2,%3}, {%4,%5,%6,%7}, {%8,%9}, {%0,%1,%2,%3};"
        : "+f"(c[0]), "+f"(c[1]), "+f"(c[2]), "+f"(c[3])
        : "r"(a0), "r"(a1), "r"(a2), "r"(a3), "r"(b0), "r"(b1));
}

__device__ __forceinline__ void cp16(uint32_t dst, const void* src) {
    asm volatile("cp.async.ca.shared.global [%0], [%1], 16;" :: "r"(dst), "l"(src));
}
__device__ __forceinline__ void cp_commit() { asm volatile("cp.async.commit_group;"); }
template <int n>
__device__ __forceinline__ void cp_wait() { asm volatile("cp.async.wait_group %0;" :: "n"(n)); }

#define LDSM4(r, addr) \
    asm volatile("ldmatrix.sync.aligned.m8n8.x4.shared.b16 {%0,%1,%2,%3}, [%4];" \
                 : "=r"((r)[0]), "=r"((r)[1]), "=r"((r)[2]), "=r"((r)[3]) \
                 : "r"(addr))

// ---------------------------------------------------------------------------
// Decompose/pack kernels
// ---------------------------------------------------------------------------
__global__ void dec_a_kernel(const float* __restrict__ src, uint32_t* __restrict__ hp,
                             uint32_t* __restrict__ lp, int n8) {
    int i = blockIdx.x * blockDim.x + threadIdx.x;
    if (i >= n8) return;
    const float4* s4 = (const float4*)src;
    float4 v0 = s4[2 * i], v1 = s4[2 * i + 1];
    uint4 h, l;
    float h0, h1;
    h0 = hhi(v0.x); h1 = hhi(v0.y); h.x = pk2h(h0, h1); l.x = pk2h(v0.x - h0, v0.y - h1);
    h0 = hhi(v0.z); h1 = hhi(v0.w); h.y = pk2h(h0, h1); l.y = pk2h(v0.z - h0, v0.w - h1);
    h0 = hhi(v1.x); h1 = hhi(v1.y); h.z = pk2h(h0, h1); l.z = pk2h(v1.x - h0, v1.y - h1);
    h0 = hhi(v1.z); h1 = hhi(v1.w); h.w = pk2h(h0, h1); l.w = pk2h(v1.z - h0, v1.w - h1);
    ((uint4*)hp)[i] = h;
    ((uint4*)lp)[i] = l;
}
// Transpose-decompose (hi only): W[K][N] fp32 -> fp16 [N][K/2] hi words
template <int N, int K>
__global__ void dec_wt_kernel(const float* __restrict__ src, uint32_t* __restrict__ hp) {
    int i = blockIdx.x * blockDim.x + threadIdx.x;
    if (i >= N * (K / 8)) return;
    int kc = i / N;
    int n = i % N;
    float v[8];
#pragma unroll
    for (int j = 0; j < 8; j++) v[j] = src[(size_t)(kc * 8 + j) * N + n];
    uint4 h;
    h.x = pk2h(hhi(v[0]), hhi(v[1]));
    h.y = pk2h(hhi(v[2]), hhi(v[3]));
    h.z = pk2h(hhi(v[4]), hhi(v[5]));
    h.w = pk2h(hhi(v[6]), hhi(v[7]));
    *(uint4*)(hp + (size_t)n * (K / 2) + kc * 4) = h;
}

// ---------------------------------------------------------------------------
// 2-term fp16 GEMM with ldmatrix. CTA 128x128, k-tile 32 elems (16 words).
// 8 warps 2m x 4n, warp 64x32. A hi/lo + B hi in [row][k_word] pad-20 smem.
// 2-stage cp.async, 2 CTAs/SM.
// ---------------------------------------------------------------------------
#define GPAD 20
#define GTILE (128 * GPAD)       // 2560 words per operand array
#define GSTG2 (3 * GTILE)        // 7680 words per stage
#define GEMM_SMEM_BYTES (2 * GSTG2 * 4)   // 61440

template <int N, bool SCATTER>
__global__ void __launch_bounds__(256, 2) f16_gemm_lm(const uint32_t* __restrict__ Ahp,
                                                      const uint32_t* __restrict__ Alp,
                                                      const uint32_t* __restrict__ Bhp,
                                                      const float* __restrict__ bias,
                                                      float* __restrict__ out) {
    constexpr int KW = 512;
    constexpr int KT = 32;
    extern __shared__ uint32_t smw[];
    const int tid = threadIdx.x;
    const int lane = tid & 31;
    const int warp = tid >> 5;
    const int wm = warp & 1;
    const int wn = warp >> 1;
    const int g = lane >> 2;
    const int t = lane & 3;
    const int mBase = blockIdx.y * 128;
    const int nBase = blockIdx.x * 128;

    const int fRow = tid >> 1;
    const int fh = (tid & 1) * 8;
    const uint32_t* gAh = Ahp + (size_t)(mBase + fRow) * KW + fh;
    const uint32_t* gAl = Alp + (size_t)(mBase + fRow) * KW + fh;
    const uint32_t* gBh = Bhp + (size_t)(nBase + fRow) * KW + fh;

    const uint32_t sBase = (uint32_t)__cvta_generic_to_shared(smw);
    const uint32_t fOff = (fRow * GPAD + fh) * 4;

    auto loadStage = [&](int s, int kt) {
        uint32_t b0 = sBase + s * (GSTG2 * 4);
        int kw = kt * 16;
        cp16(b0 + fOff, gAh + kw);
        cp16(b0 + fOff + 16, gAh + kw + 4);
        cp16(b0 + GTILE * 4 + fOff, gAl + kw);
        cp16(b0 + GTILE * 4 + fOff + 16, gAl + kw + 4);
        cp16(b0 + 2 * GTILE * 4 + fOff, gBh + kw);
        cp16(b0 + 2 * GTILE * 4 + fOff + 16, gBh + kw + 4);
    };

    const int aOff = ((lane & 7) + ((lane >> 3) & 1) * 8) * GPAD + ((lane >> 4) & 1) * 4;
    const int bOff = ((lane & 7) + ((lane >> 4) & 1) * 8) * GPAD + ((lane >> 3) & 1) * 4;

    float c[4][4][4];
#pragma unroll
    for (int mi = 0; mi < 4; mi++)
#pragma unroll
        for (int ni = 0; ni < 4; ni++)
#pragma unroll
            for (int r = 0; r < 4; r++) c[mi][ni][r] = 0.f;

    loadStage(0, 0);
    cp_commit();

    for (int kt = 0; kt < KT; kt++) {
        if (kt + 1 < KT) {
            loadStage((kt + 1) & 1, kt + 1);
            cp_commit();
            cp_wait<1>();
        } else {
            cp_wait<0>();
        }
        __syncthreads();

        const uint32_t sb = sBase + (kt & 1) * (GSTG2 * 4);
        const uint32_t sAh_u = sb;
        const uint32_t sAl_u = sb + GTILE * 4;
        const uint32_t sBh_u = sb + 2 * GTILE * 4;

#pragma unroll
        for (int ks = 0; ks < 2; ks++) {
            const int kw0 = ks * 8;
            uint32_t ah[4][4], al[4][4], bh[2][4];
#pragma unroll
            for (int mi = 0; mi < 4; mi++) {
                uint32_t base = ((wm * 64 + mi * 16) * GPAD + aOff + kw0) * 4;
                LDSM4(ah[mi], sAh_u + base);
                LDSM4(al[mi], sAl_u + base);
            }
#pragma unroll
            for (int q = 0; q < 2; q++) {
                uint32_t base = ((wn * 32 + q * 16) * GPAD + bOff + kw0) * 4;
                LDSM4(bh[q], sBh_u + base);
            }
#pragma unroll
            for (int mi = 0; mi < 4; mi++)
#pragma unroll
                for (int ni = 0; ni < 4; ni++) {
                    const int q = ni >> 1;
                    const int r = (ni & 1) * 2;
                    mma_f16(c[mi][ni], al[mi][0], al[mi][1], al[mi][2], al[mi][3],
                            bh[q][r], bh[q][r + 1]);
                    mma_f16(c[mi][ni], ah[mi][0], ah[mi][1], ah[mi][2], ah[mi][3],
                            bh[q][r], bh[q][r + 1]);
                }
        }
        __syncthreads();
    }

    // Epilogue
#pragma unroll
    for (int mi = 0; mi < 4; mi++) {
#pragma unroll
        for (int ni = 0; ni < 4; ni++) {
#pragma unroll
            for (int half = 0; half < 2; half++) {
                int m = mBase + wm * 64 + mi * 16 + g + half * 8;
                int n = nBase + wn * 32 + ni * 8 + t * 2;
                float v0 = c[mi][ni][half * 2 + 0] + bias[n];
                float v1 = c[mi][ni][half * 2 + 1] + bias[n + 1];
                if (SCATTER) {
                    int b = m >> 11;
                    int s2 = m & (SS - 1);
                    int h = n / 192;
                    int rem = n - h * 192;
                    int ty2 = rem >> 6;
                    int d = rem & 63;
                    int idx = ((b * HH + h) * SS + s2) * HD + d;
                    float* dst = (ty2 == 0) ? g_q : (ty2 == 1) ? g_k : g_v;
                    dst[idx] = v0;
                    dst[idx + 1] = v1;
                } else {
                    *(float2*)(out + (size_t)m * N + n) = make_float2(v0, v1);
                }
            }
        }
    }
}

// ---------------------------------------------------------------------------
// 2-term fp16 flash attention with ldmatrix.
// Q tile 128, KV tile 64, 8 warps x 16 exclusive rows.
// smem (words): Qh/Ql [128][36] | Ph/Pl [128][36] | Kh [64][36] (natural)
//               Vh [32][68] (kv_word x d) | staging Ks,Vs fp32 [64][68]
// ---------------------------------------------------------------------------
#define AQP 36
#define AKP 68
#define AQSZ (128 * AQP)     // 4608 words
#define AKHSZ (64 * AQP)     // 2304 words (K hi, [kv][36])
#define AVSZ (32 * AKP)      // 2176 words (V hi, [kv_word][d])
#define ASTGF (64 * AKP)     // 4352 floats
#define ATTN_SMEM_WORDS (4 * AQSZ + AKHSZ + AVSZ + 2 * ASTGF)
#define ATTN_SMEM_BYTES (ATTN_SMEM_WORDS * 4)   // 126464

__global__ void __launch_bounds__(256, 1) attn_kernel5() {
    extern __shared__ uint32_t smw[];
    uint32_t* sQh = smw;
    uint32_t* sQl = sQh + AQSZ;
    uint32_t* sPh = sQl + AQSZ;
    uint32_t* sPl = sPh + AQSZ;
    uint32_t* sKh = sPl + AQSZ;              // [kv][36]
    uint32_t* sVh = sKh + AKHSZ;             // [kv_word][d]
    float* sKs = (float*)(sVh + AVSZ);       // staging fp32 [kv][68]
    float* sVs = sKs + ASTGF;

    const int tid = threadIdx.x;
    const int lane = tid & 31;
    const int warp = tid >> 5;
    const int g = lane >> 2;
    const int t = lane & 3;
    const int qt = (gridDim.x - 1) - blockIdx.x;
    const int bh = blockIdx.y;
    const int b = bh >> 4, h = bh & 15;
    const int qBase = qt * 128;
    const int m0 = warp * 16;

    const float* Qg = g_q + (size_t)(bh * SS + qBase) * HD;
    const float* Kg = g_k + (size_t)bh * SS * HD;
    const float* Vg = g_v + (size_t)bh * SS * HD;

    const int lr = tid >> 4;
    const int d4 = (tid & 15) * 4;

    // ldmatrix per-lane offsets (words, pad AQP=36)
    const int aOff = ((lane & 7) + ((lane >> 3) & 1) * 8) * AQP + ((lane >> 4) & 1) * 4;
    const int bOff = ((lane & 7) + ((lane >> 4) & 1) * 8) * AQP + ((lane >> 3) & 1) * 4;
    const uint32_t sQh_u = (uint32_t)__cvta_generic_to_shared(sQh);
    const uint32_t sQl_u = (uint32_t)__cvta_generic_to_shared(sQl);
    const uint32_t sPh_u = (uint32_t)__cvta_generic_to_shared(sPh);
    const uint32_t sPl_u = (uint32_t)__cvta_generic_to_shared(sPl);
    const uint32_t sKh_u = (uint32_t)__cvta_generic_to_shared(sKh);

    // Load Q: scale, split hi/lo fp16, pack [row][d_word] pad 36
#pragma unroll
    for (int p = 0; p < 8; p++) {
        int row = lr + p * 16;
        float4 v = *(const float4*)(Qg + row * HD + d4);
        v.x *= 0.125f; v.y *= 0.125f; v.z *= 0.125f; v.w *= 0.125f;
        float h0 = hhi(v.x), h1 = hhi(v.y), h2 = hhi(v.z), h3 = hhi(v.w);
        sQh[row * AQP + (d4 >> 1)] = pk2h(h0, h1);
        sQh[row * AQP + (d4 >> 1) + 1] = pk2h(h2, h3);
        sQl[row * AQP + (d4 >> 1)] = pk2h(v.x - h0, v.y - h1);
        sQl[row * AQP + (d4 >> 1) + 1] = pk2h(v.z - h2, v.w - h3);
    }

    uint32_t sKs_u = (uint32_t)__cvta_generic_to_shared(sKs);
    uint32_t sVs_u = (uint32_t)__cvta_generic_to_shared(sVs);
    auto prefetch = [&](int kvB) {
        const float* Kt = Kg + (size_t)kvB * HD;
        const float* Vt = Vg + (size_t)kvB * HD;
#pragma unroll
        for (int p = 0; p < 4; p++) {
            int row = lr + p * 16;
            uint32_t soff = (row * AKP + d4) * 4;
            cp16(sKs_u + soff, Kt + row * HD + d4);
            cp16(sVs_u + soff, Vt + row * HD + d4);
        }
    };

    float m_[2] = {-1e30f, -1e30f};
    float l_[2] = {0.f, 0.f};
    float co[8][4];
#pragma unroll
    for (int ni = 0; ni < 8; ni++)
#pragma unroll
        for (int r = 0; r < 4; r++) co[ni][r] = 0.f;

    const int jmax = 2 * qt + 1;
    prefetch(0);
    cp_commit();

    const int vrr = tid >> 3;
    const int vd8 = (tid & 7) * 8;

    for (int j = 0; j <= jmax; j++) {
        const int kvBase = j * 64;
        cp_wait<0>();
        __syncthreads();

        // K hi: [kv][d] staging -> [kv][36] fp16-packed (no transpose)
#pragma unroll
        for (int p = 0; p < 4; p++) {
            int row = lr + p * 16;
            float4 kv = *(float4*)&sKs[row * AKP + d4];
            sKh[row * AQP + (d4 >> 1)] = pk2h(hhi(kv.x), hhi(kv.y));
            sKh[row * AQP + (d4 >> 1) + 1] = pk2h(hhi(kv.z), hhi(kv.w));
        }
        // V hi: [kv][d] staging -> [kv_word][d]
        {
            float4 r0a = *(float4*)&sVs[(2 * vrr) * AKP + vd8];
            float4 r0b = *(float4*)&sVs[(2 * vrr) * AKP + vd8 + 4];
            float4 r1a = *(float4*)&sVs[(2 * vrr + 1) * AKP + vd8];
            float4 r1b = *(float4*)&sVs[(2 * vrr + 1) * AKP + vd8 + 4];
            float av[8] = {r0a.x, r0a.y, r0a.z, r0a.w, r0b.x, r0b.y, r0b.z, r0b.w};
            float bv[8] = {r1a.x, r1a.y, r1a.z, r1a.w, r1b.x, r1b.y, r1b.z, r1b.w};
#pragma unroll
            for (int i = 0; i < 8; i++)
                sVh[vrr * AKP + vd8 + i] = pk2h(hhi(av[i]), hhi(bv[i]));
        }
        __syncthreads();

        if (j < jmax) prefetch(kvBase + 64);
        cp_commit();

        if (kvBase > qBase + m0 + 15) continue;

        // Scores S = Q K^T (2-term fp16, ldmatrix operands)
        float sc[8][4];
#pragma unroll
        for (int ni = 0; ni < 8; ni++)
#pragma unroll
            for (int r = 0; r < 4; r++) sc[ni][r] = 0.f;
#pragma unroll
        for (int ks = 0; ks < 4; ks++) {
            const int kw0 = ks * 8;
            uint32_t qh[4], ql[4], kb[4][4];
            uint32_t abase = (m0 * AQP + aOff + kw0) * 4;
            LDSM4(qh, sQh_u + abase);
            LDSM4(ql, sQl_u + abase);
#pragma unroll
            for (int q2 = 0; q2 < 4; q2++) {
                uint32_t bbase = ((q2 * 16) * AQP + bOff + kw0) * 4;
                LDSM4(kb[q2], sKh_u + bbase);
            }
#pragma unroll
            for (int ni = 0; ni < 8; ni++) {
                const int q2 = ni >> 1;
                const int r = (ni & 1) * 2;
                mma_f16(sc[ni], ql[0], ql[1], ql[2], ql[3], kb[q2][r], kb[q2][r + 1]);
                mma_f16(sc[ni], qh[0], qh[1], qh[2], qh[3], kb[q2][r], kb[q2][r + 1]);
            }
        }

        // Causal mask
        if (kvBase + 63 > qBase + m0) {
#pragma unroll
            for (int ni = 0; ni < 8; ni++) {
#pragma unroll
                for (int r = 0; r < 4; r++) {
                    int row = qBase + m0 + g + ((r >= 2) ? 8 : 0);
                    int col = kvBase + ni * 8 + 2 * t + (r & 1);
                    if (col > row) sc[ni][r] = -1e30f;
                }
            }
        }

        // Warp-local online softmax (rows g and g+8)
        float mx0 = -1e30f, mx1 = -1e30f;
#pragma unroll
        for (int ni = 0; ni < 8; ni++) {
            mx0 = fmaxf(mx0, fmaxf(sc[ni][0], sc[ni][1]));
            mx1 = fmaxf(mx1, fmaxf(sc[ni][2], sc[ni][3]));
        }
#pragma unroll
        for (int o = 1; o <= 2; o <<= 1) {
            mx0 = fmaxf(mx0, __shfl_xor_sync(0xffffffffu, mx0, o));
            mx1 = fmaxf(mx1, __shfl_xor_sync(0xffffffffu, mx1, o));
        }
        float mn0 = fmaxf(m_[0], mx0), mn1 = fmaxf(m_[1], mx1);
        float a0 = __expf(m_[0] - mn0), a1 = __expf(m_[1] - mn1);
        float s0 = 0.f, s1 = 0.f;
#pragma unroll
        for (int ni = 0; ni < 8; ni++) {
            sc[ni][0] = __expf(sc[ni][0] - mn0);
            sc[ni][1] = __expf(sc[ni][1] - mn0);
            sc[ni][2] = __expf(sc[ni][2] - mn1);
            sc[ni][3] = __expf(sc[ni][3] - mn1);
            s0 += sc[ni][0] + sc[ni][1];
            s1 += sc[ni][2] + sc[ni][3];
        }
#pragma unroll
        for (int o = 1; o <= 2; o <<= 1) {
            s0 += __shfl_xor_sync(0xffffffffu, s0, o);
            s1 += __shfl_xor_sync(0xffffffffu, s1, o);
        }
        l_[0] = l_[0] * a0 + s0; m_[0] = mn0;
        l_[1] = l_[1] * a1 + s1; m_[1] = mn1;
#pragma unroll
        for (int ni = 0; ni < 8; ni++) {
            co[ni][0] *= a0; co[ni][1] *= a0;
            co[ni][2] *= a1; co[ni][3] *= a1;
        }

        // Pack P (hi/lo fp16) — warp-exclusive rows, [row][kv_word]
#pragma unroll
        for (int ni = 0; ni < 8; ni++) {
            int w0 = (m0 + g) * AQP + ni * 4 + t;
            int w1 = (m0 + g + 8) * AQP + ni * 4 + t;
            float h0 = hhi(sc[ni][0]), h1 = hhi(sc[ni][1]);
            float h2 = hhi(sc[ni][2]), h3 = hhi(sc[ni][3]);
            sPh[w0] = pk2h(h0, h1);
            sPh[w1] = pk2h(h2, h3);
            sPl[w0] = pk2h(sc[ni][0] - h0, sc[ni][1] - h1);
            sPl[w1] = pk2h(sc[ni][2] - h2, sc[ni][3] - h3);
        }
        __syncwarp();

        // O += P @ V (2-term fp16; P via ldmatrix, V scalar B-frags)
#pragma unroll
        for (int ks = 0; ks < 4; ks++) {
            const int kw0 = ks * 8;
            uint32_t ph[4], pl[4];
            uint32_t abase = (m0 * AQP + aOff + kw0) * 4;
            LDSM4(ph, sPh_u + abase);
            LDSM4(pl, sPl_u + abase);
#pragma unroll
            for (int ni = 0; ni < 8; ni++) {
                int j0 = (kw0 + t) * AKP + ni * 8 + g;
                int j1 = (kw0 + t + 4) * AKP + ni * 8 + g;
                uint32_t vh0 = sVh[j0], vh1 = sVh[j1];
                mma_f16(co[ni], pl[0], pl[1], pl[2], pl[3], vh0, vh1);
                mma_f16(co[ni], ph[0], ph[1], ph[2], ph[3], vh0, vh1);
            }
        }
    }

    // Epilogue: normalize, pack hi/lo fp16 for out-proj A input
    float inv0 = 1.0f / l_[0];
    float inv1 = 1.0f / l_[1];
    int r0 = qBase + m0 + g;
    int r1 = r0 + 8;
#pragma unroll
    for (int ni = 0; ni < 8; ni++) {
        int w = h * (HD / 2) + ni * 4 + t;
        size_t i0 = (size_t)(b * SS + r0) * (DM / 2) + w;
        size_t i1 = (size_t)(b * SS + r1) * (DM / 2) + w;
        float v0 = co[ni][0] * inv0, v1 = co[ni][1] * inv0;
        float v2 = co[ni][2] * inv1, v3 = co[ni][3] * inv1;
        float h0 = hhi(v0), h1 = hhi(v1), h2 = hhi(v2), h3 = hhi(v3);
        g_athp[i0] = pk2h(h0, h1);
        g_athp[i1] = pk2h(h2, h3);
        g_atlp[i0] = pk2h(v0 - h0, v1 - h1);
        g_atlp[i1] = pk2h(v2 - h2, v3 - h3);
    }
}

// ---------------------------------------------------------------------------

extern "C" void kernel_launch(void* const* d_in, const int* in_sizes, int n_in,
                              void* d_out, int out_size) {
    (void)in_sizes; (void)n_in; (void)out_size;
    const float* x     = (const float*)d_in[0];
    const float* w_qkv = (const float*)d_in[1];
    const float* b_qkv = (const float*)d_in[2];
    const float* w_out = (const float*)d_in[3];
    const float* b_out = (const float*)d_in[4];
    float* out = (float*)d_out;

    uint32_t *xhp, *xlp, *wqhp, *wohp, *athp, *atlp;
    cudaGetSymbolAddress((void**)&xhp, g_xhp);
    cudaGetSymbolAddress((void**)&xlp, g_xlp);
    cudaGetSymbolAddress((void**)&wqhp, g_wqhp);
    cudaGetSymbolAddress((void**)&wohp, g_wohp);
    cudaGetSymbolAddress((void**)&athp, g_athp);
    cudaGetSymbolAddress((void**)&atlp, g_atlp);

    // Decompose/pack: x -> hi/lo [M][K/2]; weights transposed -> hi [N][K/2]
    dec_a_kernel<<<(BB*SS*DIN/8 + 255) / 256, 256>>>(x, xhp, xlp, BB*SS*DIN/8);
    dec_wt_kernel<3*DM, DIN><<<(3*DM*(DIN/8) + 255) / 256, 256>>>(w_qkv, wqhp);
    dec_wt_kernel<DM, DM><<<(DM*(DM/8) + 255) / 256, 256>>>(w_out, wohp);

    // QKV GEMM (scatter to per-head q/k/v)
    {
        cudaFuncSetAttribute(f16_gemm_lm<3 * DM, true>,
                             cudaFuncAttributeMaxDynamicSharedMemorySize, GEMM_SMEM_BYTES);
        dim3 grid(3 * DM / 128, BB * SS / 128);
        f16_gemm_lm<3 * DM, true><<<grid, 256, GEMM_SMEM_BYTES>>>(xhp, xlp, wqhp, b_qkv, nullptr);
    }
    // Flash attention (2-term fp16), writes packed hi/lo output
    {
        cudaFuncSetAttribute(attn_kernel5, cudaFuncAttributeMaxDynamicSharedMemorySize, ATTN_SMEM_BYTES);
        dim3 grid(SS / 128, BH);
        attn_kernel5<<<grid, 256, ATTN_SMEM_BYTES>>>();
    }
    // Output GEMM
    {
        cudaFuncSetAttribute(f16_gemm_lm<DM, false>,
                             cudaFuncAttributeMaxDynamicSharedMemorySize, GEMM_SMEM_BYTES);
        dim3 grid(DM / 128, BB * SS / 128);
        f16_gemm_lm<DM, false><<<grid, 256, GEMM_SMEM_BYTES>>>(athp, atlp, wohp, b_out, out);
    }
}

// round 13
// speedup vs baseline: 3.5094x; 1.0937x over previous
#include <cuda_runtime.h>
#include <cuda_fp16.h>
#include <cstdint>

#define BB 2
#define SS 2048
#define DIN 1024
#define DM 1024
#define HH 16
#define HD 64
#define BH (BB*HH)

// ---------------------------------------------------------------------------
// Scratch (__device__ globals; no allocation allowed)
// ---------------------------------------------------------------------------
__device__ uint32_t g_qhp[BH*SS*HD/2];       // Q fp16 hi, pre-scaled, [bh][s][d_word]
__device__ uint32_t g_qlp[BH*SS*HD/2];       // Q fp16 lo
__device__ uint32_t g_khp[BH*SS*HD/2];       // K fp16 hi
__device__ uint32_t g_vhp[BH*SS*HD/2];       // V fp16 hi
__device__ uint32_t g_xhp[BB*SS*DIN/2];      // x fp16 [M][K/2] hi words
__device__ uint32_t g_xlp[BB*SS*DIN/2];
__device__ uint32_t g_wqhp[3*DM*(DIN/2)];    // W_qkv^T fp16 [N][K/2] hi
__device__ uint32_t g_wohp[DM*(DM/2)];       // W_out^T fp16 [N][K/2] hi
__device__ uint32_t g_athp[BB*SS*DM/2];      // attn out fp16 hi
__device__ uint32_t g_atlp[BB*SS*DM/2];      // attn out fp16 lo

// ---------------------------------------------------------------------------
// fp16 helpers
// ---------------------------------------------------------------------------
__device__ __forceinline__ uint32_t pk2h(float a, float b) {
    __half2 v = __floats2half2_rn(a, b);
    return *reinterpret_cast<uint32_t*>(&v);
}
__device__ __forceinline__ float hhi(float a) {
    return __half2float(__float2half_rn(a));
}

__device__ __forceinline__ void mma_f16(float c[4],
                                        uint32_t a0, uint32_t a1, uint32_t a2, uint32_t a3,
                                        uint32_t b0, uint32_t b1) {
    asm volatile(
        "mma.sync.aligned.m16n8k16.row.col.f32.f16.f16.f32 "
        "{%0,%1,%2,%3}, {%4,%5,%6,%7}, {%8,%9}, {%0,%1,%2,%3};"
        : "+f"(c[0]), "+f"(c[1]), "+f"(c[2]), "+f"(c[3])
        : "r"(a0), "r"(a1), "r"(a2), "r"(a3), "r"(b0), "r"(b1));
}

__device__ __forceinline__ void cp16(uint32_t dst, const void* src) {
    asm volatile("cp.async.ca.shared.global [%0], [%1], 16;" :: "r"(dst), "l"(src));
}
__device__ __forceinline__ void cp_commit() { asm volatile("cp.async.commit_group;"); }
template <int n>
__device__ __forceinline__ void cp_wait() { asm volatile("cp.async.wait_group %0;" :: "n"(n)); }

#define LDSM4(r, addr) \
    asm volatile("ldmatrix.sync.aligned.m8n8.x4.shared.b16 {%0,%1,%2,%3}, [%4];" \
                 : "=r"((r)[0]), "=r"((r)[1]), "=r"((r)[2]), "=r"((r)[3]) \
                 : "r"(addr))
#define LDSM4T(r, addr) \
    asm volatile("ldmatrix.sync.aligned.m8n8.x4.trans.shared.b16 {%0,%1,%2,%3}, [%4];" \
                 : "=r"((r)[0]), "=r"((r)[1]), "=r"((r)[2]), "=r"((r)[3]) \
                 : "r"(addr))

// ---------------------------------------------------------------------------
// Decompose/pack kernels
// ---------------------------------------------------------------------------
__global__ void dec_a_kernel(const float* __restrict__ src, uint32_t* __restrict__ hp,
                             uint32_t* __restrict__ lp, int n8) {
    int i = blockIdx.x * blockDim.x + threadIdx.x;
    if (i >= n8) return;
    const float4* s4 = (const float4*)src;
    float4 v0 = s4[2 * i], v1 = s4[2 * i + 1];
    uint4 h, l;
    float h0, h1;
    h0 = hhi(v0.x); h1 = hhi(v0.y); h.x = pk2h(h0, h1); l.x = pk2h(v0.x - h0, v0.y - h1);
    h0 = hhi(v0.z); h1 = hhi(v0.w); h.y = pk2h(h0, h1); l.y = pk2h(v0.z - h0, v0.w - h1);
    h0 = hhi(v1.x); h1 = hhi(v1.y); h.z = pk2h(h0, h1); l.z = pk2h(v1.x - h0, v1.y - h1);
    h0 = hhi(v1.z); h1 = hhi(v1.w); h.w = pk2h(h0, h1); l.w = pk2h(v1.z - h0, v1.w - h1);
    ((uint4*)hp)[i] = h;
    ((uint4*)lp)[i] = l;
}
template <int N, int K>
__global__ void dec_wt_kernel(const float* __restrict__ src, uint32_t* __restrict__ hp) {
    int i = blockIdx.x * blockDim.x + threadIdx.x;
    if (i >= N * (K / 8)) return;
    int kc = i / N;
    int n = i % N;
    float v[8];
#pragma unroll
    for (int j = 0; j < 8; j++) v[j] = src[(size_t)(kc * 8 + j) * N + n];
    uint4 h;
    h.x = pk2h(hhi(v[0]), hhi(v[1]));
    h.y = pk2h(hhi(v[2]), hhi(v[3]));
    h.z = pk2h(hhi(v[4]), hhi(v[5]));
    h.w = pk2h(hhi(v[6]), hhi(v[7]));
    *(uint4*)(hp + (size_t)n * (K / 2) + kc * 4) = h;
}

// ---------------------------------------------------------------------------
// 2-term fp16 GEMM with ldmatrix (unchanged core). SCATTER epilogue now writes
// packed fp16 Q(hi/lo, pre-scaled)/K(hi)/V(hi) words directly.
// ---------------------------------------------------------------------------
#define GPAD 20
#define GTILE (128 * GPAD)
#define GSTG2 (3 * GTILE)
#define GEMM_SMEM_BYTES (2 * GSTG2 * 4)   // 61440

template <int N, bool SCATTER>
__global__ void __launch_bounds__(256, 2) f16_gemm_lm(const uint32_t* __restrict__ Ahp,
                                                      const uint32_t* __restrict__ Alp,
                                                      const uint32_t* __restrict__ Bhp,
                                                      const float* __restrict__ bias,
                                                      float* __restrict__ out) {
    constexpr int KW = 512;
    constexpr int KT = 32;
    extern __shared__ uint32_t smw[];
    const int tid = threadIdx.x;
    const int lane = tid & 31;
    const int warp = tid >> 5;
    const int wm = warp & 1;
    const int wn = warp >> 1;
    const int g = lane >> 2;
    const int t = lane & 3;
    const int mBase = blockIdx.y * 128;
    const int nBase = blockIdx.x * 128;

    const int fRow = tid >> 1;
    const int fh = (tid & 1) * 8;
    const uint32_t* gAh = Ahp + (size_t)(mBase + fRow) * KW + fh;
    const uint32_t* gAl = Alp + (size_t)(mBase + fRow) * KW + fh;
    const uint32_t* gBh = Bhp + (size_t)(nBase + fRow) * KW + fh;

    const uint32_t sBase = (uint32_t)__cvta_generic_to_shared(smw);
    const uint32_t fOff = (fRow * GPAD + fh) * 4;

    auto loadStage = [&](int s, int kt) {
        uint32_t b0 = sBase + s * (GSTG2 * 4);
        int kw = kt * 16;
        cp16(b0 + fOff, gAh + kw);
        cp16(b0 + fOff + 16, gAh + kw + 4);
        cp16(b0 + GTILE * 4 + fOff, gAl + kw);
        cp16(b0 + GTILE * 4 + fOff + 16, gAl + kw + 4);
        cp16(b0 + 2 * GTILE * 4 + fOff, gBh + kw);
        cp16(b0 + 2 * GTILE * 4 + fOff + 16, gBh + kw + 4);
    };

    const int aOff = ((lane & 7) + ((lane >> 3) & 1) * 8) * GPAD + ((lane >> 4) & 1) * 4;
    const int bOff = ((lane & 7) + ((lane >> 4) & 1) * 8) * GPAD + ((lane >> 3) & 1) * 4;

    float c[4][4][4];
#pragma unroll
    for (int mi = 0; mi < 4; mi++)
#pragma unroll
        for (int ni = 0; ni < 4; ni++)
#pragma unroll
            for (int r = 0; r < 4; r++) c[mi][ni][r] = 0.f;

    loadStage(0, 0);
    cp_commit();

    for (int kt = 0; kt < KT; kt++) {
        if (kt + 1 < KT) {
            loadStage((kt + 1) & 1, kt + 1);
            cp_commit();
            cp_wait<1>();
        } else {
            cp_wait<0>();
        }
        __syncthreads();

        const uint32_t sb = sBase + (kt & 1) * (GSTG2 * 4);
        const uint32_t sAh_u = sb;
        const uint32_t sAl_u = sb + GTILE * 4;
        const uint32_t sBh_u = sb + 2 * GTILE * 4;

#pragma unroll
        for (int ks = 0; ks < 2; ks++) {
            const int kw0 = ks * 8;
            uint32_t ah[4][4], al[4][4], bh[2][4];
#pragma unroll
            for (int mi = 0; mi < 4; mi++) {
                uint32_t base = ((wm * 64 + mi * 16) * GPAD + aOff + kw0) * 4;
                LDSM4(ah[mi], sAh_u + base);
                LDSM4(al[mi], sAl_u + base);
            }
#pragma unroll
            for (int q = 0; q < 2; q++) {
                uint32_t base = ((wn * 32 + q * 16) * GPAD + bOff + kw0) * 4;
                LDSM4(bh[q], sBh_u + base);
            }
#pragma unroll
            for (int mi = 0; mi < 4; mi++)
#pragma unroll
                for (int ni = 0; ni < 4; ni++) {
                    const int q = ni >> 1;
                    const int r = (ni & 1) * 2;
                    mma_f16(c[mi][ni], al[mi][0], al[mi][1], al[mi][2], al[mi][3],
                            bh[q][r], bh[q][r + 1]);
                    mma_f16(c[mi][ni], ah[mi][0], ah[mi][1], ah[mi][2], ah[mi][3],
                            bh[q][r], bh[q][r + 1]);
                }
        }
        __syncthreads();
    }

    // Epilogue
#pragma unroll
    for (int mi = 0; mi < 4; mi++) {
#pragma unroll
        for (int ni = 0; ni < 4; ni++) {
#pragma unroll
            for (int half = 0; half < 2; half++) {
                int m = mBase + wm * 64 + mi * 16 + g + half * 8;
                int n = nBase + wn * 32 + ni * 8 + t * 2;
                float v0 = c[mi][ni][half * 2 + 0] + bias[n];
                float v1 = c[mi][ni][half * 2 + 1] + bias[n + 1];
                if (SCATTER) {
                    int b = m >> 11;
                    int s2 = m & (SS - 1);
                    int h = n / 192;
                    int rem = n - h * 192;
                    int ty2 = rem >> 6;
                    int d = rem & 63;
                    size_t widx = ((size_t)(b * HH + h) * SS + s2) * (HD / 2) + (d >> 1);
                    if (ty2 == 0) {
                        float q0 = v0 * 0.125f, q1 = v1 * 0.125f;
                        float h0 = hhi(q0), h1 = hhi(q1);
                        g_qhp[widx] = pk2h(h0, h1);
                        g_qlp[widx] = pk2h(q0 - h0, q1 - h1);
                    } else if (ty2 == 1) {
                        g_khp[widx] = pk2h(hhi(v0), hhi(v1));
                    } else {
                        g_vhp[widx] = pk2h(hhi(v0), hhi(v1));
                    }
                } else {
                    *(float2*)(out + (size_t)m * N + n) = make_float2(v0, v1);
                }
            }
        }
    }
}

// ---------------------------------------------------------------------------
// 2-term fp16 flash attention, fully pre-packed inputs.
// Q tile 128, KV tile 64, 8 warps x 16 exclusive rows.
// smem (words): Qh/Ql [128][36] | Ph/Pl [128][36] | ring of 3: K[64][36] V[64][36]
// K: non-trans ldmatrix B-frags. V: ldmatrix.trans B-frags (no repack anywhere).
// ---------------------------------------------------------------------------
#define AQP 36
#define AQSZ (128 * AQP)     // 4608 words
#define AKSZ (64 * AQP)      // 2304 words per K or V tile
#define ASTG (2 * AKSZ)      // K+V per ring stage
#define ATTN_SMEM_WORDS (4 * AQSZ + 3 * ASTG)
#define ATTN_SMEM_BYTES (ATTN_SMEM_WORDS * 4)   // 129024

__global__ void __launch_bounds__(256, 1) attn_kernel6() {
    extern __shared__ uint32_t smw[];
    uint32_t* sQh = smw;
    uint32_t* sQl = sQh + AQSZ;
    uint32_t* sPh = sQl + AQSZ;
    uint32_t* sPl = sPh + AQSZ;
    uint32_t* sRing = sPl + AQSZ;     // 3 stages x (K tile | V tile)

    const int tid = threadIdx.x;
    const int lane = tid & 31;
    const int warp = tid >> 5;
    const int g = lane >> 2;
    const int t = lane & 3;
    const int qt = (gridDim.x - 1) - blockIdx.x;
    const int bh = blockIdx.y;
    const int b = bh >> 4, h = bh & 15;
    const int qBase = qt * 128;
    const int m0 = warp * 16;

    const uint32_t* Qh = g_qhp + (size_t)(bh * SS + qBase) * (HD / 2);
    const uint32_t* Ql = g_qlp + (size_t)(bh * SS + qBase) * (HD / 2);
    const uint32_t* Kh = g_khp + (size_t)bh * SS * (HD / 2);
    const uint32_t* Vh = g_vhp + (size_t)bh * SS * (HD / 2);

    const uint32_t sBase = (uint32_t)__cvta_generic_to_shared(smw);
    const uint32_t sQh_u = sBase;
    const uint32_t sQl_u = sBase + AQSZ * 4;
    const uint32_t sPh_u = sBase + 2 * AQSZ * 4;
    const uint32_t sPl_u = sBase + 3 * AQSZ * 4;
    const uint32_t sRing_u = sBase + 4 * AQSZ * 4;

    // ldmatrix per-lane offsets (words, pad 36)
    const int aOff = ((lane & 7) + ((lane >> 3) & 1) * 8) * AQP + ((lane >> 4) & 1) * 4;
    const int bOff = ((lane & 7) + ((lane >> 4) & 1) * 8) * AQP + ((lane >> 3) & 1) * 4;
    // V trans-frag offset: tile0/1 rows +0/+8, tile2/3 col +4 words
    const int vOff = (((lane & 7) + ((lane >> 3) & 1) * 8) * AQP + ((lane >> 4) & 1) * 4);

    // Q load: 128 rows x 32 words, 2 threads/row
    {
        int qRow = tid >> 1;
        int qc = (tid & 1) * 16;
        const uint32_t* gh = Qh + (size_t)qRow * 32 + qc;
        const uint32_t* gl = Ql + (size_t)qRow * 32 + qc;
        uint32_t dst = (qRow * AQP + qc) * 4;
#pragma unroll
        for (int c2 = 0; c2 < 4; c2++) {
            cp16(sQh_u + dst + c2 * 16, gh + c2 * 4);
            cp16(sQl_u + dst + c2 * 16, gl + c2 * 4);
        }
    }

    // KV tile load: 64 rows x 32 words each, 4 threads/row
    const int kRow = tid >> 2;
    const int kc = (tid & 3) * 8;
    auto prefetchKV = [&](int stg, int j) {
        int kvB = j * 64;
        uint32_t dst = sRing_u + (stg * ASTG + kRow * AQP + kc) * 4;
        const uint32_t* gk = Kh + (size_t)(kvB + kRow) * 32 + kc;
        const uint32_t* gv = Vh + (size_t)(kvB + kRow) * 32 + kc;
        cp16(dst, gk);
        cp16(dst + 16, gk + 4);
        cp16(dst + AKSZ * 4, gv);
        cp16(dst + AKSZ * 4 + 16, gv + 4);
    };

    float m_[2] = {-1e30f, -1e30f};
    float l_[2] = {0.f, 0.f};
    float co[8][4];
#pragma unroll
    for (int ni = 0; ni < 8; ni++)
#pragma unroll
        for (int r = 0; r < 4; r++) co[ni][r] = 0.f;

    const int jmax = 2 * qt + 1;
    prefetchKV(0, 0);
    cp_commit();          // group: Q + KV0
    prefetchKV(1, 1);
    cp_commit();          // group: KV1

    for (int j = 0; j <= jmax; j++) {
        const int kvBase = j * 64;
        const int stg = j % 3;
        if (j < jmax) cp_wait<1>();
        else cp_wait<0>();
        __syncthreads();

        if (j + 2 <= jmax) {
            prefetchKV((j + 2) % 3, j + 2);
            cp_commit();
        }

        if (kvBase > qBase + m0 + 15) continue;  // warp tile fully masked

        const uint32_t sK_u = sRing_u + stg * ASTG * 4;
        const uint32_t sV_u = sK_u + AKSZ * 4;

        // Scores S = Q K^T (2-term fp16)
        float sc[8][4];
#pragma unroll
        for (int ni = 0; ni < 8; ni++)
#pragma unroll
            for (int r = 0; r < 4; r++) sc[ni][r] = 0.f;
#pragma unroll
        for (int ks = 0; ks < 4; ks++) {
            const int kw0 = ks * 8;
            uint32_t qh[4], ql[4], kb[4][4];
            uint32_t abase = (m0 * AQP + aOff + kw0) * 4;
            LDSM4(qh, sQh_u + abase);
            LDSM4(ql, sQl_u + abase);
#pragma unroll
            for (int q2 = 0; q2 < 4; q2++) {
                uint32_t bbase = ((q2 * 16) * AQP + bOff + kw0) * 4;
                LDSM4(kb[q2], sK_u + bbase);
            }
#pragma unroll
            for (int ni = 0; ni < 8; ni++) {
                const int q2 = ni >> 1;
                const int r = (ni & 1) * 2;
                mma_f16(sc[ni], ql[0], ql[1], ql[2], ql[3], kb[q2][r], kb[q2][r + 1]);
                mma_f16(sc[ni], qh[0], qh[1], qh[2], qh[3], kb[q2][r], kb[q2][r + 1]);
            }
        }

        // Causal mask
        if (kvBase + 63 > qBase + m0) {
#pragma unroll
            for (int ni = 0; ni < 8; ni++) {
#pragma unroll
                for (int r = 0; r < 4; r++) {
                    int row = qBase + m0 + g + ((r >= 2) ? 8 : 0);
                    int col = kvBase + ni * 8 + 2 * t + (r & 1);
                    if (col > row) sc[ni][r] = -1e30f;
                }
            }
        }

        // Warp-local online softmax (rows g and g+8)
        float mx0 = -1e30f, mx1 = -1e30f;
#pragma unroll
        for (int ni = 0; ni < 8; ni++) {
            mx0 = fmaxf(mx0, fmaxf(sc[ni][0], sc[ni][1]));
            mx1 = fmaxf(mx1, fmaxf(sc[ni][2], sc[ni][3]));
        }
#pragma unroll
        for (int o = 1; o <= 2; o <<= 1) {
            mx0 = fmaxf(mx0, __shfl_xor_sync(0xffffffffu, mx0, o));
            mx1 = fmaxf(mx1, __shfl_xor_sync(0xffffffffu, mx1, o));
        }
        float mn0 = fmaxf(m_[0], mx0), mn1 = fmaxf(m_[1], mx1);
        float a0 = __expf(m_[0] - mn0), a1 = __expf(m_[1] - mn1);
        float s0 = 0.f, s1 = 0.f;
#pragma unroll
        for (int ni = 0; ni < 8; ni++) {
            sc[ni][0] = __expf(sc[ni][0] - mn0);
            sc[ni][1] = __expf(sc[ni][1] - mn0);
            sc[ni][2] = __expf(sc[ni][2] - mn1);
            sc[ni][3] = __expf(sc[ni][3] - mn1);
            s0 += sc[ni][0] + sc[ni][1];
            s1 += sc[ni][2] + sc[ni][3];
        }
#pragma unroll
        for (int o = 1; o <= 2; o <<= 1) {
            s0 += __shfl_xor_sync(0xffffffffu, s0, o);
            s1 += __shfl_xor_sync(0xffffffffu, s1, o);
        }
        l_[0] = l_[0] * a0 + s0; m_[0] = mn0;
        l_[1] = l_[1] * a1 + s1; m_[1] = mn1;
#pragma unroll
        for (int ni = 0; ni < 8; ni++) {
            co[ni][0] *= a0; co[ni][1] *= a0;
            co[ni][2] *= a1; co[ni][3] *= a1;
        }

        // Pack P (hi/lo fp16) — warp-exclusive rows
#pragma unroll
        for (int ni = 0; ni < 8; ni++) {
            int w0 = (m0 + g) * AQP + ni * 4 + t;
            int w1 = (m0 + g + 8) * AQP + ni * 4 + t;
            float h0 = hhi(sc[ni][0]), h1 = hhi(sc[ni][1]);
            float h2 = hhi(sc[ni][2]), h3 = hhi(sc[ni][3]);
            sPh[w0] = pk2h(h0, h1);
            sPh[w1] = pk2h(h2, h3);
            sPl[w0] = pk2h(sc[ni][0] - h0, sc[ni][1] - h1);
            sPl[w1] = pk2h(sc[ni][2] - h2, sc[ni][3] - h3);
        }
        __syncwarp();

        // O += P @ V (2-term fp16; P via ldmatrix, V via ldmatrix.trans)
#pragma unroll
        for (int ks = 0; ks < 4; ks++) {
            const int kw0 = ks * 8;
            uint32_t ph[4], pl[4];
            uint32_t abase = (m0 * AQP + aOff + kw0) * 4;
            LDSM4(ph, sPh_u + abase);
            LDSM4(pl, sPl_u + abase);
#pragma unroll
            for (int np = 0; np < 4; np++) {
                uint32_t vb[4];
                uint32_t vbase = ((ks * 16) * AQP + np * 8 + vOff) * 4;
                LDSM4T(vb, sV_u + vbase);
                mma_f16(co[2 * np], pl[0], pl[1], pl[2], pl[3], vb[0], vb[1]);
                mma_f16(co[2 * np], ph[0], ph[1], ph[2], ph[3], vb[0], vb[1]);
                mma_f16(co[2 * np + 1], pl[0], pl[1], pl[2], pl[3], vb[2], vb[3]);
                mma_f16(co[2 * np + 1], ph[0], ph[1], ph[2], ph[3], vb[2], vb[3]);
            }
        }
    }

    // Epilogue: normalize, pack hi/lo fp16 for out-proj A input
    float inv0 = 1.0f / l_[0];
    float inv1 = 1.0f / l_[1];
    int r0 = qBase + m0 + g;
    int r1 = r0 + 8;
#pragma unroll
    for (int ni = 0; ni < 8; ni++) {
        int w = h * (HD / 2) + ni * 4 + t;
        size_t i0 = (size_t)(b * SS + r0) * (DM / 2) + w;
        size_t i1 = (size_t)(b * SS + r1) * (DM / 2) + w;
        float v0 = co[ni][0] * inv0, v1 = co[ni][1] * inv0;
        float v2 = co[ni][2] * inv1, v3 = co[ni][3] * inv1;
        float h0 = hhi(v0), h1 = hhi(v1), h2 = hhi(v2), h3 = hhi(v3);
        g_athp[i0] = pk2h(h0, h1);
        g_athp[i1] = pk2h(h2, h3);
        g_atlp[i0] = pk2h(v0 - h0, v1 - h1);
        g_atlp[i1] = pk2h(v2 - h2, v3 - h3);
    }
}

// ---------------------------------------------------------------------------

extern "C" void kernel_launch(void* const* d_in, const int* in_sizes, int n_in,
                              void* d_out, int out_size) {
    (void)in_sizes; (void)n_in; (void)out_size;
    const float* x     = (const float*)d_in[0];
    const float* w_qkv = (const float*)d_in[1];
    const float* b_qkv = (const float*)d_in[2];
    const float* w_out = (const float*)d_in[3];
    const float* b_out = (const float*)d_in[4];
    float* out = (float*)d_out;

    uint32_t *xhp, *xlp, *wqhp, *wohp, *athp, *atlp;
    cudaGetSymbolAddress((void**)&xhp, g_xhp);
    cudaGetSymbolAddress((void**)&xlp, g_xlp);
    cudaGetSymbolAddress((void**)&wqhp, g_wqhp);
    cudaGetSymbolAddress((void**)&wohp, g_wohp);
    cudaGetSymbolAddress((void**)&athp, g_athp);
    cudaGetSymbolAddress((void**)&atlp, g_atlp);

    // Decompose/pack: x -> hi/lo [M][K/2]; weights transposed -> hi [N][K/2]
    dec_a_kernel<<<(BB*SS*DIN/8 + 255) / 256, 256>>>(x, xhp, xlp, BB*SS*DIN/8);
    dec_wt_kernel<3*DM, DIN><<<(3*DM*(DIN/8) + 255) / 256, 256>>>(w_qkv, wqhp);
    dec_wt_kernel<DM, DM><<<(DM*(DM/8) + 255) / 256, 256>>>(w_out, wohp);

    // QKV GEMM (scatter packed fp16 q/k/v)
    {
        cudaFuncSetAttribute(f16_gemm_lm<3 * DM, true>,
                             cudaFuncAttributeMaxDynamicSharedMemorySize, GEMM_SMEM_BYTES);
        dim3 grid(3 * DM / 128, BB * SS / 128);
        f16_gemm_lm<3 * DM, true><<<grid, 256, GEMM_SMEM_BYTES>>>(xhp, xlp, wqhp, b_qkv, nullptr);
    }
    // Flash attention (2-term fp16, pre-packed inputs)
    {
        cudaFuncSetAttribute(attn_kernel6, cudaFuncAttributeMaxDynamicSharedMemorySize, ATTN_SMEM_BYTES);
        dim3 grid(SS / 128, BH);
        attn_kernel6<<<grid, 256, ATTN_SMEM_BYTES>>>();
    }
    // Output GEMM
    {
        cudaFuncSetAttribute(f16_gemm_lm<DM, false>,
                             cudaFuncAttributeMaxDynamicSharedMemorySize, GEMM_SMEM_BYTES);
        dim3 grid(DM / 128, BB * SS / 128);
        f16_gemm_lm<DM, false><<<grid, 256, GEMM_SMEM_BYTES>>>(athp, atlp, wohp, b_out, out);
    }
}

// round 14
// speedup vs baseline: 3.6919x; 1.0520x over previous
#include <cuda_runtime.h>
#include <cuda_fp16.h>
#include <cstdint>

#define BB 2
#define SS 2048
#define DIN 1024
#define DM 1024
#define HH 16
#define HD 64
#define BH (BB*HH)

// ---------------------------------------------------------------------------
// Scratch (__device__ globals; no allocation allowed)
// ---------------------------------------------------------------------------
__device__ uint32_t g_qhp[BH*SS*HD/2];       // Q fp16 hi, pre-scaled, [bh][s][d_word]
__device__ uint32_t g_qlp[BH*SS*HD/2];       // Q fp16 lo
__device__ uint32_t g_khp[BH*SS*HD/2];       // K fp16 hi
__device__ uint32_t g_vhp[BH*SS*HD/2];       // V fp16 hi
__device__ uint32_t g_xhp[BB*SS*DIN/2];      // x fp16 [M][K/2] hi words
__device__ uint32_t g_xlp[BB*SS*DIN/2];
__device__ uint32_t g_wqhp[3*DM*(DIN/2)];    // W_qkv^T fp16 [N][K/2] hi
__device__ uint32_t g_wohp[DM*(DM/2)];       // W_out^T fp16 [N][K/2] hi
__device__ uint32_t g_athp[BB*SS*DM/2];      // attn out fp16 hi
__device__ uint32_t g_atlp[BB*SS*DM/2];      // attn out fp16 lo

// ---------------------------------------------------------------------------
// fp16 helpers
// ---------------------------------------------------------------------------
__device__ __forceinline__ uint32_t pk2h(float a, float b) {
    __half2 v = __floats2half2_rn(a, b);
    return *reinterpret_cast<uint32_t*>(&v);
}
__device__ __forceinline__ float hhi(float a) {
    return __half2float(__float2half_rn(a));
}

__device__ __forceinline__ void mma_f16(float c[4],
                                        uint32_t a0, uint32_t a1, uint32_t a2, uint32_t a3,
                                        uint32_t b0, uint32_t b1) {
    asm volatile(
        "mma.sync.aligned.m16n8k16.row.col.f32.f16.f16.f32 "
        "{%0,%1,%2,%3}, {%4,%5,%6,%7}, {%8,%9}, {%0,%1,%2,%3};"
        : "+f"(c[0]), "+f"(c[1]), "+f"(c[2]), "+f"(c[3])
        : "r"(a0), "r"(a1), "r"(a2), "r"(a3), "r"(b0), "r"(b1));
}

__device__ __forceinline__ void cp16(uint32_t dst, const void* src) {
    asm volatile("cp.async.ca.shared.global [%0], [%1], 16;" :: "r"(dst), "l"(src));
}
__device__ __forceinline__ void cp_commit() { asm volatile("cp.async.commit_group;"); }
template <int n>
__device__ __forceinline__ void cp_wait() { asm volatile("cp.async.wait_group %0;" :: "n"(n)); }

#define LDSM4(r, addr) \
    asm volatile("ldmatrix.sync.aligned.m8n8.x4.shared.b16 {%0,%1,%2,%3}, [%4];" \
                 : "=r"((r)[0]), "=r"((r)[1]), "=r"((r)[2]), "=r"((r)[3]) \
                 : "r"(addr))
#define LDSM4T(r, addr) \
    asm volatile("ldmatrix.sync.aligned.m8n8.x4.trans.shared.b16 {%0,%1,%2,%3}, [%4];" \
                 : "=r"((r)[0]), "=r"((r)[1]), "=r"((r)[2]), "=r"((r)[3]) \
                 : "r"(addr))

// ---------------------------------------------------------------------------
// Decompose/pack kernels
// ---------------------------------------------------------------------------
__global__ void dec_a_kernel(const float* __restrict__ src, uint32_t* __restrict__ hp,
                             uint32_t* __restrict__ lp, int n8) {
    int i = blockIdx.x * blockDim.x + threadIdx.x;
    if (i >= n8) return;
    const float4* s4 = (const float4*)src;
    float4 v0 = s4[2 * i], v1 = s4[2 * i + 1];
    uint4 h, l;
    float h0, h1;
    h0 = hhi(v0.x); h1 = hhi(v0.y); h.x = pk2h(h0, h1); l.x = pk2h(v0.x - h0, v0.y - h1);
    h0 = hhi(v0.z); h1 = hhi(v0.w); h.y = pk2h(h0, h1); l.y = pk2h(v0.z - h0, v0.w - h1);
    h0 = hhi(v1.x); h1 = hhi(v1.y); h.z = pk2h(h0, h1); l.z = pk2h(v1.x - h0, v1.y - h1);
    h0 = hhi(v1.z); h1 = hhi(v1.w); h.w = pk2h(h0, h1); l.w = pk2h(v1.z - h0, v1.w - h1);
    ((uint4*)hp)[i] = h;
    ((uint4*)lp)[i] = l;
}
template <int N, int K>
__global__ void dec_wt_kernel(const float* __restrict__ src, uint32_t* __restrict__ hp) {
    int i = blockIdx.x * blockDim.x + threadIdx.x;
    if (i >= N * (K / 8)) return;
    int kc = i / N;
    int n = i % N;
    float v[8];
#pragma unroll
    for (int j = 0; j < 8; j++) v[j] = src[(size_t)(kc * 8 + j) * N + n];
    uint4 h;
    h.x = pk2h(hhi(v[0]), hhi(v[1]));
    h.y = pk2h(hhi(v[2]), hhi(v[3]));
    h.z = pk2h(hhi(v[4]), hhi(v[5]));
    h.w = pk2h(hhi(v[6]), hhi(v[7]));
    *(uint4*)(hp + (size_t)n * (K / 2) + kc * 4) = h;
}

// ---------------------------------------------------------------------------
// 2-term fp16 GEMM with ldmatrix (at mma.sync ceiling; unchanged core).
// ---------------------------------------------------------------------------
#define GPAD 20
#define GTILE (128 * GPAD)
#define GSTG2 (3 * GTILE)
#define GEMM_SMEM_BYTES (2 * GSTG2 * 4)   // 61440

template <int N, bool SCATTER>
__global__ void __launch_bounds__(256, 2) f16_gemm_lm(const uint32_t* __restrict__ Ahp,
                                                      const uint32_t* __restrict__ Alp,
                                                      const uint32_t* __restrict__ Bhp,
                                                      const float* __restrict__ bias,
                                                      float* __restrict__ out) {
    constexpr int KW = 512;
    constexpr int KT = 32;
    extern __shared__ uint32_t smw[];
    const int tid = threadIdx.x;
    const int lane = tid & 31;
    const int warp = tid >> 5;
    const int wm = warp & 1;
    const int wn = warp >> 1;
    const int g = lane >> 2;
    const int t = lane & 3;
    const int mBase = blockIdx.y * 128;
    const int nBase = blockIdx.x * 128;

    const int fRow = tid >> 1;
    const int fh = (tid & 1) * 8;
    const uint32_t* gAh = Ahp + (size_t)(mBase + fRow) * KW + fh;
    const uint32_t* gAl = Alp + (size_t)(mBase + fRow) * KW + fh;
    const uint32_t* gBh = Bhp + (size_t)(nBase + fRow) * KW + fh;

    const uint32_t sBase = (uint32_t)__cvta_generic_to_shared(smw);
    const uint32_t fOff = (fRow * GPAD + fh) * 4;

    auto loadStage = [&](int s, int kt) {
        uint32_t b0 = sBase + s * (GSTG2 * 4);
        int kw = kt * 16;
        cp16(b0 + fOff, gAh + kw);
        cp16(b0 + fOff + 16, gAh + kw + 4);
        cp16(b0 + GTILE * 4 + fOff, gAl + kw);
        cp16(b0 + GTILE * 4 + fOff + 16, gAl + kw + 4);
        cp16(b0 + 2 * GTILE * 4 + fOff, gBh + kw);
        cp16(b0 + 2 * GTILE * 4 + fOff + 16, gBh + kw + 4);
    };

    const int aOff = ((lane & 7) + ((lane >> 3) & 1) * 8) * GPAD + ((lane >> 4) & 1) * 4;
    const int bOff = ((lane & 7) + ((lane >> 4) & 1) * 8) * GPAD + ((lane >> 3) & 1) * 4;

    float c[4][4][4];
#pragma unroll
    for (int mi = 0; mi < 4; mi++)
#pragma unroll
        for (int ni = 0; ni < 4; ni++)
#pragma unroll
            for (int r = 0; r < 4; r++) c[mi][ni][r] = 0.f;

    loadStage(0, 0);
    cp_commit();

    for (int kt = 0; kt < KT; kt++) {
        if (kt + 1 < KT) {
            loadStage((kt + 1) & 1, kt + 1);
            cp_commit();
            cp_wait<1>();
        } else {
            cp_wait<0>();
        }
        __syncthreads();

        const uint32_t sb = sBase + (kt & 1) * (GSTG2 * 4);
        const uint32_t sAh_u = sb;
        const uint32_t sAl_u = sb + GTILE * 4;
        const uint32_t sBh_u = sb + 2 * GTILE * 4;

#pragma unroll
        for (int ks = 0; ks < 2; ks++) {
            const int kw0 = ks * 8;
            uint32_t ah[4][4], al[4][4], bh[2][4];
#pragma unroll
            for (int mi = 0; mi < 4; mi++) {
                uint32_t base = ((wm * 64 + mi * 16) * GPAD + aOff + kw0) * 4;
                LDSM4(ah[mi], sAh_u + base);
                LDSM4(al[mi], sAl_u + base);
            }
#pragma unroll
            for (int q = 0; q < 2; q++) {
                uint32_t base = ((wn * 32 + q * 16) * GPAD + bOff + kw0) * 4;
                LDSM4(bh[q], sBh_u + base);
            }
#pragma unroll
            for (int mi = 0; mi < 4; mi++)
#pragma unroll
                for (int ni = 0; ni < 4; ni++) {
                    const int q = ni >> 1;
                    const int r = (ni & 1) * 2;
                    mma_f16(c[mi][ni], al[mi][0], al[mi][1], al[mi][2], al[mi][3],
                            bh[q][r], bh[q][r + 1]);
                    mma_f16(c[mi][ni], ah[mi][0], ah[mi][1], ah[mi][2], ah[mi][3],
                            bh[q][r], bh[q][r + 1]);
                }
        }
        __syncthreads();
    }

    // Epilogue
#pragma unroll
    for (int mi = 0; mi < 4; mi++) {
#pragma unroll
        for (int ni = 0; ni < 4; ni++) {
#pragma unroll
            for (int half = 0; half < 2; half++) {
                int m = mBase + wm * 64 + mi * 16 + g + half * 8;
                int n = nBase + wn * 32 + ni * 8 + t * 2;
                float v0 = c[mi][ni][half * 2 + 0] + bias[n];
                float v1 = c[mi][ni][half * 2 + 1] + bias[n + 1];
                if (SCATTER) {
                    int b = m >> 11;
                    int s2 = m & (SS - 1);
                    int h = n / 192;
                    int rem = n - h * 192;
                    int ty2 = rem >> 6;
                    int d = rem & 63;
                    size_t widx = ((size_t)(b * HH + h) * SS + s2) * (HD / 2) + (d >> 1);
                    if (ty2 == 0) {
                        float q0 = v0 * 0.125f, q1 = v1 * 0.125f;
                        float h0 = hhi(q0), h1 = hhi(q1);
                        g_qhp[widx] = pk2h(h0, h1);
                        g_qlp[widx] = pk2h(q0 - h0, q1 - h1);
                    } else if (ty2 == 1) {
                        g_khp[widx] = pk2h(hhi(v0), hhi(v1));
                    } else {
                        g_vhp[widx] = pk2h(hhi(v0), hhi(v1));
                    }
                } else {
                    *(float2*)(out + (size_t)m * N + n) = make_float2(v0, v1);
                }
            }
        }
    }
}

// ---------------------------------------------------------------------------
// fp16 flash attention: 2-term QK^T, 1-term P@V, pre-packed inputs.
// Q tile 128, KV tile 64, 8 warps x 16 exclusive rows, 2 CTAs/SM.
// smem (words): Qh/Ql [128][36] | Ph [128][36] | ring of 3: K[64][36] V[64][36]
// ---------------------------------------------------------------------------
#define AQP 36
#define AQSZ (128 * AQP)     // 4608 words
#define AKSZ (64 * AQP)      // 2304 words per K or V tile
#define ASTG (2 * AKSZ)      // K+V per ring stage
#define ATTN_SMEM_WORDS (3 * AQSZ + 3 * ASTG)
#define ATTN_SMEM_BYTES (ATTN_SMEM_WORDS * 4)   // 110592

__global__ void __launch_bounds__(256, 2) attn_kernel7() {
    extern __shared__ uint32_t smw[];
    uint32_t* sPh = smw + 2 * AQSZ;

    const int tid = threadIdx.x;
    const int lane = tid & 31;
    const int warp = tid >> 5;
    const int g = lane >> 2;
    const int t = lane & 3;
    const int qt = (gridDim.x - 1) - blockIdx.x;
    const int bh = blockIdx.y;
    const int b = bh >> 4, h = bh & 15;
    const int qBase = qt * 128;
    const int m0 = warp * 16;

    const uint32_t* Qh = g_qhp + (size_t)(bh * SS + qBase) * (HD / 2);
    const uint32_t* Ql = g_qlp + (size_t)(bh * SS + qBase) * (HD / 2);
    const uint32_t* Kh = g_khp + (size_t)bh * SS * (HD / 2);
    const uint32_t* Vh = g_vhp + (size_t)bh * SS * (HD / 2);

    const uint32_t sBase = (uint32_t)__cvta_generic_to_shared(smw);
    const uint32_t sQh_u = sBase;
    const uint32_t sQl_u = sBase + AQSZ * 4;
    const uint32_t sPh_u = sBase + 2 * AQSZ * 4;
    const uint32_t sRing_u = sBase + 3 * AQSZ * 4;

    // ldmatrix per-lane offsets (words, pad 36)
    const int aOff = ((lane & 7) + ((lane >> 3) & 1) * 8) * AQP + ((lane >> 4) & 1) * 4;
    const int bOff = ((lane & 7) + ((lane >> 4) & 1) * 8) * AQP + ((lane >> 3) & 1) * 4;
    const int vOff = (((lane & 7) + ((lane >> 3) & 1) * 8) * AQP + ((lane >> 4) & 1) * 4);

    // Q load: 128 rows x 32 words, 2 threads/row
    {
        int qRow = tid >> 1;
        int qc = (tid & 1) * 16;
        const uint32_t* gh = Qh + (size_t)qRow * 32 + qc;
        const uint32_t* gl = Ql + (size_t)qRow * 32 + qc;
        uint32_t dst = (qRow * AQP + qc) * 4;
#pragma unroll
        for (int c2 = 0; c2 < 4; c2++) {
            cp16(sQh_u + dst + c2 * 16, gh + c2 * 4);
            cp16(sQl_u + dst + c2 * 16, gl + c2 * 4);
        }
    }

    // KV tile load: 64 rows x 32 words each, 4 threads/row
    const int kRow = tid >> 2;
    const int kc = (tid & 3) * 8;
    auto prefetchKV = [&](int stg, int j) {
        int kvB = j * 64;
        uint32_t dst = sRing_u + (stg * ASTG + kRow * AQP + kc) * 4;
        const uint32_t* gk = Kh + (size_t)(kvB + kRow) * 32 + kc;
        const uint32_t* gv = Vh + (size_t)(kvB + kRow) * 32 + kc;
        cp16(dst, gk);
        cp16(dst + 16, gk + 4);
        cp16(dst + AKSZ * 4, gv);
        cp16(dst + AKSZ * 4 + 16, gv + 4);
    };

    float m_[2] = {-1e30f, -1e30f};
    float l_[2] = {0.f, 0.f};
    float co[8][4];
#pragma unroll
    for (int ni = 0; ni < 8; ni++)
#pragma unroll
        for (int r = 0; r < 4; r++) co[ni][r] = 0.f;

    const int jmax = 2 * qt + 1;
    prefetchKV(0, 0);
    cp_commit();          // group: Q + KV0
    prefetchKV(1, 1);
    cp_commit();          // group: KV1

    for (int j = 0; j <= jmax; j++) {
        const int kvBase = j * 64;
        const int stg = j % 3;
        if (j < jmax) cp_wait<1>();
        else cp_wait<0>();
        __syncthreads();

        if (j + 2 <= jmax) {
            prefetchKV((j + 2) % 3, j + 2);
            cp_commit();
        }

        if (kvBase > qBase + m0 + 15) continue;  // warp tile fully masked

        const uint32_t sK_u = sRing_u + stg * ASTG * 4;
        const uint32_t sV_u = sK_u + AKSZ * 4;

        // Scores S = Q K^T (2-term fp16)
        float sc[8][4];
#pragma unroll
        for (int ni = 0; ni < 8; ni++)
#pragma unroll
            for (int r = 0; r < 4; r++) sc[ni][r] = 0.f;
#pragma unroll
        for (int ks = 0; ks < 4; ks++) {
            const int kw0 = ks * 8;
            uint32_t qh[4], ql[4], kb[4][4];
            uint32_t abase = (m0 * AQP + aOff + kw0) * 4;
            LDSM4(qh, sQh_u + abase);
            LDSM4(ql, sQl_u + abase);
#pragma unroll
            for (int q2 = 0; q2 < 4; q2++) {
                uint32_t bbase = ((q2 * 16) * AQP + bOff + kw0) * 4;
                LDSM4(kb[q2], sK_u + bbase);
            }
#pragma unroll
            for (int ni = 0; ni < 8; ni++) {
                const int q2 = ni >> 1;
                const int r = (ni & 1) * 2;
                mma_f16(sc[ni], ql[0], ql[1], ql[2], ql[3], kb[q2][r], kb[q2][r + 1]);
                mma_f16(sc[ni], qh[0], qh[1], qh[2], qh[3], kb[q2][r], kb[q2][r + 1]);
            }
        }

        // Causal mask
        if (kvBase + 63 > qBase + m0) {
#pragma unroll
            for (int ni = 0; ni < 8; ni++) {
#pragma unroll
                for (int r = 0; r < 4; r++) {
                    int row = qBase + m0 + g + ((r >= 2) ? 8 : 0);
                    int col = kvBase + ni * 8 + 2 * t + (r & 1);
                    if (col > row) sc[ni][r] = -1e30f;
                }
            }
        }

        // Warp-local online softmax (rows g and g+8)
        float mx0 = -1e30f, mx1 = -1e30f;
#pragma unroll
        for (int ni = 0; ni < 8; ni++) {
            mx0 = fmaxf(mx0, fmaxf(sc[ni][0], sc[ni][1]));
            mx1 = fmaxf(mx1, fmaxf(sc[ni][2], sc[ni][3]));
        }
#pragma unroll
        for (int o = 1; o <= 2; o <<= 1) {
            mx0 = fmaxf(mx0, __shfl_xor_sync(0xffffffffu, mx0, o));
            mx1 = fmaxf(mx1, __shfl_xor_sync(0xffffffffu, mx1, o));
        }
        float mn0 = fmaxf(m_[0], mx0), mn1 = fmaxf(m_[1], mx1);
        float a0 = __expf(m_[0] - mn0), a1 = __expf(m_[1] - mn1);
        float s0 = 0.f, s1 = 0.f;
#pragma unroll
        for (int ni = 0; ni < 8; ni++) {
            sc[ni][0] = __expf(sc[ni][0] - mn0);
            sc[ni][1] = __expf(sc[ni][1] - mn0);
            sc[ni][2] = __expf(sc[ni][2] - mn1);
            sc[ni][3] = __expf(sc[ni][3] - mn1);
            s0 += sc[ni][0] + sc[ni][1];
            s1 += sc[ni][2] + sc[ni][3];
        }
#pragma unroll
        for (int o = 1; o <= 2; o <<= 1) {
            s0 += __shfl_xor_sync(0xffffffffu, s0, o);
            s1 += __shfl_xor_sync(0xffffffffu, s1, o);
        }
        l_[0] = l_[0] * a0 + s0; m_[0] = mn0;
        l_[1] = l_[1] * a1 + s1; m_[1] = mn1;
#pragma unroll
        for (int ni = 0; ni < 8; ni++) {
            co[ni][0] *= a0; co[ni][1] *= a0;
            co[ni][2] *= a1; co[ni][3] *= a1;
        }

        // Pack P (hi only) — warp-exclusive rows
#pragma unroll
        for (int ni = 0; ni < 8; ni++) {
            int w0 = (m0 + g) * AQP + ni * 4 + t;
            int w1 = (m0 + g + 8) * AQP + ni * 4 + t;
            sPh[w0] = pk2h(sc[ni][0], sc[ni][1]);
            sPh[w1] = pk2h(sc[ni][2], sc[ni][3]);
        }
        __syncwarp();

        // O += P @ V (1-term fp16; P via ldmatrix, V via ldmatrix.trans)
#pragma unroll
        for (int ks = 0; ks < 4; ks++) {
            const int kw0 = ks * 8;
            uint32_t ph[4];
            uint32_t abase = (m0 * AQP + aOff + kw0) * 4;
            LDSM4(ph, sPh_u + abase);
#pragma unroll
            for (int np = 0; np < 4; np++) {
                uint32_t vb[4];
                uint32_t vbase = ((ks * 16) * AQP + np * 8 + vOff) * 4;
                LDSM4T(vb, sV_u + vbase);
                mma_f16(co[2 * np], ph[0], ph[1], ph[2], ph[3], vb[0], vb[1]);
                mma_f16(co[2 * np + 1], ph[0], ph[1], ph[2], ph[3], vb[2], vb[3]);
            }
        }
    }

    // Epilogue: normalize, pack hi/lo fp16 for out-proj A input
    float inv0 = 1.0f / l_[0];
    float inv1 = 1.0f / l_[1];
    int r0 = qBase + m0 + g;
    int r1 = r0 + 8;
#pragma unroll
    for (int ni = 0; ni < 8; ni++) {
        int w = h * (HD / 2) + ni * 4 + t;
        size_t i0 = (size_t)(b * SS + r0) * (DM / 2) + w;
        size_t i1 = (size_t)(b * SS + r1) * (DM / 2) + w;
        float v0 = co[ni][0] * inv0, v1 = co[ni][1] * inv0;
        float v2 = co[ni][2] * inv1, v3 = co[ni][3] * inv1;
        float h0 = hhi(v0), h1 = hhi(v1), h2 = hhi(v2), h3 = hhi(v3);
        g_athp[i0] = pk2h(h0, h1);
        g_athp[i1] = pk2h(h2, h3);
        g_atlp[i0] = pk2h(v0 - h0, v1 - h1);
        g_atlp[i1] = pk2h(v2 - h2, v3 - h3);
    }
}

// ---------------------------------------------------------------------------

extern "C" void kernel_launch(void* const* d_in, const int* in_sizes, int n_in,
                              void* d_out, int out_size) {
    (void)in_sizes; (void)n_in; (void)out_size;
    const float* x     = (const float*)d_in[0];
    const float* w_qkv = (const float*)d_in[1];
    const float* b_qkv = (const float*)d_in[2];
    const float* w_out = (const float*)d_in[3];
    const float* b_out = (const float*)d_in[4];
    float* out = (float*)d_out;

    uint32_t *xhp, *xlp, *wqhp, *wohp, *athp, *atlp;
    cudaGetSymbolAddress((void**)&xhp, g_xhp);
    cudaGetSymbolAddress((void**)&xlp, g_xlp);
    cudaGetSymbolAddress((void**)&wqhp, g_wqhp);
    cudaGetSymbolAddress((void**)&wohp, g_wohp);
    cudaGetSymbolAddress((void**)&athp, g_athp);
    cudaGetSymbolAddress((void**)&atlp, g_atlp);

    // Decompose/pack: x -> hi/lo [M][K/2]; weights transposed -> hi [N][K/2]
    dec_a_kernel<<<(BB*SS*DIN/8 + 255) / 256, 256>>>(x, xhp, xlp, BB*SS*DIN/8);
    dec_wt_kernel<3*DM, DIN><<<(3*DM*(DIN/8) + 255) / 256, 256>>>(w_qkv, wqhp);
    dec_wt_kernel<DM, DM><<<(DM*(DM/8) + 255) / 256, 256>>>(w_out, wohp);

    // QKV GEMM (scatter packed fp16 q/k/v)
    {
        cudaFuncSetAttribute(f16_gemm_lm<3 * DM, true>,
                             cudaFuncAttributeMaxDynamicSharedMemorySize, GEMM_SMEM_BYTES);
        dim3 grid(3 * DM / 128, BB * SS / 128);
        f16_gemm_lm<3 * DM, true><<<grid, 256, GEMM_SMEM_BYTES>>>(xhp, xlp, wqhp, b_qkv, nullptr);
    }
    // Flash attention (2-term QK, 1-term PV, 2 CTAs/SM)
    {
        cudaFuncSetAttribute(attn_kernel7, cudaFuncAttributeMaxDynamicSharedMemorySize, ATTN_SMEM_BYTES);
        dim3 grid(SS / 128, BH);
        attn_kernel7<<<grid, 256, ATTN_SMEM_BYTES>>>();
    }
    // Output GEMM
    {
        cudaFuncSetAttribute(f16_gemm_lm<DM, false>,
                             cudaFuncAttributeMaxDynamicSharedMemorySize, GEMM_SMEM_BYTES);
        dim3 grid(DM / 128, BB * SS / 128);
        f16_gemm_lm<DM, false><<<grid, 256, GEMM_SMEM_BYTES>>>(athp, atlp, wohp, b_out, out);
    }
}

// round 15
// speedup vs baseline: 4.7615x; 1.2897x over previous
#include <cuda_runtime.h>
#include <cuda_fp16.h>
#include <cstdint>

#define BB 2
#define SS 2048
#define DIN 1024
#define DM 1024
#define HH 16
#define HD 64
#define BH (BB*HH)

// ---------------------------------------------------------------------------
// Scratch (__device__ globals; no allocation allowed)
// ---------------------------------------------------------------------------
__device__ uint32_t g_qhp[BH*SS*HD/2];       // Q fp16 hi, pre-scaled, [bh][s][d_word]
__device__ uint32_t g_qlp[BH*SS*HD/2];       // Q fp16 lo
__device__ uint32_t g_khp[BH*SS*HD/2];       // K fp16 hi
__device__ uint32_t g_vhp[BH*SS*HD/2];       // V fp16 hi
__device__ uint32_t g_xhp[BB*SS*DIN/2];      // x fp16 [M][K/2] hi words
__device__ uint32_t g_wqhp[3*DM*(DIN/2)];    // W_qkv^T fp16 [N][K/2] hi
__device__ uint32_t g_wohp[DM*(DM/2)];       // W_out^T fp16 [N][K/2] hi
__device__ uint32_t g_athp[BB*SS*DM/2];      // attn out fp16 hi

// ---------------------------------------------------------------------------
// fp16 helpers
// ---------------------------------------------------------------------------
__device__ __forceinline__ uint32_t pk2h(float a, float b) {
    __half2 v = __floats2half2_rn(a, b);
    return *reinterpret_cast<uint32_t*>(&v);
}
__device__ __forceinline__ float hhi(float a) {
    return __half2float(__float2half_rn(a));
}

__device__ __forceinline__ void mma_f16(float c[4],
                                        uint32_t a0, uint32_t a1, uint32_t a2, uint32_t a3,
                                        uint32_t b0, uint32_t b1) {
    asm volatile(
        "mma.sync.aligned.m16n8k16.row.col.f32.f16.f16.f32 "
        "{%0,%1,%2,%3}, {%4,%5,%6,%7}, {%8,%9}, {%0,%1,%2,%3};"
        : "+f"(c[0]), "+f"(c[1]), "+f"(c[2]), "+f"(c[3])
        : "r"(a0), "r"(a1), "r"(a2), "r"(a3), "r"(b0), "r"(b1));
}

__device__ __forceinline__ void cp16(uint32_t dst, const void* src) {
    asm volatile("cp.async.ca.shared.global [%0], [%1], 16;" :: "r"(dst), "l"(src));
}
__device__ __forceinline__ void cp_commit() { asm volatile("cp.async.commit_group;"); }
template <int n>
__device__ __forceinline__ void cp_wait() { asm volatile("cp.async.wait_group %0;" :: "n"(n)); }

#define LDSM4(r, addr) \
    asm volatile("ldmatrix.sync.aligned.m8n8.x4.shared.b16 {%0,%1,%2,%3}, [%4];" \
                 : "=r"((r)[0]), "=r"((r)[1]), "=r"((r)[2]), "=r"((r)[3]) \
                 : "r"(addr))
#define LDSM4T(r, addr) \
    asm volatile("ldmatrix.sync.aligned.m8n8.x4.trans.shared.b16 {%0,%1,%2,%3}, [%4];" \
                 : "=r"((r)[0]), "=r"((r)[1]), "=r"((r)[2]), "=r"((r)[3]) \
                 : "r"(addr))

// ---------------------------------------------------------------------------
// Decompose/pack kernels
// ---------------------------------------------------------------------------
__global__ void dec_a_hi_kernel(const float* __restrict__ src, uint32_t* __restrict__ hp,
                                int n8) {
    int i = blockIdx.x * blockDim.x + threadIdx.x;
    if (i >= n8) return;
    const float4* s4 = (const float4*)src;
    float4 v0 = s4[2 * i], v1 = s4[2 * i + 1];
    uint4 h;
    h.x = pk2h(hhi(v0.x), hhi(v0.y));
    h.y = pk2h(hhi(v0.z), hhi(v0.w));
    h.z = pk2h(hhi(v1.x), hhi(v1.y));
    h.w = pk2h(hhi(v1.z), hhi(v1.w));
    ((uint4*)hp)[i] = h;
}
template <int N, int K>
__global__ void dec_wt_kernel(const float* __restrict__ src, uint32_t* __restrict__ hp) {
    int i = blockIdx.x * blockDim.x + threadIdx.x;
    if (i >= N * (K / 8)) return;
    int kc = i / N;
    int n = i % N;
    float v[8];
#pragma unroll
    for (int j = 0; j < 8; j++) v[j] = src[(size_t)(kc * 8 + j) * N + n];
    uint4 h;
    h.x = pk2h(hhi(v[0]), hhi(v[1]));
    h.y = pk2h(hhi(v[2]), hhi(v[3]));
    h.z = pk2h(hhi(v[4]), hhi(v[5]));
    h.w = pk2h(hhi(v[6]), hhi(v[7]));
    *(uint4*)(hp + (size_t)n * (K / 2) + kc * 4) = h;
}

// ---------------------------------------------------------------------------
// 1-term fp16 GEMM with ldmatrix. CTA 128x128, k-tile 32 elems (16 words).
// 8 warps 2m x 4n, warp 64x32. A hi + B hi in [row][k_word] pad-20 smem.
// 2-stage cp.async, 2 CTAs/SM.
// ---------------------------------------------------------------------------
#define GPAD 20
#define GTILE (128 * GPAD)
#define GSTG2 (2 * GTILE)
#define GEMM_SMEM_BYTES (2 * GSTG2 * 4)   // 40960

template <int N, bool SCATTER>
__global__ void __launch_bounds__(256, 2) f16_gemm_hi(const uint32_t* __restrict__ Ahp,
                                                      const uint32_t* __restrict__ Bhp,
                                                      const float* __restrict__ bias,
                                                      float* __restrict__ out) {
    constexpr int KW = 512;
    constexpr int KT = 32;
    extern __shared__ uint32_t smw[];
    const int tid = threadIdx.x;
    const int lane = tid & 31;
    const int warp = tid >> 5;
    const int wm = warp & 1;
    const int wn = warp >> 1;
    const int g = lane >> 2;
    const int t = lane & 3;
    const int mBase = blockIdx.y * 128;
    const int nBase = blockIdx.x * 128;

    const int fRow = tid >> 1;
    const int fh = (tid & 1) * 8;
    const uint32_t* gAh = Ahp + (size_t)(mBase + fRow) * KW + fh;
    const uint32_t* gBh = Bhp + (size_t)(nBase + fRow) * KW + fh;

    const uint32_t sBase = (uint32_t)__cvta_generic_to_shared(smw);
    const uint32_t fOff = (fRow * GPAD + fh) * 4;

    auto loadStage = [&](int s, int kt) {
        uint32_t b0 = sBase + s * (GSTG2 * 4);
        int kw = kt * 16;
        cp16(b0 + fOff, gAh + kw);
        cp16(b0 + fOff + 16, gAh + kw + 4);
        cp16(b0 + GTILE * 4 + fOff, gBh + kw);
        cp16(b0 + GTILE * 4 + fOff + 16, gBh + kw + 4);
    };

    const int aOff = ((lane & 7) + ((lane >> 3) & 1) * 8) * GPAD + ((lane >> 4) & 1) * 4;
    const int bOff = ((lane & 7) + ((lane >> 4) & 1) * 8) * GPAD + ((lane >> 3) & 1) * 4;

    float c[4][4][4];
#pragma unroll
    for (int mi = 0; mi < 4; mi++)
#pragma unroll
        for (int ni = 0; ni < 4; ni++)
#pragma unroll
            for (int r = 0; r < 4; r++) c[mi][ni][r] = 0.f;

    loadStage(0, 0);
    cp_commit();

    for (int kt = 0; kt < KT; kt++) {
        if (kt + 1 < KT) {
            loadStage((kt + 1) & 1, kt + 1);
            cp_commit();
            cp_wait<1>();
        } else {
            cp_wait<0>();
        }
        __syncthreads();

        const uint32_t sb = sBase + (kt & 1) * (GSTG2 * 4);
        const uint32_t sAh_u = sb;
        const uint32_t sBh_u = sb + GTILE * 4;

#pragma unroll
        for (int ks = 0; ks < 2; ks++) {
            const int kw0 = ks * 8;
            uint32_t ah[4][4], bh[2][4];
#pragma unroll
            for (int mi = 0; mi < 4; mi++) {
                uint32_t base = ((wm * 64 + mi * 16) * GPAD + aOff + kw0) * 4;
                LDSM4(ah[mi], sAh_u + base);
            }
#pragma unroll
            for (int q = 0; q < 2; q++) {
                uint32_t base = ((wn * 32 + q * 16) * GPAD + bOff + kw0) * 4;
                LDSM4(bh[q], sBh_u + base);
            }
#pragma unroll
            for (int mi = 0; mi < 4; mi++)
#pragma unroll
                for (int ni = 0; ni < 4; ni++) {
                    const int q = ni >> 1;
                    const int r = (ni & 1) * 2;
                    mma_f16(c[mi][ni], ah[mi][0], ah[mi][1], ah[mi][2], ah[mi][3],
                            bh[q][r], bh[q][r + 1]);
                }
        }
        __syncthreads();
    }

    // Epilogue
#pragma unroll
    for (int mi = 0; mi < 4; mi++) {
#pragma unroll
        for (int ni = 0; ni < 4; ni++) {
#pragma unroll
            for (int half = 0; half < 2; half++) {
                int m = mBase + wm * 64 + mi * 16 + g + half * 8;
                int n = nBase + wn * 32 + ni * 8 + t * 2;
                float v0 = c[mi][ni][half * 2 + 0] + bias[n];
                float v1 = c[mi][ni][half * 2 + 1] + bias[n + 1];
                if (SCATTER) {
                    int b = m >> 11;
                    int s2 = m & (SS - 1);
                    int h = n / 192;
                    int rem = n - h * 192;
                    int ty2 = rem >> 6;
                    int d = rem & 63;
                    size_t widx = ((size_t)(b * HH + h) * SS + s2) * (HD / 2) + (d >> 1);
                    if (ty2 == 0) {
                        float q0 = v0 * 0.125f, q1 = v1 * 0.125f;
                        float h0 = hhi(q0), h1 = hhi(q1);
                        g_qhp[widx] = pk2h(h0, h1);
                        g_qlp[widx] = pk2h(q0 - h0, q1 - h1);
                    } else if (ty2 == 1) {
                        g_khp[widx] = pk2h(hhi(v0), hhi(v1));
                    } else {
                        g_vhp[widx] = pk2h(hhi(v0), hhi(v1));
                    }
                } else {
                    *(float2*)(out + (size_t)m * N + n) = make_float2(v0, v1);
                }
            }
        }
    }
}

// ---------------------------------------------------------------------------
// fp16 flash attention: 2-term QK^T, 1-term P@V, pre-packed inputs.
// Q tile 128, KV tile 64, 8 warps x 16 exclusive rows, 2 CTAs/SM.
// smem (words): Qh/Ql [128][36] | Ph [128][36] | ring of 3: K[64][36] V[64][36]
// ---------------------------------------------------------------------------
#define AQP 36
#define AQSZ (128 * AQP)     // 4608 words
#define AKSZ (64 * AQP)      // 2304 words per K or V tile
#define ASTG (2 * AKSZ)      // K+V per ring stage
#define ATTN_SMEM_WORDS (3 * AQSZ + 3 * ASTG)
#define ATTN_SMEM_BYTES (ATTN_SMEM_WORDS * 4)   // 110592

__global__ void __launch_bounds__(256, 2) attn_kernel8() {
    extern __shared__ uint32_t smw[];
    uint32_t* sPh = smw + 2 * AQSZ;

    const int tid = threadIdx.x;
    const int lane = tid & 31;
    const int warp = tid >> 5;
    const int g = lane >> 2;
    const int t = lane & 3;
    const int qt = (gridDim.x - 1) - blockIdx.x;
    const int bh = blockIdx.y;
    const int b = bh >> 4, h = bh & 15;
    const int qBase = qt * 128;
    const int m0 = warp * 16;

    const uint32_t* Qh = g_qhp + (size_t)(bh * SS + qBase) * (HD / 2);
    const uint32_t* Ql = g_qlp + (size_t)(bh * SS + qBase) * (HD / 2);
    const uint32_t* Kh = g_khp + (size_t)bh * SS * (HD / 2);
    const uint32_t* Vh = g_vhp + (size_t)bh * SS * (HD / 2);

    const uint32_t sBase = (uint32_t)__cvta_generic_to_shared(smw);
    const uint32_t sQh_u = sBase;
    const uint32_t sQl_u = sBase + AQSZ * 4;
    const uint32_t sPh_u = sBase + 2 * AQSZ * 4;
    const uint32_t sRing_u = sBase + 3 * AQSZ * 4;

    // ldmatrix per-lane offsets (words, pad 36)
    const int aOff = ((lane & 7) + ((lane >> 3) & 1) * 8) * AQP + ((lane >> 4) & 1) * 4;
    const int bOff = ((lane & 7) + ((lane >> 4) & 1) * 8) * AQP + ((lane >> 3) & 1) * 4;
    const int vOff = (((lane & 7) + ((lane >> 3) & 1) * 8) * AQP + ((lane >> 4) & 1) * 4);

    // Q load: 128 rows x 32 words, 2 threads/row
    {
        int qRow = tid >> 1;
        int qc = (tid & 1) * 16;
        const uint32_t* gh = Qh + (size_t)qRow * 32 + qc;
        const uint32_t* gl = Ql + (size_t)qRow * 32 + qc;
        uint32_t dst = (qRow * AQP + qc) * 4;
#pragma unroll
        for (int c2 = 0; c2 < 4; c2++) {
            cp16(sQh_u + dst + c2 * 16, gh + c2 * 4);
            cp16(sQl_u + dst + c2 * 16, gl + c2 * 4);
        }
    }

    // KV tile load: 64 rows x 32 words each, 4 threads/row
    const int kRow = tid >> 2;
    const int kc = (tid & 3) * 8;
    auto prefetchKV = [&](int stg, int j) {
        int kvB = j * 64;
        uint32_t dst = sRing_u + (stg * ASTG + kRow * AQP + kc) * 4;
        const uint32_t* gk = Kh + (size_t)(kvB + kRow) * 32 + kc;
        const uint32_t* gv = Vh + (size_t)(kvB + kRow) * 32 + kc;
        cp16(dst, gk);
        cp16(dst + 16, gk + 4);
        cp16(dst + AKSZ * 4, gv);
        cp16(dst + AKSZ * 4 + 16, gv + 4);
    };

    float m_[2] = {-1e30f, -1e30f};
    float l_[2] = {0.f, 0.f};
    float co[8][4];
#pragma unroll
    for (int ni = 0; ni < 8; ni++)
#pragma unroll
        for (int r = 0; r < 4; r++) co[ni][r] = 0.f;

    const int jmax = 2 * qt + 1;
    prefetchKV(0, 0);
    cp_commit();          // group: Q + KV0
    prefetchKV(1, 1);
    cp_commit();          // group: KV1

    for (int j = 0; j <= jmax; j++) {
        const int kvBase = j * 64;
        const int stg = j % 3;
        if (j < jmax) cp_wait<1>();
        else cp_wait<0>();
        __syncthreads();

        if (j + 2 <= jmax) {
            prefetchKV((j + 2) % 3, j + 2);
            cp_commit();
        }

        if (kvBase > qBase + m0 + 15) continue;  // warp tile fully masked

        const uint32_t sK_u = sRing_u + stg * ASTG * 4;
        const uint32_t sV_u = sK_u + AKSZ * 4;

        // Scores S = Q K^T (2-term fp16)
        float sc[8][4];
#pragma unroll
        for (int ni = 0; ni < 8; ni++)
#pragma unroll
            for (int r = 0; r < 4; r++) sc[ni][r] = 0.f;
#pragma unroll
        for (int ks = 0; ks < 4; ks++) {
            const int kw0 = ks * 8;
            uint32_t qh[4], ql[4], kb[4][4];
            uint32_t abase = (m0 * AQP + aOff + kw0) * 4;
            LDSM4(qh, sQh_u + abase);
            LDSM4(ql, sQl_u + abase);
#pragma unroll
            for (int q2 = 0; q2 < 4; q2++) {
                uint32_t bbase = ((q2 * 16) * AQP + bOff + kw0) * 4;
                LDSM4(kb[q2], sK_u + bbase);
            }
#pragma unroll
            for (int ni = 0; ni < 8; ni++) {
                const int q2 = ni >> 1;
                const int r = (ni & 1) * 2;
                mma_f16(sc[ni], ql[0], ql[1], ql[2], ql[3], kb[q2][r], kb[q2][r + 1]);
                mma_f16(sc[ni], qh[0], qh[1], qh[2], qh[3], kb[q2][r], kb[q2][r + 1]);
            }
        }

        // Causal mask
        if (kvBase + 63 > qBase + m0) {
#pragma unroll
            for (int ni = 0; ni < 8; ni++) {
#pragma unroll
                for (int r = 0; r < 4; r++) {
                    int row = qBase + m0 + g + ((r >= 2) ? 8 : 0);
                    int col = kvBase + ni * 8 + 2 * t + (r & 1);
                    if (col > row) sc[ni][r] = -1e30f;
                }
            }
        }

        // Warp-local online softmax (rows g and g+8)
        float mx0 = -1e30f, mx1 = -1e30f;
#pragma unroll
        for (int ni = 0; ni < 8; ni++) {
            mx0 = fmaxf(mx0, fmaxf(sc[ni][0], sc[ni][1]));
            mx1 = fmaxf(mx1, fmaxf(sc[ni][2], sc[ni][3]));
        }
#pragma unroll
        for (int o = 1; o <= 2; o <<= 1) {
            mx0 = fmaxf(mx0, __shfl_xor_sync(0xffffffffu, mx0, o));
            mx1 = fmaxf(mx1, __shfl_xor_sync(0xffffffffu, mx1, o));
        }
        float mn0 = fmaxf(m_[0], mx0), mn1 = fmaxf(m_[1], mx1);
        float a0 = __expf(m_[0] - mn0), a1 = __expf(m_[1] - mn1);
        float s0 = 0.f, s1 = 0.f;
#pragma unroll
        for (int ni = 0; ni < 8; ni++) {
            sc[ni][0] = __expf(sc[ni][0] - mn0);
            sc[ni][1] = __expf(sc[ni][1] - mn0);
            sc[ni][2] = __expf(sc[ni][2] - mn1);
            sc[ni][3] = __expf(sc[ni][3] - mn1);
            s0 += sc[ni][0] + sc[ni][1];
            s1 += sc[ni][2] + sc[ni][3];
        }
#pragma unroll
        for (int o = 1; o <= 2; o <<= 1) {
            s0 += __shfl_xor_sync(0xffffffffu, s0, o);
            s1 += __shfl_xor_sync(0xffffffffu, s1, o);
        }
        l_[0] = l_[0] * a0 + s0; m_[0] = mn0;
        l_[1] = l_[1] * a1 + s1; m_[1] = mn1;
#pragma unroll
        for (int ni = 0; ni < 8; ni++) {
            co[ni][0] *= a0; co[ni][1] *= a0;
            co[ni][2] *= a1; co[ni][3] *= a1;
        }

        // Pack P (hi only) — warp-exclusive rows
#pragma unroll
        for (int ni = 0; ni < 8; ni++) {
            int w0 = (m0 + g) * AQP + ni * 4 + t;
            int w1 = (m0 + g + 8) * AQP + ni * 4 + t;
            sPh[w0] = pk2h(sc[ni][0], sc[ni][1]);
            sPh[w1] = pk2h(sc[ni][2], sc[ni][3]);
        }
        __syncwarp();

        // O += P @ V (1-term fp16; P via ldmatrix, V via ldmatrix.trans)
#pragma unroll
        for (int ks = 0; ks < 4; ks++) {
            const int kw0 = ks * 8;
            uint32_t ph[4];
            uint32_t abase = (m0 * AQP + aOff + kw0) * 4;
            LDSM4(ph, sPh_u + abase);
#pragma unroll
            for (int np = 0; np < 4; np++) {
                uint32_t vb[4];
                uint32_t vbase = ((ks * 16) * AQP + np * 8 + vOff) * 4;
                LDSM4T(vb, sV_u + vbase);
                mma_f16(co[2 * np], ph[0], ph[1], ph[2], ph[3], vb[0], vb[1]);
                mma_f16(co[2 * np + 1], ph[0], ph[1], ph[2], ph[3], vb[2], vb[3]);
            }
        }
    }

    // Epilogue: normalize, pack fp16 hi for out-proj A input
    float inv0 = 1.0f / l_[0];
    float inv1 = 1.0f / l_[1];
    int r0 = qBase + m0 + g;
    int r1 = r0 + 8;
#pragma unroll
    for (int ni = 0; ni < 8; ni++) {
        int w = h * (HD / 2) + ni * 4 + t;
        size_t i0 = (size_t)(b * SS + r0) * (DM / 2) + w;
        size_t i1 = (size_t)(b * SS + r1) * (DM / 2) + w;
        g_athp[i0] = pk2h(co[ni][0] * inv0, co[ni][1] * inv0);
        g_athp[i1] = pk2h(co[ni][2] * inv1, co[ni][3] * inv1);
    }
}

// ---------------------------------------------------------------------------

extern "C" void kernel_launch(void* const* d_in, const int* in_sizes, int n_in,
                              void* d_out, int out_size) {
    (void)in_sizes; (void)n_in; (void)out_size;
    const float* x     = (const float*)d_in[0];
    const float* w_qkv = (const float*)d_in[1];
    const float* b_qkv = (const float*)d_in[2];
    const float* w_out = (const float*)d_in[3];
    const float* b_out = (const float*)d_in[4];
    float* out = (float*)d_out;

    uint32_t *xhp, *wqhp, *wohp, *athp;
    cudaGetSymbolAddress((void**)&xhp, g_xhp);
    cudaGetSymbolAddress((void**)&wqhp, g_wqhp);
    cudaGetSymbolAddress((void**)&wohp, g_wohp);
    cudaGetSymbolAddress((void**)&athp, g_athp);

    // Pack: x -> hi [M][K/2]; weights transposed -> hi [N][K/2]
    dec_a_hi_kernel<<<(BB*SS*DIN/8 + 255) / 256, 256>>>(x, xhp, BB*SS*DIN/8);
    dec_wt_kernel<3*DM, DIN><<<(3*DM*(DIN/8) + 255) / 256, 256>>>(w_qkv, wqhp);
    dec_wt_kernel<DM, DM><<<(DM*(DM/8) + 255) / 256, 256>>>(w_out, wohp);

    // QKV GEMM (scatter packed fp16 q/k/v)
    {
        cudaFuncSetAttribute(f16_gemm_hi<3 * DM, true>,
                             cudaFuncAttributeMaxDynamicSharedMemorySize, GEMM_SMEM_BYTES);
        dim3 grid(3 * DM / 128, BB * SS / 128);
        f16_gemm_hi<3 * DM, true><<<grid, 256, GEMM_SMEM_BYTES>>>(xhp, wqhp, b_qkv, nullptr);
    }
    // Flash attention (2-term QK, 1-term PV, 2 CTAs/SM)
    {
        cudaFuncSetAttribute(attn_kernel8, cudaFuncAttributeMaxDynamicSharedMemorySize, ATTN_SMEM_BYTES);
        dim3 grid(SS / 128, BH);
        attn_kernel8<<<grid, 256, ATTN_SMEM_BYTES>>>();
    }
    // Output GEMM
    {
        cudaFuncSetAttribute(f16_gemm_hi<DM, false>,
                             cudaFuncAttributeMaxDynamicSharedMemorySize, GEMM_SMEM_BYTES);
        dim3 grid(DM / 128, BB * SS / 128);
        f16_gemm_hi<DM, false><<<grid, 256, GEMM_SMEM_BYTES>>>(athp, wohp, b_out, out);
    }
}

// round 16
// speedup vs baseline: 5.3715x; 1.1281x over previous
#include <cuda_runtime.h>
#include <cuda_fp16.h>
#include <cstdint>

#define BB 2
#define SS 2048
#define DIN 1024
#define DM 1024
#define HH 16
#define HD 64
#define BH (BB*HH)

// ---------------------------------------------------------------------------
// Scratch (__device__ globals; no allocation allowed)
// ---------------------------------------------------------------------------
__device__ uint32_t g_qhp[BH*SS*HD/2];       // Q fp16 hi, pre-scaled, [bh][s][d_word]
__device__ uint32_t g_khp[BH*SS*HD/2];       // K fp16 hi
__device__ uint32_t g_vhp[BH*SS*HD/2];       // V fp16 hi
__device__ uint32_t g_xhp[BB*SS*DIN/2];      // x fp16 [M][K/2] hi words
__device__ uint32_t g_wqhp[3*DM*(DIN/2)];    // W_qkv^T fp16 [N][K/2] hi
__device__ uint32_t g_wohp[DM*(DM/2)];       // W_out^T fp16 [N][K/2] hi
__device__ uint32_t g_athp[BB*SS*DM/2];      // attn out fp16 hi

// ---------------------------------------------------------------------------
// fp16 helpers
// ---------------------------------------------------------------------------
__device__ __forceinline__ uint32_t pk2h(float a, float b) {
    __half2 v = __floats2half2_rn(a, b);
    return *reinterpret_cast<uint32_t*>(&v);
}
__device__ __forceinline__ float hhi(float a) {
    return __half2float(__float2half_rn(a));
}

__device__ __forceinline__ void mma_f16(float c[4],
                                        uint32_t a0, uint32_t a1, uint32_t a2, uint32_t a3,
                                        uint32_t b0, uint32_t b1) {
    asm volatile(
        "mma.sync.aligned.m16n8k16.row.col.f32.f16.f16.f32 "
        "{%0,%1,%2,%3}, {%4,%5,%6,%7}, {%8,%9}, {%0,%1,%2,%3};"
        : "+f"(c[0]), "+f"(c[1]), "+f"(c[2]), "+f"(c[3])
        : "r"(a0), "r"(a1), "r"(a2), "r"(a3), "r"(b0), "r"(b1));
}

__device__ __forceinline__ void cp16(uint32_t dst, const void* src) {
    asm volatile("cp.async.ca.shared.global [%0], [%1], 16;" :: "r"(dst), "l"(src));
}
__device__ __forceinline__ void cp_commit() { asm volatile("cp.async.commit_group;"); }
template <int n>
__device__ __forceinline__ void cp_wait() { asm volatile("cp.async.wait_group %0;" :: "n"(n)); }

#define LDSM4(r, addr) \
    asm volatile("ldmatrix.sync.aligned.m8n8.x4.shared.b16 {%0,%1,%2,%3}, [%4];" \
                 : "=r"((r)[0]), "=r"((r)[1]), "=r"((r)[2]), "=r"((r)[3]) \
                 : "r"(addr))
#define LDSM4T(r, addr) \
    asm volatile("ldmatrix.sync.aligned.m8n8.x4.trans.shared.b16 {%0,%1,%2,%3}, [%4];" \
                 : "=r"((r)[0]), "=r"((r)[1]), "=r"((r)[2]), "=r"((r)[3]) \
                 : "r"(addr))

// ---------------------------------------------------------------------------
// Merged pack kernel: x -> [M][K/2] hi; W_qkv^T, W_out^T -> [N][K/2] hi
// ---------------------------------------------------------------------------
#define DEC_NA (BB*SS*DIN/8)       // 524288
#define DEC_NB (3*DM*(DIN/8))      // 393216
#define DEC_NC (DM*(DM/8))         // 131072

__global__ void dec_all_kernel(const float* __restrict__ x, uint32_t* __restrict__ xhp,
                               const float* __restrict__ wq, uint32_t* __restrict__ wqhp,
                               const float* __restrict__ wo, uint32_t* __restrict__ wohp) {
    int i = blockIdx.x * blockDim.x + threadIdx.x;
    if (i < DEC_NA) {
        const float4* s4 = (const float4*)x;
        float4 v0 = s4[2 * i], v1 = s4[2 * i + 1];
        uint4 h;
        h.x = pk2h(hhi(v0.x), hhi(v0.y));
        h.y = pk2h(hhi(v0.z), hhi(v0.w));
        h.z = pk2h(hhi(v1.x), hhi(v1.y));
        h.w = pk2h(hhi(v1.z), hhi(v1.w));
        ((uint4*)xhp)[i] = h;
    } else if (i < DEC_NA + DEC_NB) {
        int j = i - DEC_NA;
        const int N = 3 * DM;
        int kc = j / N;
        int n = j % N;
        float v[8];
#pragma unroll
        for (int q = 0; q < 8; q++) v[q] = wq[(size_t)(kc * 8 + q) * N + n];
        uint4 h;
        h.x = pk2h(hhi(v[0]), hhi(v[1]));
        h.y = pk2h(hhi(v[2]), hhi(v[3]));
        h.z = pk2h(hhi(v[4]), hhi(v[5]));
        h.w = pk2h(hhi(v[6]), hhi(v[7]));
        *(uint4*)(wqhp + (size_t)n * (DIN / 2) + kc * 4) = h;
    } else if (i < DEC_NA + DEC_NB + DEC_NC) {
        int j = i - DEC_NA - DEC_NB;
        const int N = DM;
        int kc = j / N;
        int n = j % N;
        float v[8];
#pragma unroll
        for (int q = 0; q < 8; q++) v[q] = wo[(size_t)(kc * 8 + q) * N + n];
        uint4 h;
        h.x = pk2h(hhi(v[0]), hhi(v[1]));
        h.y = pk2h(hhi(v[2]), hhi(v[3]));
        h.z = pk2h(hhi(v[4]), hhi(v[5]));
        h.w = pk2h(hhi(v[6]), hhi(v[7]));
        *(uint4*)(wohp + (size_t)n * (DM / 2) + kc * 4) = h;
    }
}

// ---------------------------------------------------------------------------
// 1-term fp16 GEMM with ldmatrix. CTA 128x128, k-tile 32 elems (16 words).
// 8 warps 2m x 4n, warp 64x32. 3-stage cp.async, ONE barrier per k-tile.
// ---------------------------------------------------------------------------
#define GPAD 20
#define GTILE (128 * GPAD)
#define GSTG2 (2 * GTILE)                 // A hi + B hi per stage
#define GEMM_SMEM_BYTES (3 * GSTG2 * 4)   // 61440

template <int N, bool SCATTER>
__global__ void __launch_bounds__(256, 2) f16_gemm_hi(const uint32_t* __restrict__ Ahp,
                                                      const uint32_t* __restrict__ Bhp,
                                                      const float* __restrict__ bias,
                                                      float* __restrict__ out) {
    constexpr int KW = 512;
    constexpr int KT = 32;
    extern __shared__ uint32_t smw[];
    const int tid = threadIdx.x;
    const int lane = tid & 31;
    const int warp = tid >> 5;
    const int wm = warp & 1;
    const int wn = warp >> 1;
    const int g = lane >> 2;
    const int t = lane & 3;
    const int mBase = blockIdx.y * 128;
    const int nBase = blockIdx.x * 128;

    const int fRow = tid >> 1;
    const int fh = (tid & 1) * 8;
    const uint32_t* gAh = Ahp + (size_t)(mBase + fRow) * KW + fh;
    const uint32_t* gBh = Bhp + (size_t)(nBase + fRow) * KW + fh;

    const uint32_t sBase = (uint32_t)__cvta_generic_to_shared(smw);
    const uint32_t fOff = (fRow * GPAD + fh) * 4;

    auto loadStage = [&](int s, int kt) {
        uint32_t b0 = sBase + s * (GSTG2 * 4);
        int kw = kt * 16;
        cp16(b0 + fOff, gAh + kw);
        cp16(b0 + fOff + 16, gAh + kw + 4);
        cp16(b0 + GTILE * 4 + fOff, gBh + kw);
        cp16(b0 + GTILE * 4 + fOff + 16, gBh + kw + 4);
    };

    const int aOff = ((lane & 7) + ((lane >> 3) & 1) * 8) * GPAD + ((lane >> 4) & 1) * 4;
    const int bOff = ((lane & 7) + ((lane >> 4) & 1) * 8) * GPAD + ((lane >> 3) & 1) * 4;

    float c[4][4][4];
#pragma unroll
    for (int mi = 0; mi < 4; mi++)
#pragma unroll
        for (int ni = 0; ni < 4; ni++)
#pragma unroll
            for (int r = 0; r < 4; r++) c[mi][ni][r] = 0.f;

    loadStage(0, 0);
    cp_commit();
    loadStage(1, 1);
    cp_commit();

    for (int kt = 0; kt < KT; kt++) {
        if (kt + 1 < KT) cp_wait<1>();
        else cp_wait<0>();
        __syncthreads();   // stage kt ready; stage (kt+2)%3's readers (iter kt-1) done

        if (kt + 2 < KT) {
            loadStage((kt + 2) % 3, kt + 2);
            cp_commit();
        }

        const uint32_t sb = sBase + (kt % 3) * (GSTG2 * 4);
        const uint32_t sAh_u = sb;
        const uint32_t sBh_u = sb + GTILE * 4;

#pragma unroll
        for (int ks = 0; ks < 2; ks++) {
            const int kw0 = ks * 8;
            uint32_t ah[4][4], bh[2][4];
#pragma unroll
            for (int mi = 0; mi < 4; mi++) {
                uint32_t base = ((wm * 64 + mi * 16) * GPAD + aOff + kw0) * 4;
                LDSM4(ah[mi], sAh_u + base);
            }
#pragma unroll
            for (int q = 0; q < 2; q++) {
                uint32_t base = ((wn * 32 + q * 16) * GPAD + bOff + kw0) * 4;
                LDSM4(bh[q], sBh_u + base);
            }
#pragma unroll
            for (int mi = 0; mi < 4; mi++)
#pragma unroll
                for (int ni = 0; ni < 4; ni++) {
                    const int q = ni >> 1;
                    const int r = (ni & 1) * 2;
                    mma_f16(c[mi][ni], ah[mi][0], ah[mi][1], ah[mi][2], ah[mi][3],
                            bh[q][r], bh[q][r + 1]);
                }
        }
    }

    // Epilogue
#pragma unroll
    for (int mi = 0; mi < 4; mi++) {
#pragma unroll
        for (int ni = 0; ni < 4; ni++) {
#pragma unroll
            for (int half = 0; half < 2; half++) {
                int m = mBase + wm * 64 + mi * 16 + g + half * 8;
                int n = nBase + wn * 32 + ni * 8 + t * 2;
                float v0 = c[mi][ni][half * 2 + 0] + bias[n];
                float v1 = c[mi][ni][half * 2 + 1] + bias[n + 1];
                if (SCATTER) {
                    int b = m >> 11;
                    int s2 = m & (SS - 1);
                    int h = n / 192;
                    int rem = n - h * 192;
                    int ty2 = rem >> 6;
                    int d = rem & 63;
                    size_t widx = ((size_t)(b * HH + h) * SS + s2) * (HD / 2) + (d >> 1);
                    if (ty2 == 0) {
                        g_qhp[widx] = pk2h(v0 * 0.125f, v1 * 0.125f);
                    } else if (ty2 == 1) {
                        g_khp[widx] = pk2h(hhi(v0), hhi(v1));
                    } else {
                        g_vhp[widx] = pk2h(hhi(v0), hhi(v1));
                    }
                } else {
                    *(float2*)(out + (size_t)m * N + n) = make_float2(v0, v1);
                }
            }
        }
    }
}

// ---------------------------------------------------------------------------
// fp16 flash attention: 1-term QK^T, 1-term P@V, pre-packed inputs.
// Q tile 128, KV tile 64, 8 warps x 16 exclusive rows, 2 CTAs/SM.
// smem (words): Qh [128][36] | Ph [128][36] | ring of 3: K[64][36] V[64][36]
// ---------------------------------------------------------------------------
#define AQP 36
#define AQSZ (128 * AQP)     // 4608 words
#define AKSZ (64 * AQP)      // 2304 words per K or V tile
#define ASTG (2 * AKSZ)      // K+V per ring stage
#define ATTN_SMEM_WORDS (2 * AQSZ + 3 * ASTG)
#define ATTN_SMEM_BYTES (ATTN_SMEM_WORDS * 4)   // 92160

__global__ void __launch_bounds__(256, 2) attn_kernel9() {
    extern __shared__ uint32_t smw[];
    uint32_t* sPh = smw + AQSZ;

    const int tid = threadIdx.x;
    const int lane = tid & 31;
    const int warp = tid >> 5;
    const int g = lane >> 2;
    const int t = lane & 3;
    const int qt = (gridDim.x - 1) - blockIdx.x;
    const int bh = blockIdx.y;
    const int b = bh >> 4, h = bh & 15;
    const int qBase = qt * 128;
    const int m0 = warp * 16;

    const uint32_t* Qh = g_qhp + (size_t)(bh * SS + qBase) * (HD / 2);
    const uint32_t* Kh = g_khp + (size_t)bh * SS * (HD / 2);
    const uint32_t* Vh = g_vhp + (size_t)bh * SS * (HD / 2);

    const uint32_t sBase = (uint32_t)__cvta_generic_to_shared(smw);
    const uint32_t sQh_u = sBase;
    const uint32_t sPh_u = sBase + AQSZ * 4;
    const uint32_t sRing_u = sBase + 2 * AQSZ * 4;

    // ldmatrix per-lane offsets (words, pad 36)
    const int aOff = ((lane & 7) + ((lane >> 3) & 1) * 8) * AQP + ((lane >> 4) & 1) * 4;
    const int bOff = ((lane & 7) + ((lane >> 4) & 1) * 8) * AQP + ((lane >> 3) & 1) * 4;
    const int vOff = ((lane & 7) + ((lane >> 3) & 1) * 8) * AQP + ((lane >> 4) & 1) * 4;

    // Q load: 128 rows x 32 words, 2 threads/row
    {
        int qRow = tid >> 1;
        int qc = (tid & 1) * 16;
        const uint32_t* gh = Qh + (size_t)qRow * 32 + qc;
        uint32_t dst = (qRow * AQP + qc) * 4;
#pragma unroll
        for (int c2 = 0; c2 < 4; c2++) cp16(sQh_u + dst + c2 * 16, gh + c2 * 4);
    }

    // KV tile load: 64 rows x 32 words each, 4 threads/row
    const int kRow = tid >> 2;
    const int kc = (tid & 3) * 8;
    auto prefetchKV = [&](int stg, int j) {
        int kvB = j * 64;
        uint32_t dst = sRing_u + (stg * ASTG + kRow * AQP + kc) * 4;
        const uint32_t* gk = Kh + (size_t)(kvB + kRow) * 32 + kc;
        const uint32_t* gv = Vh + (size_t)(kvB + kRow) * 32 + kc;
        cp16(dst, gk);
        cp16(dst + 16, gk + 4);
        cp16(dst + AKSZ * 4, gv);
        cp16(dst + AKSZ * 4 + 16, gv + 4);
    };

    float m_[2] = {-1e30f, -1e30f};
    float l_[2] = {0.f, 0.f};
    float co[8][4];
#pragma unroll
    for (int ni = 0; ni < 8; ni++)
#pragma unroll
        for (int r = 0; r < 4; r++) co[ni][r] = 0.f;

    const int jmax = 2 * qt + 1;
    prefetchKV(0, 0);
    cp_commit();          // group: Q + KV0
    prefetchKV(1, 1);
    cp_commit();          // group: KV1

    for (int j = 0; j <= jmax; j++) {
        const int kvBase = j * 64;
        const int stg = j % 3;
        if (j < jmax) cp_wait<1>();
        else cp_wait<0>();
        __syncthreads();

        if (j + 2 <= jmax) {
            prefetchKV((j + 2) % 3, j + 2);
            cp_commit();
        }

        if (kvBase > qBase + m0 + 15) continue;  // warp tile fully masked

        const uint32_t sK_u = sRing_u + stg * ASTG * 4;
        const uint32_t sV_u = sK_u + AKSZ * 4;

        // Scores S = Q K^T (1-term fp16)
        float sc[8][4];
#pragma unroll
        for (int ni = 0; ni < 8; ni++)
#pragma unroll
            for (int r = 0; r < 4; r++) sc[ni][r] = 0.f;
#pragma unroll
        for (int ks = 0; ks < 4; ks++) {
            const int kw0 = ks * 8;
            uint32_t qh[4], kb[4][4];
            uint32_t abase = (m0 * AQP + aOff + kw0) * 4;
            LDSM4(qh, sQh_u + abase);
#pragma unroll
            for (int q2 = 0; q2 < 4; q2++) {
                uint32_t bbase = ((q2 * 16) * AQP + bOff + kw0) * 4;
                LDSM4(kb[q2], sK_u + bbase);
            }
#pragma unroll
            for (int ni = 0; ni < 8; ni++) {
                const int q2 = ni >> 1;
                const int r = (ni & 1) * 2;
                mma_f16(sc[ni], qh[0], qh[1], qh[2], qh[3], kb[q2][r], kb[q2][r + 1]);
            }
        }

        // Causal mask
        if (kvBase + 63 > qBase + m0) {
#pragma unroll
            for (int ni = 0; ni < 8; ni++) {
#pragma unroll
                for (int r = 0; r < 4; r++) {
                    int row = qBase + m0 + g + ((r >= 2) ? 8 : 0);
                    int col = kvBase + ni * 8 + 2 * t + (r & 1);
                    if (col > row) sc[ni][r] = -1e30f;
                }
            }
        }

        // Warp-local online softmax (rows g and g+8)
        float mx0 = -1e30f, mx1 = -1e30f;
#pragma unroll
        for (int ni = 0; ni < 8; ni++) {
            mx0 = fmaxf(mx0, fmaxf(sc[ni][0], sc[ni][1]));
            mx1 = fmaxf(mx1, fmaxf(sc[ni][2], sc[ni][3]));
        }
#pragma unroll
        for (int o = 1; o <= 2; o <<= 1) {
            mx0 = fmaxf(mx0, __shfl_xor_sync(0xffffffffu, mx0, o));
            mx1 = fmaxf(mx1, __shfl_xor_sync(0xffffffffu, mx1, o));
        }
        float mn0 = fmaxf(m_[0], mx0), mn1 = fmaxf(m_[1], mx1);
        float a0 = __expf(m_[0] - mn0), a1 = __expf(m_[1] - mn1);
        float s0 = 0.f, s1 = 0.f;
#pragma unroll
        for (int ni = 0; ni < 8; ni++) {
            sc[ni][0] = __expf(sc[ni][0] - mn0);
            sc[ni][1] = __expf(sc[ni][1] - mn0);
            sc[ni][2] = __expf(sc[ni][2] - mn1);
            sc[ni][3] = __expf(sc[ni][3] - mn1);
            s0 += sc[ni][0] + sc[ni][1];
            s1 += sc[ni][2] + sc[ni][3];
        }
#pragma unroll
        for (int o = 1; o <= 2; o <<= 1) {
            s0 += __shfl_xor_sync(0xffffffffu, s0, o);
            s1 += __shfl_xor_sync(0xffffffffu, s1, o);
        }
        l_[0] = l_[0] * a0 + s0; m_[0] = mn0;
        l_[1] = l_[1] * a1 + s1; m_[1] = mn1;
#pragma unroll
        for (int ni = 0; ni < 8; ni++) {
            co[ni][0] *= a0; co[ni][1] *= a0;
            co[ni][2] *= a1; co[ni][3] *= a1;
        }

        // Pack P (hi only) — warp-exclusive rows
#pragma unroll
        for (int ni = 0; ni < 8; ni++) {
            int w0 = (m0 + g) * AQP + ni * 4 + t;
            int w1 = (m0 + g + 8) * AQP + ni * 4 + t;
            sPh[w0] = pk2h(sc[ni][0], sc[ni][1]);
            sPh[w1] = pk2h(sc[ni][2], sc[ni][3]);
        }
        __syncwarp();

        // O += P @ V (1-term fp16; P via ldmatrix, V via ldmatrix.trans)
#pragma unroll
        for (int ks = 0; ks < 4; ks++) {
            const int kw0 = ks * 8;
            uint32_t ph[4];
            uint32_t abase = (m0 * AQP + aOff + kw0) * 4;
            LDSM4(ph, sPh_u + abase);
#pragma unroll
            for (int np = 0; np < 4; np++) {
                uint32_t vb[4];
                uint32_t vbase = ((ks * 16) * AQP + np * 8 + vOff) * 4;
                LDSM4T(vb, sV_u + vbase);
                mma_f16(co[2 * np], ph[0], ph[1], ph[2], ph[3], vb[0], vb[1]);
                mma_f16(co[2 * np + 1], ph[0], ph[1], ph[2], ph[3], vb[2], vb[3]);
            }
        }
    }

    // Epilogue: normalize, pack fp16 hi for out-proj A input
    float inv0 = 1.0f / l_[0];
    float inv1 = 1.0f / l_[1];
    int r0 = qBase + m0 + g;
    int r1 = r0 + 8;
#pragma unroll
    for (int ni = 0; ni < 8; ni++) {
        int w = h * (HD / 2) + ni * 4 + t;
        size_t i0 = (size_t)(b * SS + r0) * (DM / 2) + w;
        size_t i1 = (size_t)(b * SS + r1) * (DM / 2) + w;
        g_athp[i0] = pk2h(co[ni][0] * inv0, co[ni][1] * inv0);
        g_athp[i1] = pk2h(co[ni][2] * inv1, co[ni][3] * inv1);
    }
}

// ---------------------------------------------------------------------------

extern "C" void kernel_launch(void* const* d_in, const int* in_sizes, int n_in,
                              void* d_out, int out_size) {
    (void)in_sizes; (void)n_in; (void)out_size;
    const float* x     = (const float*)d_in[0];
    const float* w_qkv = (const float*)d_in[1];
    const float* b_qkv = (const float*)d_in[2];
    const float* w_out = (const float*)d_in[3];
    const float* b_out = (const float*)d_in[4];
    float* out = (float*)d_out;

    uint32_t *xhp, *wqhp, *wohp, *athp;
    cudaGetSymbolAddress((void**)&xhp, g_xhp);
    cudaGetSymbolAddress((void**)&wqhp, g_wqhp);
    cudaGetSymbolAddress((void**)&wohp, g_wohp);
    cudaGetSymbolAddress((void**)&athp, g_athp);

    // Pack x + both weight transposes in one launch
    {
        int total = DEC_NA + DEC_NB + DEC_NC;
        dec_all_kernel<<<(total + 255) / 256, 256>>>(x, xhp, w_qkv, wqhp, w_out, wohp);
    }

    // QKV GEMM (scatter packed fp16 q/k/v)
    {
        cudaFuncSetAttribute(f16_gemm_hi<3 * DM, true>,
                             cudaFuncAttributeMaxDynamicSharedMemorySize, GEMM_SMEM_BYTES);
        dim3 grid(3 * DM / 128, BB * SS / 128);
        f16_gemm_hi<3 * DM, true><<<grid, 256, GEMM_SMEM_BYTES>>>(xhp, wqhp, b_qkv, nullptr);
    }
    // Flash attention (1-term QK, 1-term PV, 2 CTAs/SM)
    {
        cudaFuncSetAttribute(attn_kernel9, cudaFuncAttributeMaxDynamicSharedMemorySize, ATTN_SMEM_BYTES);
        dim3 grid(SS / 128, BH);
        attn_kernel9<<<grid, 256, ATTN_SMEM_BYTES>>>();
    }
    // Output GEMM
    {
        cudaFuncSetAttribute(f16_gemm_hi<DM, false>,
                             cudaFuncAttributeMaxDynamicSharedMemorySize, GEMM_SMEM_BYTES);
        dim3 grid(DM / 128, BB * SS / 128);
        f16_gemm_hi<DM, false><<<grid, 256, GEMM_SMEM_BYTES>>>(athp, wohp, b_out, out);
    }
}